// round 1
// baseline (speedup 1.0000x reference)
#include <cuda_runtime.h>
#include <math.h>

// ---------------- problem constants ----------------
#define BB   16
#define SSQ  256
#define DD   512
#define LLAT 64
#define KCL  20
#define MCC  10
#define NTOK 4096            // B*S
#define NZ   40960           // B*S*MC
#define NPB  2560            // S*MC
#define LOG_NORM_F (-0.91893853320467274178f)

// ---------------- scratch (device globals; no allocation allowed) ----------------
__device__ float g_q[NTOK*DD];
__device__ float g_k[NTOK*DD];
__device__ float g_v[NTOK*DD];
__device__ float g_o[NTOK*DD];
__device__ float g_hA[NTOK*DD];
__device__ float g_hB[NTOK*DD];
__device__ float g_att[64*SSQ*SSQ];
__device__ float g_stats[NTOK*128];
__device__ float g_z[NZ*LLAT];
__device__ float g_logqz[NZ];
__device__ float g_mu[BB*KCL*LLAT];
__device__ float g_m2[BB*KCL];
__device__ float g_logpi[BB*KCL];
__device__ float g_Nk[BB*KCL];
__device__ float g_post[BB*NPB*KCL];
__device__ float g_d1[41943040];   // 40960*1024
__device__ float g_d2[41943040];
__device__ double g_rec;
__device__ double g_kl;

// ---------------- helpers ----------------
__device__ __forceinline__ float warpRedSum(float v){
#pragma unroll
    for (int o = 16; o > 0; o >>= 1) v += __shfl_xor_sync(0xffffffffu, v, o);
    return v;
}

// =======================================================================
// Generic SGEMM: C[M,N] = epilogue(A[M,K] @ W[K,N])
// 128x128x8 tile, 8x8 per thread, 256 threads.
// Requires: M%128==0, N%128==0, K%8==0 (true for every call here).
// epilogue: +bias, optional relu, optional residual add (res + relu(x)),
// or lossMode: accumulate sum((relu(x) - H[row/10, col])^2) into g_rec.
// =======================================================================
__global__ __launch_bounds__(256, 2) void gemm_kernel(
    const float* __restrict__ A, const float* __restrict__ W,
    float* __restrict__ C, int M, int N, int K,
    const float* __restrict__ bias, const float* __restrict__ residual,
    int relu, int lossMode, const float* __restrict__ lossH)
{
    __shared__ float As[8][132];
    __shared__ float Bs[8][128];
    const int tid = threadIdx.x;
    const int m0 = blockIdx.y * 128, n0 = blockIdx.x * 128;
    const int arow = tid >> 1;
    const int aq   = (tid & 1) << 2;
    const int brow = tid >> 5;
    const int bcol = (tid & 31) << 2;
    const float* Ap = A + (size_t)(m0 + arow) * K + aq;
    const float* Wp = W + (size_t)brow * N + n0 + bcol;
    const int tx = tid & 15, ty = tid >> 4;

    float acc[8][8];
#pragma unroll
    for (int i = 0; i < 8; i++)
#pragma unroll
        for (int j = 0; j < 8; j++) acc[i][j] = 0.f;

    for (int k0 = 0; k0 < K; k0 += 8) {
        float4 av = *(const float4*)(Ap + k0);
        float4 bv = *(const float4*)(Wp + (size_t)k0 * N);
        As[aq+0][arow] = av.x; As[aq+1][arow] = av.y;
        As[aq+2][arow] = av.z; As[aq+3][arow] = av.w;
        *(float4*)&Bs[brow][bcol] = bv;
        __syncthreads();
#pragma unroll
        for (int kk = 0; kk < 8; kk++) {
            float fa[8], fb[8];
            *(float4*)&fa[0] = *(const float4*)&As[kk][ty*8];
            *(float4*)&fa[4] = *(const float4*)&As[kk][ty*8+4];
            *(float4*)&fb[0] = *(const float4*)&Bs[kk][tx*8];
            *(float4*)&fb[4] = *(const float4*)&Bs[kk][tx*8+4];
#pragma unroll
            for (int i = 0; i < 8; i++)
#pragma unroll
                for (int j = 0; j < 8; j++)
                    acc[i][j] = fmaf(fa[i], fb[j], acc[i][j]);
        }
        __syncthreads();
    }

    float bl[8];
#pragma unroll
    for (int j = 0; j < 8; j++) bl[j] = bias ? bias[n0 + tx*8 + j] : 0.f;

    if (!lossMode) {
#pragma unroll
        for (int i = 0; i < 8; i++) {
            int m = m0 + ty*8 + i;
            float out[8];
#pragma unroll
            for (int j = 0; j < 8; j++) {
                float v = acc[i][j] + bl[j];
                if (relu) v = fmaxf(v, 0.f);
                out[j] = v;
            }
            if (residual) {
                const float* rp = residual + (size_t)m * N + n0 + tx*8;
#pragma unroll
                for (int j = 0; j < 8; j++) out[j] += rp[j];
            }
            float* cp = C + (size_t)m * N + n0 + tx*8;
            *(float4*)cp     = make_float4(out[0], out[1], out[2], out[3]);
            *(float4*)(cp+4) = make_float4(out[4], out[5], out[6], out[7]);
        }
    } else {
        double s = 0.0;
#pragma unroll
        for (int i = 0; i < 8; i++) {
            int m = m0 + ty*8 + i;
            const float* hp = lossH + (size_t)(m / 10) * 512 + n0 + tx*8;
#pragma unroll
            for (int j = 0; j < 8; j++) {
                float v = fmaxf(acc[i][j] + bl[j], 0.f);
                float r = v - hp[j];
                s += (double)r * (double)r;
            }
        }
#pragma unroll
        for (int o = 16; o > 0; o >>= 1) s += __shfl_xor_sync(0xffffffffu, s, o);
        __shared__ double ds[8];
        int lane = tid & 31, w = tid >> 5;
        if (lane == 0) ds[w] = s;
        __syncthreads();
        if (tid == 0) {
            double t = 0;
            for (int i2 = 0; i2 < 8; i2++) t += ds[i2];
            atomicAdd(&g_rec, t);
        }
    }
}

// =======================================================================
// Attention: scores = Q Kt / sqrt(D), per (b,h). 128x128 tile of 256x256.
// =======================================================================
__global__ __launch_bounds__(256, 2) void attn_scores_kernel()
{
    __shared__ float As[8][132];
    __shared__ float Bs[8][132];
    const int tid = threadIdx.x;
    const int bh = blockIdx.z, b = bh >> 2, h = bh & 3;
    const int q0 = blockIdx.y * 128, n0 = blockIdx.x * 128;
    const int arow = tid >> 1, aq = (tid & 1) << 2;
    const float* Ap = g_q + ((size_t)b*SSQ + q0 + arow)*DD + h*128 + aq;
    const float* Bp = g_k + ((size_t)b*SSQ + n0 + arow)*DD + h*128 + aq;
    const int tx = tid & 15, ty = tid >> 4;

    float acc[8][8];
#pragma unroll
    for (int i = 0; i < 8; i++)
#pragma unroll
        for (int j = 0; j < 8; j++) acc[i][j] = 0.f;

    for (int k0 = 0; k0 < 128; k0 += 8) {
        float4 av = *(const float4*)(Ap + k0);
        float4 bv = *(const float4*)(Bp + k0);
        As[aq+0][arow] = av.x; As[aq+1][arow] = av.y;
        As[aq+2][arow] = av.z; As[aq+3][arow] = av.w;
        Bs[aq+0][arow] = bv.x; Bs[aq+1][arow] = bv.y;
        Bs[aq+2][arow] = bv.z; Bs[aq+3][arow] = bv.w;
        __syncthreads();
#pragma unroll
        for (int kk = 0; kk < 8; kk++) {
            float fa[8], fb[8];
            *(float4*)&fa[0] = *(const float4*)&As[kk][ty*8];
            *(float4*)&fa[4] = *(const float4*)&As[kk][ty*8+4];
            *(float4*)&fb[0] = *(const float4*)&Bs[kk][tx*8];
            *(float4*)&fb[4] = *(const float4*)&Bs[kk][tx*8+4];
#pragma unroll
            for (int i = 0; i < 8; i++)
#pragma unroll
                for (int j = 0; j < 8; j++)
                    acc[i][j] = fmaf(fa[i], fb[j], acc[i][j]);
        }
        __syncthreads();
    }
    const float scale = 0.044194173824159216f; // 1/sqrt(512)
#pragma unroll
    for (int i = 0; i < 8; i++) {
        float* cp = g_att + ((size_t)bh*SSQ + q0 + ty*8 + i)*SSQ + n0 + tx*8;
        *(float4*)cp = make_float4(acc[i][0]*scale, acc[i][1]*scale, acc[i][2]*scale, acc[i][3]*scale);
        *(float4*)(cp+4) = make_float4(acc[i][4]*scale, acc[i][5]*scale, acc[i][6]*scale, acc[i][7]*scale);
    }
}

__global__ void softmax_kernel()
{
    const int row = blockIdx.x;
    float* p = g_att + (size_t)row * SSQ;
    const int tid = threadIdx.x, lane = tid & 31, w = tid >> 5;
    __shared__ float sm[8];
    float v = p[tid];
    float m = v;
#pragma unroll
    for (int o = 16; o > 0; o >>= 1) m = fmaxf(m, __shfl_xor_sync(0xffffffffu, m, o));
    if (lane == 0) sm[w] = m;
    __syncthreads();
    float bm = sm[0];
#pragma unroll
    for (int i = 1; i < 8; i++) bm = fmaxf(bm, sm[i]);
    float e = expf(v - bm);
    float s = warpRedSum(e);
    __syncthreads();
    if (lane == 0) sm[w] = s;
    __syncthreads();
    float bs = 0.f;
#pragma unroll
    for (int i = 0; i < 8; i++) bs += sm[i];
    p[tid] = e / bs;
}

// o = q + att @ v  (per (b,h): 256x128, K=256)
__global__ __launch_bounds__(256, 2) void attn_out_kernel()
{
    __shared__ float As[8][132];
    __shared__ float Bs[8][128];
    const int tid = threadIdx.x;
    const int bh = blockIdx.y, b = bh >> 2, h = bh & 3;
    const int q0 = blockIdx.x * 128;
    const int arow = tid >> 1, aq = (tid & 1) << 2;
    const float* Ap = g_att + ((size_t)bh*SSQ + q0 + arow)*SSQ + aq;
    const int brow = tid >> 5, bcol = (tid & 31) << 2;
    const float* Bp = g_v + ((size_t)b*SSQ + brow)*DD + h*128 + bcol;
    const int tx = tid & 15, ty = tid >> 4;

    float acc[8][8];
#pragma unroll
    for (int i = 0; i < 8; i++)
#pragma unroll
        for (int j = 0; j < 8; j++) acc[i][j] = 0.f;

    for (int k0 = 0; k0 < 256; k0 += 8) {
        float4 av = *(const float4*)(Ap + k0);
        float4 bv = *(const float4*)(Bp + (size_t)k0 * DD);
        As[aq+0][arow] = av.x; As[aq+1][arow] = av.y;
        As[aq+2][arow] = av.z; As[aq+3][arow] = av.w;
        *(float4*)&Bs[brow][bcol] = bv;
        __syncthreads();
#pragma unroll
        for (int kk = 0; kk < 8; kk++) {
            float fa[8], fb[8];
            *(float4*)&fa[0] = *(const float4*)&As[kk][ty*8];
            *(float4*)&fa[4] = *(const float4*)&As[kk][ty*8+4];
            *(float4*)&fb[0] = *(const float4*)&Bs[kk][tx*8];
            *(float4*)&fb[4] = *(const float4*)&Bs[kk][tx*8+4];
#pragma unroll
            for (int i = 0; i < 8; i++)
#pragma unroll
                for (int j = 0; j < 8; j++)
                    acc[i][j] = fmaf(fa[i], fb[j], acc[i][j]);
        }
        __syncthreads();
    }
#pragma unroll
    for (int i = 0; i < 8; i++) {
        size_t base = ((size_t)b*SSQ + q0 + ty*8 + i)*DD + h*128 + tx*8;
#pragma unroll
        for (int j = 0; j < 8; j++)
            g_o[base + j] = g_q[base + j] + acc[i][j];
    }
}

// =======================================================================
// z = mean + eps*std ; logqz = -0.5*sum(logvar + eps^2) + L*LOG_NORM
// =======================================================================
__global__ void z_kernel(const float* __restrict__ eps)
{
    const int bs = blockIdx.x, l = threadIdx.x;
    const int lane = l & 31, w = l >> 5;
    const float mean = g_stats[(size_t)bs*128 + l];
    const float lv   = g_stats[(size_t)bs*128 + 64 + l];
    const float sd = expf(0.5f * lv);
    __shared__ float sm[2];
    for (int m = 0; m < 10; m++) {
        size_t off = ((size_t)bs*10 + m)*64 + l;
        float e = eps[off];
        g_z[off] = mean + e * sd;
        float qv = warpRedSum(lv + e*e);
        if (lane == 0) sm[w] = qv;
        __syncthreads();
        if (l == 0) g_logqz[(size_t)bs*10 + m] = -0.5f*(sm[0] + sm[1]) + 64.f*LOG_NORM_F;
        __syncthreads();
    }
}

__global__ void init_mu_kernel(const int* __restrict__ idx)
{
    const int b = blockIdx.x, k = blockIdx.y, l = threadIdx.x;
    const int lane = l & 31, w = l >> 5;
    const int n = idx[b*KCL + k];
    float v = g_z[((size_t)b*NPB + n)*64 + l];
    g_mu[((size_t)b*KCL + k)*64 + l] = v;
    float s = warpRedSum(v*v);
    __shared__ float sm[2];
    if (lane == 0) sm[w] = s;
    __syncthreads();
    if (l == 0) {
        g_m2[b*KCL + k] = sm[0] + sm[1];
        g_logpi[b*KCL + k] = -2.9957322735539909f; // log(1/20)
    }
}

__global__ void zero_nk_kernel()
{
    int i = threadIdx.x;
    if (i < BB*KCL) g_Nk[i] = 0.f;
}

// EM phase 1: posteriors + Nk. warp per n, streaming softmax over K=20.
__global__ __launch_bounds__(256) void em_post_kernel()
{
    const int b = blockIdx.y;
    const int tid = threadIdx.x, lane = tid & 31, w = tid >> 5;
    __shared__ float mus[KCL*64];
    __shared__ float sc[KCL];
    __shared__ float nkacc[KCL];
    for (int i = tid; i < KCL*64; i += 256) mus[i] = g_mu[(size_t)b*KCL*64 + i];
    if (tid < KCL) { sc[tid] = -0.5f*g_m2[b*KCL+tid] + g_logpi[b*KCL+tid]; nkacc[tid] = 0.f; }
    __syncthreads();

    float nkloc = 0.f;
    const int nbase = blockIdx.x*64 + w*8;
    for (int t = 0; t < 8; t++) {
        int n = nbase + t;
        const float* zp = g_z + ((size_t)b*NPB + n)*64;
        float z0 = zp[lane], z1 = zp[lane+32];
        float mx = -1e30f, s = 0.f, myll = 0.f;
#pragma unroll
        for (int k2 = 0; k2 < KCL; k2++) {
            float p = z0*mus[k2*64+lane] + z1*mus[k2*64+32+lane];
            p = warpRedSum(p) + sc[k2];
            if (lane == k2) myll = p;
            float nm = fmaxf(mx, p);
            s = s*expf(mx - nm) + expf(p - nm);
            mx = nm;
        }
        if (lane < KCL) {
            float pk = expf(myll - mx) / s;
            g_post[((size_t)b*NPB + n)*KCL + lane] = pk;
            nkloc += pk;
        }
    }
    if (lane < KCL) atomicAdd(&nkacc[lane], nkloc);
    __syncthreads();
    if (tid < KCL) atomicAdd(&g_Nk[b*KCL + tid], nkacc[tid]);
}

// EM phase 2: mu = post^T z / Nk ; m2 ; logpi
__global__ void em_update_kernel()
{
    const int k = blockIdx.x, b = blockIdx.y, l = threadIdx.x;
    const int lane = l & 31, w = l >> 5;
    const float* zp = g_z + (size_t)b*NPB*64;
    const float* pp = g_post + (size_t)b*NPB*KCL;
    float a0 = 0.f, a1 = 0.f, a2 = 0.f, a3 = 0.f;
    for (int n = 0; n < NPB; n += 4) {
        a0 = fmaf(__ldg(&pp[(size_t)(n+0)*KCL + k]), zp[(size_t)(n+0)*64 + l], a0);
        a1 = fmaf(__ldg(&pp[(size_t)(n+1)*KCL + k]), zp[(size_t)(n+1)*64 + l], a1);
        a2 = fmaf(__ldg(&pp[(size_t)(n+2)*KCL + k]), zp[(size_t)(n+2)*64 + l], a2);
        a3 = fmaf(__ldg(&pp[(size_t)(n+3)*KCL + k]), zp[(size_t)(n+3)*64 + l], a3);
    }
    float acc = (a0 + a1) + (a2 + a3);
    float nk = g_Nk[b*KCL + k];
    float m = acc / nk;
    g_mu[((size_t)b*KCL + k)*64 + l] = m;
    float s = warpRedSum(m*m);
    __shared__ float sm[2];
    if (lane == 0) sm[w] = s;
    __syncthreads();
    if (l == 0) {
        g_m2[b*KCL + k] = sm[0] + sm[1];
        float tot = 0.f;
        for (int j = 0; j < KCL; j++) tot += g_Nk[b*KCL + j];
        g_logpi[b*KCL + k] = logf(nk / tot);
    }
}

// KL: log_pz via logsumexp, kl += logqz - logpz
__global__ __launch_bounds__(256) void kl_kernel()
{
    const int b = blockIdx.y;
    const int tid = threadIdx.x, lane = tid & 31, w = tid >> 5;
    __shared__ float mus[KCL*64];
    __shared__ float sc[KCL];
    for (int i = tid; i < KCL*64; i += 256) mus[i] = g_mu[(size_t)b*KCL*64 + i];
    if (tid < KCL) sc[tid] = -0.5f*g_m2[b*KCL+tid] + g_logpi[b*KCL+tid];
    __syncthreads();

    double loc = 0.0;
    const int nbase = blockIdx.x*64 + w*8;
    for (int t = 0; t < 8; t++) {
        int n = nbase + t;
        const float* zp = g_z + ((size_t)b*NPB + n)*64;
        float z0 = zp[lane], z1 = zp[lane+32];
        float sq = warpRedSum(z0*z0 + z1*z1);
        float mx = -1e30f, s = 0.f;
#pragma unroll
        for (int k2 = 0; k2 < KCL; k2++) {
            float p = z0*mus[k2*64+lane] + z1*mus[k2*64+32+lane];
            p = warpRedSum(p) + sc[k2];
            float nm = fmaxf(mx, p);
            s = s*expf(mx - nm) + expf(p - nm);
            mx = nm;
        }
        float lpz = mx + logf(s) - 0.5f*sq + 64.f*LOG_NORM_F;
        if (lane == 0) loc += (double)(g_logqz[(size_t)b*NPB + n] - lpz);
    }
    __shared__ double dacc[8];
    if (lane == 0) dacc[w] = loc;
    __syncthreads();
    if (tid == 0) {
        double t = 0;
        for (int i = 0; i < 8; i++) t += dacc[i];
        atomicAdd(&g_kl, t);
    }
}

__global__ void zero_accum_kernel() { g_rec = 0.0; g_kl = 0.0; }

__global__ void finalize_kernel(float* __restrict__ out)
{
    out[0] = (float)(g_rec / 40960.0);
    out[1] = (float)(g_kl / 40960.0);
}

// ---------------- host ----------------
static void* symaddr(const void* s)
{
    void* p = nullptr;
    cudaGetSymbolAddress(&p, s);
    return p;
}

extern "C" void kernel_launch(void* const* d_in, const int* in_sizes, int n_in,
                              void* d_out, int out_size)
{
    const float *H, *eps, *wq, *bq, *wk, *bk, *wv, *bv, *wo, *bo, *wz, *bz;
    const float *w1, *b1, *w2, *b2, *w3, *b3;
    const int* init_idx;

    if (n_in >= 3 && in_sizes[2] == 320) {
        // reference-signature order
        H = (const float*)d_in[0];  eps = (const float*)d_in[1]; init_idx = (const int*)d_in[2];
        wq = (const float*)d_in[3]; bq = (const float*)d_in[4];
        wk = (const float*)d_in[5]; bk = (const float*)d_in[6];
        wv = (const float*)d_in[7]; bv = (const float*)d_in[8];
        wo = (const float*)d_in[9]; bo = (const float*)d_in[10];
        wz = (const float*)d_in[11]; bz = (const float*)d_in[12];
        w1 = (const float*)d_in[13]; b1 = (const float*)d_in[14];
        w2 = (const float*)d_in[15]; b2 = (const float*)d_in[16];
        w3 = (const float*)d_in[17]; b3 = (const float*)d_in[18];
    } else {
        // setup_inputs dict-insertion order (init_idx last)
        H = (const float*)d_in[0];  eps = (const float*)d_in[1];
        wq = (const float*)d_in[2]; bq = (const float*)d_in[3];
        wk = (const float*)d_in[4]; bk = (const float*)d_in[5];
        wv = (const float*)d_in[6]; bv = (const float*)d_in[7];
        wo = (const float*)d_in[8]; bo = (const float*)d_in[9];
        wz = (const float*)d_in[10]; bz = (const float*)d_in[11];
        w1 = (const float*)d_in[12]; b1 = (const float*)d_in[13];
        w2 = (const float*)d_in[14]; b2 = (const float*)d_in[15];
        w3 = (const float*)d_in[16]; b3 = (const float*)d_in[17];
        init_idx = (const int*)d_in[18];
    }

    float* qp   = (float*)symaddr(g_q);
    float* kp   = (float*)symaddr(g_k);
    float* vp   = (float*)symaddr(g_v);
    float* op   = (float*)symaddr(g_o);
    float* hA   = (float*)symaddr(g_hA);
    float* hB   = (float*)symaddr(g_hB);
    float* st   = (float*)symaddr(g_stats);
    float* zp   = (float*)symaddr(g_z);
    float* d1p  = (float*)symaddr(g_d1);
    float* d2p  = (float*)symaddr(g_d2);

    zero_accum_kernel<<<1, 1>>>();

    const float* xin = H;
    float* layer_out[2] = { hA, hB };
    for (int i = 0; i < 2; i++) {
        const size_t woff = (size_t)i * DD * DD;
        const size_t boff = (size_t)i * DD;
        gemm_kernel<<<dim3(4, 32), 256>>>(xin, wq + woff, qp, NTOK, DD, DD, bq + boff, nullptr, 0, 0, nullptr);
        gemm_kernel<<<dim3(4, 32), 256>>>(xin, wk + woff, kp, NTOK, DD, DD, bk + boff, nullptr, 0, 0, nullptr);
        gemm_kernel<<<dim3(4, 32), 256>>>(xin, wv + woff, vp, NTOK, DD, DD, bv + boff, nullptr, 0, 0, nullptr);
        attn_scores_kernel<<<dim3(2, 2, 64), 256>>>();
        softmax_kernel<<<64 * SSQ, 256>>>();
        attn_out_kernel<<<dim3(2, 64), 256>>>();
        gemm_kernel<<<dim3(4, 32), 256>>>(op, wo + woff, layer_out[i], NTOK, DD, DD, bo + boff, op, 1, 0, nullptr);
        xin = layer_out[i];
    }

    gemm_kernel<<<dim3(1, 32), 256>>>(xin, wz, st, NTOK, 128, DD, bz, nullptr, 0, 0, nullptr);
    z_kernel<<<NTOK, 64>>>(eps);
    init_mu_kernel<<<dim3(BB, KCL), 64>>>(init_idx);

    for (int it = 0; it < 5; it++) {
        zero_nk_kernel<<<1, 320>>>();
        em_post_kernel<<<dim3(40, BB), 256>>>();
        em_update_kernel<<<dim3(KCL, BB), 64>>>();
    }

    gemm_kernel<<<dim3(8, 320), 256>>>(zp,  w1, d1p, NZ, 1024, 64,   b1, nullptr, 1, 0, nullptr);
    gemm_kernel<<<dim3(8, 320), 256>>>(d1p, w2, d2p, NZ, 1024, 1024, b2, nullptr, 1, 0, nullptr);
    gemm_kernel<<<dim3(4, 320), 256>>>(d2p, w3, nullptr, NZ, 512, 1024, b3, nullptr, 1, 1, H);

    kl_kernel<<<dim3(40, BB), 256>>>();
    finalize_kernel<<<1, 1>>>((float*)d_out);
    (void)in_sizes; (void)n_in; (void)out_size;
}

// round 3
// speedup vs baseline: 1.5045x; 1.5045x over previous
#include <cuda_runtime.h>
#include <math.h>
#include <stdint.h>

// ---------------- problem constants ----------------
#define BB   16
#define SSQ  256
#define DD   512
#define KCL  20
#define NTOK 4096            // B*S
#define NZ   40960           // B*S*MC
#define NPB  2560            // S*MC
#define LOG_NORM_F (-0.91893853320467274178f)

// ---------------- scratch (device globals) ----------------
__device__ float g_q[NTOK*DD];
__device__ float g_k[NTOK*DD];
__device__ float g_v[NTOK*DD];
__device__ float g_vt[64*128*256];
__device__ float g_o[NTOK*DD];
__device__ float g_hA[NTOK*DD];
__device__ float g_hB[NTOK*DD];
__device__ float g_att[64*SSQ*SSQ];
__device__ float g_stats[NTOK*128];
__device__ float g_z[NZ*64];
__device__ float g_logqz[NZ];
__device__ float g_mu[BB*KCL*64];
__device__ float g_m2[BB*KCL];
__device__ float g_logpi[BB*KCL];
__device__ float g_Nk[BB*KCL];
__device__ float g_post[BB*NPB*KCL];
__device__ float g_wt[1024*1024];
__device__ float g_d1[41943040];   // 40960*1024
__device__ float g_d2[41943040];
__device__ double g_rec;
__device__ double g_kl;

// ---------------- helpers ----------------
__device__ __forceinline__ float warpRedSum(float v){
#pragma unroll
    for (int o = 16; o > 0; o >>= 1) v += __shfl_xor_sync(0xffffffffu, v, o);
    return v;
}

__device__ __forceinline__ uint32_t f2tf32(float x){
    uint32_t u;
    asm("cvt.rna.tf32.f32 %0, %1;" : "=r"(u) : "f"(x));
    return u;
}

__device__ __forceinline__ void mma8(float* d, const uint32_t* a, const uint32_t* b){
    asm volatile(
        "mma.sync.aligned.m16n8k8.row.col.f32.tf32.tf32.f32 "
        "{%0,%1,%2,%3}, {%4,%5,%6,%7}, {%8,%9}, {%0,%1,%2,%3};"
        : "+f"(d[0]), "+f"(d[1]), "+f"(d[2]), "+f"(d[3])
        : "r"(a[0]), "r"(a[1]), "r"(a[2]), "r"(a[3]), "r"(b[0]), "r"(b[1]));
}

// =======================================================================
// TF32 tensor-core GEMM: C[m,n] = epi( scale * sum_k A[m,k]*B[n,k] )
// A: [M,K] row-major (lda), B: [N,K] row-major (ldb).
// Tile 128x128, K-chunk 32. 256 threads = 8 warps (4 along M x 2 along N),
// warp tile 32x64 built from m16n8k8 MMAs.
// Fragment-major smem layout: A frag = 1 LDS.128, B frag = 1 LDS.64.
// Double-buffered smem (64KB dynamic), 1 syncthreads per K-chunk.
// Batch via blockIdx.z: off = (z>>2)*s?b + (z&3)*s?h.
// =======================================================================
__global__ __launch_bounds__(256) void gemm_mma_kernel(
    const float* __restrict__ A, int lda, long long sAb, long long sAh,
    const float* __restrict__ B, int ldb, long long sBb, long long sBh,
    float* __restrict__ C, int ldc, long long sCb, long long sCh,
    int K,
    const float* __restrict__ bias,
    const float* __restrict__ residual, int ldres,
    float scale, int doRelu, int lossMode, const float* __restrict__ lossH)
{
    extern __shared__ uint32_t smbuf[];   // [2][8192]: per buf A 4096 + B 4096
    const int tid = threadIdx.x;
    const int wid = tid >> 5, lane = tid & 31;

    const int zb = blockIdx.z >> 2, zh = blockIdx.z & 3;
    A += (long long)zb * sAb + (long long)zh * sAh;
    B += (long long)zb * sBb + (long long)zh * sBh;
    if (C)        C        += (long long)zb * sCb + (long long)zh * sCh;
    if (residual) residual += (long long)zb * sCb + (long long)zh * sCh;

    const int m0 = blockIdx.y * 128, n0 = blockIdx.x * 128;

    // ---- staging indices: thread (tid) handles row srow, float4 cols jb..jb+3
    const int srow = tid >> 1;
    const int jb = (tid & 1) * 4;
    const float* gA = A + (size_t)(m0 + srow) * lda;
    const float* gB = B + (size_t)(n0 + srow) * ldb;

    // smem float-index bases for each of the 4 float4 stores per operand.
    // A: fi = ((t*8 + mt)*32 + (m&7)*4 + q)*4 + s,  s = ((m>>3)&1) + 2*(j&1)
    // B: fi = ((t*16 + nt)*32 + (n&7)*4 + q)*2 + s, s = (j&1)
    int fiA[4], fiB[4];
#pragma unroll
    for (int i = 0; i < 4; i++){
        int j = jb + i, t = j >> 1;
        fiA[i] = ((t*8  + (srow>>4))*32 + (srow&7)*4)*4 + ((srow>>3)&1) + 2*(j&1);
        fiB[i] = ((t*16 + (srow>>3))*32 + (srow&7)*4)*2 + (j&1);
    }

    float acc[2][8][4];
#pragma unroll
    for (int i = 0; i < 2; i++)
#pragma unroll
        for (int j = 0; j < 8; j++)
#pragma unroll
            for (int q = 0; q < 4; q++) acc[i][j][q] = 0.f;

    const int wm = (wid & 3) * 32;   // warp m offset in tile
    const int wn = (wid >> 2) * 64;  // warp n offset in tile

    const int nc = K >> 5;
    float4 rA[4], rB[4];
#pragma unroll
    for (int i = 0; i < 4; i++){
        rA[i] = *(const float4*)(gA + (jb + i) * 4);
        rB[i] = *(const float4*)(gB + (jb + i) * 4);
    }

    for (int c = 0; c < nc; c++){
        uint32_t* bufA = smbuf + (c & 1) * 8192;
        uint32_t* bufB = bufA + 4096;
#pragma unroll
        for (int i = 0; i < 4; i++){
            const float* av = (const float*)&rA[i];
            const float* bv = (const float*)&rB[i];
#pragma unroll
            for (int q = 0; q < 4; q++){
                bufA[fiA[i] + q*4] = f2tf32(av[q]);
                bufB[fiB[i] + q*2] = f2tf32(bv[q]);
            }
        }
        if (c + 1 < nc){
            const float* gA2 = gA + (c + 1) * 32;
            const float* gB2 = gB + (c + 1) * 32;
#pragma unroll
            for (int i = 0; i < 4; i++){
                rA[i] = *(const float4*)(gA2 + (jb + i) * 4);
                rB[i] = *(const float4*)(gB2 + (jb + i) * 4);
            }
        }
        __syncthreads();

        const int mt0 = wm >> 4, nt0 = wn >> 3;
#pragma unroll
        for (int t = 0; t < 4; t++){
            uint32_t a0[4], a1[4];
            *(uint4*)a0 = *(const uint4*)(bufA + ((t*8 + mt0    )*32 + lane)*4);
            *(uint4*)a1 = *(const uint4*)(bufA + ((t*8 + mt0 + 1)*32 + lane)*4);
#pragma unroll
            for (int nt = 0; nt < 8; nt++){
                uint32_t b[2];
                *(uint2*)b = *(const uint2*)(bufB + ((t*16 + nt0 + nt)*32 + lane)*2);
                mma8(acc[0][nt], a0, b);
                mma8(acc[1][nt], a1, b);
            }
        }
    }
    __syncthreads();

    // ---- epilogue
    if (!lossMode){
#pragma unroll
        for (int mt = 0; mt < 2; mt++){
#pragma unroll
            for (int half = 0; half < 2; half++){
                int r = m0 + wm + mt*16 + (lane >> 2) + half*8;
                float* crow = C + (size_t)r * ldc;
                const float* rrow = residual ? (residual + (size_t)r * ldres) : nullptr;
#pragma unroll
                for (int nt = 0; nt < 8; nt++){
                    int col = n0 + wn + nt*8 + (lane & 3)*2;
                    float f0 = acc[mt][nt][half*2 + 0] * scale;
                    float f1 = acc[mt][nt][half*2 + 1] * scale;
                    if (bias){ f0 += bias[col]; f1 += bias[col + 1]; }
                    if (doRelu){ f0 = fmaxf(f0, 0.f); f1 = fmaxf(f1, 0.f); }
                    if (rrow){
                        float2 rv = *(const float2*)(rrow + col);
                        f0 += rv.x; f1 += rv.y;
                    }
                    *(float2*)(crow + col) = make_float2(f0, f1);
                }
            }
        }
    } else {
        double lsum = 0.0;
#pragma unroll
        for (int mt = 0; mt < 2; mt++){
#pragma unroll
            for (int half = 0; half < 2; half++){
                int r = m0 + wm + mt*16 + (lane >> 2) + half*8;
                const float* hrow = lossH + (size_t)(r / 10) * 512;
#pragma unroll
                for (int nt = 0; nt < 8; nt++){
                    int col = n0 + wn + nt*8 + (lane & 3)*2;
                    float f0 = fmaxf(acc[mt][nt][half*2 + 0] + bias[col], 0.f);
                    float f1 = fmaxf(acc[mt][nt][half*2 + 1] + bias[col + 1], 0.f);
                    float d0 = f0 - hrow[col];
                    float d1 = f1 - hrow[col + 1];
                    lsum += (double)d0 * d0 + (double)d1 * d1;
                }
            }
        }
#pragma unroll
        for (int o = 16; o > 0; o >>= 1) lsum += __shfl_xor_sync(0xffffffffu, lsum, o);
        __shared__ double ds[8];
        if (lane == 0) ds[wid] = lsum;
        __syncthreads();
        if (tid == 0){
            double t = 0;
            for (int i = 0; i < 8; i++) t += ds[i];
            atomicAdd(&g_rec, t);
        }
    }
}

// =======================================================================
// weight transpose: out[n*K + k] = W[k*N + n]
// =======================================================================
__global__ void transpose_w_kernel(const float* __restrict__ W,
                                   float* __restrict__ out, int K, int N)
{
    __shared__ float t[32][33];
    const int k0 = blockIdx.y * 32, n0 = blockIdx.x * 32;
    for (int i = threadIdx.y; i < 32; i += 8)
        t[i][threadIdx.x] = W[(size_t)(k0 + i) * N + n0 + threadIdx.x];
    __syncthreads();
    for (int i = threadIdx.y; i < 32; i += 8)
        out[(size_t)(n0 + i) * K + k0 + threadIdx.x] = t[threadIdx.x][i];
}

// g_vt[bh][n][k] = g_v[b][k][h*128+n]
__global__ void transpose_v_kernel()
{
    __shared__ float t[32][33];
    const int bh = blockIdx.z, b = bh >> 2, h = bh & 3;
    const int k0 = blockIdx.x * 32;   // seq
    const int n0 = blockIdx.y * 32;   // head-dim
    for (int i = threadIdx.y; i < 32; i += 8)
        t[i][threadIdx.x] = g_v[((size_t)b * 256 + k0 + i) * 512 + h * 128 + n0 + threadIdx.x];
    __syncthreads();
    for (int i = threadIdx.y; i < 32; i += 8)
        g_vt[((size_t)bh * 128 + n0 + i) * 256 + k0 + threadIdx.x] = t[threadIdx.x][i];
}

// =======================================================================
// fp32 SIMT GEMM (precision-sensitive stats projection only)
// =======================================================================
__global__ __launch_bounds__(256, 2) void gemm_kernel(
    const float* __restrict__ A, const float* __restrict__ W,
    float* __restrict__ C, int M, int N, int K,
    const float* __restrict__ bias)
{
    __shared__ float As[8][132];
    __shared__ float Bs[8][128];
    const int tid = threadIdx.x;
    const int m0 = blockIdx.y * 128, n0 = blockIdx.x * 128;
    const int arow = tid >> 1;
    const int aq   = (tid & 1) << 2;
    const int brow = tid >> 5;
    const int bcol = (tid & 31) << 2;
    const float* Ap = A + (size_t)(m0 + arow) * K + aq;
    const float* Wp = W + (size_t)brow * N + n0 + bcol;
    const int tx = tid & 15, ty = tid >> 4;

    float acc[8][8];
#pragma unroll
    for (int i = 0; i < 8; i++)
#pragma unroll
        for (int j = 0; j < 8; j++) acc[i][j] = 0.f;

    for (int k0 = 0; k0 < K; k0 += 8) {
        float4 av = *(const float4*)(Ap + k0);
        float4 bv = *(const float4*)(Wp + (size_t)k0 * N);
        As[aq+0][arow] = av.x; As[aq+1][arow] = av.y;
        As[aq+2][arow] = av.z; As[aq+3][arow] = av.w;
        *(float4*)&Bs[brow][bcol] = bv;
        __syncthreads();
#pragma unroll
        for (int kk = 0; kk < 8; kk++) {
            float fa[8], fb[8];
            *(float4*)&fa[0] = *(const float4*)&As[kk][ty*8];
            *(float4*)&fa[4] = *(const float4*)&As[kk][ty*8+4];
            *(float4*)&fb[0] = *(const float4*)&Bs[kk][tx*8];
            *(float4*)&fb[4] = *(const float4*)&Bs[kk][tx*8+4];
#pragma unroll
            for (int i = 0; i < 8; i++)
#pragma unroll
                for (int j = 0; j < 8; j++)
                    acc[i][j] = fmaf(fa[i], fb[j], acc[i][j]);
        }
        __syncthreads();
    }

    float bl[8];
#pragma unroll
    for (int j = 0; j < 8; j++) bl[j] = bias ? bias[n0 + tx*8 + j] : 0.f;
#pragma unroll
    for (int i = 0; i < 8; i++) {
        int m = m0 + ty*8 + i;
        float* cp = C + (size_t)m * N + n0 + tx*8;
        *(float4*)cp     = make_float4(acc[i][0]+bl[0], acc[i][1]+bl[1], acc[i][2]+bl[2], acc[i][3]+bl[3]);
        *(float4*)(cp+4) = make_float4(acc[i][4]+bl[4], acc[i][5]+bl[5], acc[i][6]+bl[6], acc[i][7]+bl[7]);
    }
}

// softmax over rows of g_att
__global__ void softmax_kernel()
{
    const int row = blockIdx.x;
    float* p = g_att + (size_t)row * SSQ;
    const int tid = threadIdx.x, lane = tid & 31, w = tid >> 5;
    __shared__ float sm[8];
    float v = p[tid];
    float m = v;
#pragma unroll
    for (int o = 16; o > 0; o >>= 1) m = fmaxf(m, __shfl_xor_sync(0xffffffffu, m, o));
    if (lane == 0) sm[w] = m;
    __syncthreads();
    float bm = sm[0];
#pragma unroll
    for (int i = 1; i < 8; i++) bm = fmaxf(bm, sm[i]);
    float e = expf(v - bm);
    float s = warpRedSum(e);
    __syncthreads();
    if (lane == 0) sm[w] = s;
    __syncthreads();
    float bs = 0.f;
#pragma unroll
    for (int i = 0; i < 8; i++) bs += sm[i];
    p[tid] = e / bs;
}

// z = mean + eps*std ; logqz
__global__ void z_kernel(const float* __restrict__ eps)
{
    const int bs = blockIdx.x, l = threadIdx.x;
    const int lane = l & 31, w = l >> 5;
    const float mean = g_stats[(size_t)bs*128 + l];
    const float lv   = g_stats[(size_t)bs*128 + 64 + l];
    const float sd = expf(0.5f * lv);
    __shared__ float sm[2];
    for (int m = 0; m < 10; m++) {
        size_t off = ((size_t)bs*10 + m)*64 + l;
        float e = eps[off];
        g_z[off] = mean + e * sd;
        float qv = warpRedSum(lv + e*e);
        if (lane == 0) sm[w] = qv;
        __syncthreads();
        if (l == 0) g_logqz[(size_t)bs*10 + m] = -0.5f*(sm[0] + sm[1]) + 64.f*LOG_NORM_F;
        __syncthreads();
    }
}

__global__ void init_mu_kernel(const int* __restrict__ idx)
{
    const int b = blockIdx.x, k = blockIdx.y, l = threadIdx.x;
    const int lane = l & 31, w = l >> 5;
    const int n = idx[b*KCL + k];
    float v = g_z[((size_t)b*NPB + n)*64 + l];
    g_mu[((size_t)b*KCL + k)*64 + l] = v;
    float s = warpRedSum(v*v);
    __shared__ float sm[2];
    if (lane == 0) sm[w] = s;
    __syncthreads();
    if (l == 0) {
        g_m2[b*KCL + k] = sm[0] + sm[1];
        g_logpi[b*KCL + k] = -2.9957322735539909f;
    }
}

__global__ void zero_nk_kernel()
{
    int i = threadIdx.x;
    if (i < BB*KCL) g_Nk[i] = 0.f;
}

__global__ __launch_bounds__(256) void em_post_kernel()
{
    const int b = blockIdx.y;
    const int tid = threadIdx.x, lane = tid & 31, w = tid >> 5;
    __shared__ float mus[KCL*64];
    __shared__ float sc[KCL];
    __shared__ float nkacc[KCL];
    for (int i = tid; i < KCL*64; i += 256) mus[i] = g_mu[(size_t)b*KCL*64 + i];
    if (tid < KCL) { sc[tid] = -0.5f*g_m2[b*KCL+tid] + g_logpi[b*KCL+tid]; nkacc[tid] = 0.f; }
    __syncthreads();

    float nkloc = 0.f;
    const int nbase = blockIdx.x*64 + w*8;
    for (int t = 0; t < 8; t++) {
        int n = nbase + t;
        const float* zp = g_z + ((size_t)b*NPB + n)*64;
        float z0 = zp[lane], z1 = zp[lane+32];
        float mx = -1e30f, s = 0.f, myll = 0.f;
#pragma unroll
        for (int k2 = 0; k2 < KCL; k2++) {
            float p = z0*mus[k2*64+lane] + z1*mus[k2*64+32+lane];
            p = warpRedSum(p) + sc[k2];
            if (lane == k2) myll = p;
            float nm = fmaxf(mx, p);
            s = s*expf(mx - nm) + expf(p - nm);
            mx = nm;
        }
        if (lane < KCL) {
            float pk = expf(myll - mx) / s;
            g_post[((size_t)b*NPB + n)*KCL + lane] = pk;
            nkloc += pk;
        }
    }
    if (lane < KCL) atomicAdd(&nkacc[lane], nkloc);
    __syncthreads();
    if (tid < KCL) atomicAdd(&g_Nk[b*KCL + tid], nkacc[tid]);
}

__global__ void em_update_kernel()
{
    const int k = blockIdx.x, b = blockIdx.y, l = threadIdx.x;
    const int lane = l & 31, w = l >> 5;
    const float* zp = g_z + (size_t)b*NPB*64;
    const float* pp = g_post + (size_t)b*NPB*KCL;
    float a0 = 0.f, a1 = 0.f, a2 = 0.f, a3 = 0.f;
    for (int n = 0; n < NPB; n += 4) {
        a0 = fmaf(__ldg(&pp[(size_t)(n+0)*KCL + k]), zp[(size_t)(n+0)*64 + l], a0);
        a1 = fmaf(__ldg(&pp[(size_t)(n+1)*KCL + k]), zp[(size_t)(n+1)*64 + l], a1);
        a2 = fmaf(__ldg(&pp[(size_t)(n+2)*KCL + k]), zp[(size_t)(n+2)*64 + l], a2);
        a3 = fmaf(__ldg(&pp[(size_t)(n+3)*KCL + k]), zp[(size_t)(n+3)*64 + l], a3);
    }
    float acc = (a0 + a1) + (a2 + a3);
    float nk = g_Nk[b*KCL + k];
    float m = acc / nk;
    g_mu[((size_t)b*KCL + k)*64 + l] = m;
    float s = warpRedSum(m*m);
    __shared__ float sm[2];
    if (lane == 0) sm[w] = s;
    __syncthreads();
    if (l == 0) {
        g_m2[b*KCL + k] = sm[0] + sm[1];
        float tot = 0.f;
        for (int j = 0; j < KCL; j++) tot += g_Nk[b*KCL + j];
        g_logpi[b*KCL + k] = logf(nk / tot);
    }
}

__global__ __launch_bounds__(256) void kl_kernel()
{
    const int b = blockIdx.y;
    const int tid = threadIdx.x, lane = tid & 31, w = tid >> 5;
    __shared__ float mus[KCL*64];
    __shared__ float sc[KCL];
    for (int i = tid; i < KCL*64; i += 256) mus[i] = g_mu[(size_t)b*KCL*64 + i];
    if (tid < KCL) sc[tid] = -0.5f*g_m2[b*KCL+tid] + g_logpi[b*KCL+tid];
    __syncthreads();

    double loc = 0.0;
    const int nbase = blockIdx.x*64 + w*8;
    for (int t = 0; t < 8; t++) {
        int n = nbase + t;
        const float* zp = g_z + ((size_t)b*NPB + n)*64;
        float z0 = zp[lane], z1 = zp[lane+32];
        float sq = warpRedSum(z0*z0 + z1*z1);
        float mx = -1e30f, s = 0.f;
#pragma unroll
        for (int k2 = 0; k2 < KCL; k2++) {
            float p = z0*mus[k2*64+lane] + z1*mus[k2*64+32+lane];
            p = warpRedSum(p) + sc[k2];
            float nm = fmaxf(mx, p);
            s = s*expf(mx - nm) + expf(p - nm);
            mx = nm;
        }
        float lpz = mx + logf(s) - 0.5f*sq + 64.f*LOG_NORM_F;
        if (lane == 0) loc += (double)(g_logqz[(size_t)b*NPB + n] - lpz);
    }
    __shared__ double dacc[8];
    if (lane == 0) dacc[w] = loc;
    __syncthreads();
    if (tid == 0) {
        double t = 0;
        for (int i = 0; i < 8; i++) t += dacc[i];
        atomicAdd(&g_kl, t);
    }
}

__global__ void zero_accum_kernel() { g_rec = 0.0; g_kl = 0.0; }

__global__ void finalize_kernel(float* __restrict__ out)
{
    out[0] = (float)(g_rec / 40960.0);
    out[1] = (float)(g_kl / 40960.0);
}

// ---------------- host ----------------
static void* symaddr(const void* s)
{
    void* p = nullptr;
    cudaGetSymbolAddress(&p, s);
    return p;
}

#define GEMM_SMEM 65536

extern "C" void kernel_launch(void* const* d_in, const int* in_sizes, int n_in,
                              void* d_out, int out_size)
{
    const float *H, *eps, *wq, *bq, *wk, *bk, *wv, *bv, *wo, *bo, *wz, *bz;
    const float *w1, *b1, *w2, *b2, *w3, *b3;
    const int* init_idx;

    if (n_in >= 3 && in_sizes[2] == 320) {
        H = (const float*)d_in[0];  eps = (const float*)d_in[1]; init_idx = (const int*)d_in[2];
        wq = (const float*)d_in[3]; bq = (const float*)d_in[4];
        wk = (const float*)d_in[5]; bk = (const float*)d_in[6];
        wv = (const float*)d_in[7]; bv = (const float*)d_in[8];
        wo = (const float*)d_in[9]; bo = (const float*)d_in[10];
        wz = (const float*)d_in[11]; bz = (const float*)d_in[12];
        w1 = (const float*)d_in[13]; b1 = (const float*)d_in[14];
        w2 = (const float*)d_in[15]; b2 = (const float*)d_in[16];
        w3 = (const float*)d_in[17]; b3 = (const float*)d_in[18];
    } else {
        H = (const float*)d_in[0];  eps = (const float*)d_in[1];
        wq = (const float*)d_in[2]; bq = (const float*)d_in[3];
        wk = (const float*)d_in[4]; bk = (const float*)d_in[5];
        wv = (const float*)d_in[6]; bv = (const float*)d_in[7];
        wo = (const float*)d_in[8]; bo = (const float*)d_in[9];
        wz = (const float*)d_in[10]; bz = (const float*)d_in[11];
        w1 = (const float*)d_in[12]; b1 = (const float*)d_in[13];
        w2 = (const float*)d_in[14]; b2 = (const float*)d_in[15];
        w3 = (const float*)d_in[16]; b3 = (const float*)d_in[17];
        init_idx = (const int*)d_in[18];
    }

    cudaFuncSetAttribute(gemm_mma_kernel,
                         cudaFuncAttributeMaxDynamicSharedMemorySize, GEMM_SMEM);

    float* qp  = (float*)symaddr(g_q);
    float* kp  = (float*)symaddr(g_k);
    float* vp  = (float*)symaddr(g_v);
    float* vtp = (float*)symaddr(g_vt);
    float* op  = (float*)symaddr(g_o);
    float* hA  = (float*)symaddr(g_hA);
    float* hB  = (float*)symaddr(g_hB);
    float* attp= (float*)symaddr(g_att);
    float* st  = (float*)symaddr(g_stats);
    float* zp  = (float*)symaddr(g_z);
    float* wt  = (float*)symaddr(g_wt);
    float* d1p = (float*)symaddr(g_d1);
    float* d2p = (float*)symaddr(g_d2);

    zero_accum_kernel<<<1, 1>>>();

    const float scl = 0.044194173824159216f; // 1/sqrt(512)
    const float* xin = H;
    float* layer_out[2] = { hA, hB };
    for (int i = 0; i < 2; i++) {
        const size_t woff = (size_t)i * DD * DD;
        const size_t boff = (size_t)i * DD;

        transpose_w_kernel<<<dim3(16,16), dim3(32,8)>>>(wq + woff, wt, 512, 512);
        gemm_mma_kernel<<<dim3(4,32,1), 256, GEMM_SMEM>>>(xin,512,0,0, wt,512,0,0, qp,512,0,0, 512,
                                              bq+boff, nullptr,0, 1.f,0,0,nullptr);
        transpose_w_kernel<<<dim3(16,16), dim3(32,8)>>>(wk + woff, wt, 512, 512);
        gemm_mma_kernel<<<dim3(4,32,1), 256, GEMM_SMEM>>>(xin,512,0,0, wt,512,0,0, kp,512,0,0, 512,
                                              bk+boff, nullptr,0, 1.f,0,0,nullptr);
        transpose_w_kernel<<<dim3(16,16), dim3(32,8)>>>(wv + woff, wt, 512, 512);
        gemm_mma_kernel<<<dim3(4,32,1), 256, GEMM_SMEM>>>(xin,512,0,0, wt,512,0,0, vp,512,0,0, 512,
                                              bv+boff, nullptr,0, 1.f,0,0,nullptr);

        // scores = q k^T / sqrt(D)   (batched over 64 bh)
        gemm_mma_kernel<<<dim3(2,2,64), 256, GEMM_SMEM>>>(qp,512,131072,128, kp,512,131072,128,
                                              attp,256,262144,65536, 128,
                                              nullptr, nullptr,0, scl,0,0,nullptr);
        softmax_kernel<<<64*SSQ, 256>>>();

        // o = q + att @ v
        transpose_v_kernel<<<dim3(8,4,64), dim3(32,8)>>>();
        gemm_mma_kernel<<<dim3(1,2,64), 256, GEMM_SMEM>>>(attp,256,262144,65536, vtp,256,131072,32768,
                                              op,512,131072,128, 256,
                                              nullptr, qp,512, 1.f,0,0,nullptr);

        // out = o + relu(o @ wo + bo)
        transpose_w_kernel<<<dim3(16,16), dim3(32,8)>>>(wo + woff, wt, 512, 512);
        gemm_mma_kernel<<<dim3(4,32,1), 256, GEMM_SMEM>>>(op,512,0,0, wt,512,0,0, layer_out[i],512,0,0, 512,
                                              bo+boff, op,512, 1.f,1,0,nullptr);
        xin = layer_out[i];
    }

    // stats (precision-sensitive): fp32 SIMT
    gemm_kernel<<<dim3(1, 32), 256>>>(xin, wz, st, NTOK, 128, DD, bz);

    z_kernel<<<NTOK, 64>>>(eps);
    init_mu_kernel<<<dim3(BB, KCL), 64>>>(init_idx);

    for (int it = 0; it < 5; it++) {
        zero_nk_kernel<<<1, 320>>>();
        em_post_kernel<<<dim3(40, BB), 256>>>();
        em_update_kernel<<<dim3(KCL, BB), 64>>>();
    }

    // decoder
    transpose_w_kernel<<<dim3(32,2), dim3(32,8)>>>(w1, wt, 64, 1024);
    gemm_mma_kernel<<<dim3(8,320,1), 256, GEMM_SMEM>>>(zp,64,0,0, wt,64,0,0, d1p,1024,0,0, 64,
                                           b1, nullptr,0, 1.f,1,0,nullptr);
    transpose_w_kernel<<<dim3(32,32), dim3(32,8)>>>(w2, wt, 1024, 1024);
    gemm_mma_kernel<<<dim3(8,320,1), 256, GEMM_SMEM>>>(d1p,1024,0,0, wt,1024,0,0, d2p,1024,0,0, 1024,
                                           b2, nullptr,0, 1.f,1,0,nullptr);
    transpose_w_kernel<<<dim3(16,32), dim3(32,8)>>>(w3, wt, 1024, 512);
    gemm_mma_kernel<<<dim3(4,320,1), 256, GEMM_SMEM>>>(d2p,1024,0,0, wt,1024,0,0, nullptr,512,0,0, 1024,
                                           b3, nullptr,0, 1.f,0,1,H);

    kl_kernel<<<dim3(40, BB), 256>>>();
    finalize_kernel<<<1, 1>>>((float*)d_out);
    (void)in_sizes; (void)n_in; (void)out_size;
}

// round 5
// speedup vs baseline: 2.0053x; 1.3329x over previous
#include <cuda_runtime.h>
#include <math.h>
#include <stdint.h>

// ---------------- problem constants ----------------
#define BB   16
#define SSQ  256
#define DD   512
#define KCL  20
#define NTOK 4096            // B*S
#define NZ   40960           // B*S*MC
#define NPB  2560            // S*MC
#define LOG_NORM_F (-0.91893853320467274178f)

// ---------------- scratch (device globals) ----------------
__device__ float g_q[NTOK*DD];
__device__ float g_k[NTOK*DD];
__device__ float g_v[NTOK*DD];
__device__ float g_vt[64*128*256];
__device__ float g_o[NTOK*DD];
__device__ float g_hA[NTOK*DD];
__device__ float g_hB[NTOK*DD];
__device__ float g_att[64*SSQ*SSQ];
__device__ float g_stats[NTOK*128];
__device__ float g_z[NZ*64];
__device__ float g_logqz[NZ];
__device__ float g_mu[BB*KCL*64];
__device__ float g_muacc[BB*KCL*64];
__device__ float g_m2[BB*KCL];
__device__ float g_logpi[BB*KCL];
__device__ float g_Nk[BB*KCL];
__device__ float g_post[BB*NPB*KCL];
__device__ float g_wt[1024*1024];
__device__ float g_d1[41943040];   // 40960*1024
__device__ float g_d2[41943040];
__device__ double g_rec;
__device__ double g_kl;

// ---------------- helpers ----------------
__device__ __forceinline__ float warpRedSum(float v){
#pragma unroll
    for (int o = 16; o > 0; o >>= 1) v += __shfl_xor_sync(0xffffffffu, v, o);
    return v;
}

__device__ __forceinline__ uint32_t smem_u32(const void* p){
    uint32_t a;
    asm("{ .reg .u64 t; cvta.to.shared.u64 t, %1; cvt.u32.u64 %0, t; }" : "=r"(a) : "l"(p));
    return a;
}

__device__ __forceinline__ uint32_t lds32(uint32_t addr){
    uint32_t v;
    asm volatile("ld.shared.b32 %0, [%1];" : "=r"(v) : "r"(addr));
    return v;
}

__device__ __forceinline__ uint32_t rna(uint32_t u){
    uint32_t o;
    asm("cvt.rna.tf32.f32 %0, %1;" : "=r"(o) : "f"(__uint_as_float(u)));
    return o;
}

__device__ __forceinline__ void mma8(float* d, const uint32_t* a, const uint32_t* b){
    asm volatile(
        "mma.sync.aligned.m16n8k8.row.col.f32.tf32.tf32.f32 "
        "{%0,%1,%2,%3}, {%4,%5,%6,%7}, {%8,%9}, {%0,%1,%2,%3};"
        : "+f"(d[0]), "+f"(d[1]), "+f"(d[2]), "+f"(d[3])
        : "r"(a[0]), "r"(a[1]), "r"(a[2]), "r"(a[3]), "r"(b[0]), "r"(b[1]));
}

#define CP16(dst, src) \
    asm volatile("cp.async.cg.shared.global [%0], [%1], 16;" :: "r"(dst), "l"(src))
#define CP_COMMIT() asm volatile("cp.async.commit_group;" ::: "memory")

// =======================================================================
// TF32 tensor-core GEMM: C[m,n] = epi( scale * sum_k A[m,k]*B[n,k] )
// A: [M,K] row-major (lda), B: [N,K] row-major (ldb).
// 128x128 tile, K-chunk 32, 3-stage cp.async pipeline (96KB smem).
// 8 warps (4M x 2N), warp tile 32x64 of m16n8k8 MMAs.
// Smem layout: row-major 128 rows x 128B, 16B groups XOR-swizzled by row&7.
// Fragments converted to tf32 with RNA in registers (unbiased rounding).
// Batch via blockIdx.z: off = (z>>2)*s?b + (z&3)*s?h.
// =======================================================================
__global__ __launch_bounds__(256, 2) void gemm_mma_kernel(
    const float* __restrict__ A, int lda, long long sAb, long long sAh,
    const float* __restrict__ B, int ldb, long long sBb, long long sBh,
    float* __restrict__ C, int ldc, long long sCb, long long sCh,
    int K,
    const float* __restrict__ bias,
    const float* __restrict__ residual, int ldres,
    float scale, int doRelu, int lossMode, const float* __restrict__ lossH)
{
    extern __shared__ __align__(16) char smem[];   // 3 * 32768 bytes
    const int tid = threadIdx.x;
    const int wid = tid >> 5, lane = tid & 31;

    const int zb = blockIdx.z >> 2, zh = blockIdx.z & 3;
    A += (long long)zb * sAb + (long long)zh * sAh;
    B += (long long)zb * sBb + (long long)zh * sBh;
    if (C)        C        += (long long)zb * sCb + (long long)zh * sCh;
    if (residual) residual += (long long)zb * sCb + (long long)zh * sCh;

    const int m0 = blockIdx.y * 128, n0 = blockIdx.x * 128;
    const int kTiles = K >> 5;
    const uint32_t smem0 = smem_u32(smem);

    // ---- staging assignment: thread handles one row of A (tid<128) or B
    const int srow = tid & 127;
    const bool isB = (tid >= 128);
    const float* gsrc = isB ? (B + (size_t)(n0 + srow) * ldb)
                            : (A + (size_t)(m0 + srow) * lda);
    const uint32_t sdst0 = smem0 + (isB ? 16384 : 0) + srow * 128;
    const int rx = srow & 7;

    // prologue: fill up to 3 stages
    const int pstages = kTiles < 3 ? kTiles : 3;
    for (int c = 0; c < pstages; c++){
        const float* gs = gsrc + c * 32;
        const uint32_t sd = sdst0 + (c % 3) * 32768;
#pragma unroll
        for (int j = 0; j < 8; j++)
            CP16(sd + ((j ^ rx) << 4), gs + j * 4);
        CP_COMMIT();
    }

    float acc[2][8][4];
#pragma unroll
    for (int i = 0; i < 2; i++)
#pragma unroll
        for (int j = 0; j < 8; j++)
#pragma unroll
            for (int q = 0; q < 4; q++) acc[i][j][q] = 0.f;

    const int wm = (wid & 3) * 32;
    const int wn = (wid >> 2) * 64;
    const int r7 = lane >> 2;
    const uint32_t fragA0 = smem0 + (wm + r7) * 128 + (lane & 3) * 4;
    const uint32_t fragB0 = smem0 + 16384 + (wn + r7) * 128 + (lane & 3) * 4;

    for (int c = 0; c < kTiles; c++){
        const int pend = (kTiles - c - 1) < 2 ? (kTiles - c - 1) : 2;
        if (pend == 2)      asm volatile("cp.async.wait_group 2;" ::: "memory");
        else if (pend == 1) asm volatile("cp.async.wait_group 1;" ::: "memory");
        else                asm volatile("cp.async.wait_group 0;" ::: "memory");
        __syncthreads();

        const uint32_t stoff = (c % 3) * 32768;
        const uint32_t baseA = fragA0 + stoff;
        const uint32_t baseB = fragB0 + stoff;
#pragma unroll
        for (int t = 0; t < 4; t++){
            const uint32_t g0 = (uint32_t)(((2*t)   ^ r7) << 4);
            const uint32_t g1 = (uint32_t)(((2*t+1) ^ r7) << 4);
            uint32_t a[2][4];
#pragma unroll
            for (int mt = 0; mt < 2; mt++){
                const uint32_t ab = baseA + mt * 2048;
                a[mt][0] = rna(lds32(ab + g0));
                a[mt][1] = rna(lds32(ab + 1024 + g0));
                a[mt][2] = rna(lds32(ab + g1));
                a[mt][3] = rna(lds32(ab + 1024 + g1));
            }
#pragma unroll
            for (int nt = 0; nt < 8; nt++){
                uint32_t b[2];
                b[0] = rna(lds32(baseB + nt * 1024 + g0));
                b[1] = rna(lds32(baseB + nt * 1024 + g1));
                mma8(acc[0][nt], a[0], b);
                mma8(acc[1][nt], a[1], b);
            }
        }
        __syncthreads();

        if (c + 3 < kTiles){
            const float* gs = gsrc + (c + 3) * 32;
            const uint32_t sd = sdst0 + ((c + 3) % 3) * 32768;
#pragma unroll
            for (int j = 0; j < 8; j++)
                CP16(sd + ((j ^ rx) << 4), gs + j * 4);
            CP_COMMIT();
        }
    }

    // ---- epilogue
    if (!lossMode){
#pragma unroll
        for (int mt = 0; mt < 2; mt++){
#pragma unroll
            for (int half = 0; half < 2; half++){
                int r = m0 + wm + mt*16 + (lane >> 2) + half*8;
                float* crow = C + (size_t)r * ldc;
                const float* rrow = residual ? (residual + (size_t)r * ldres) : nullptr;
#pragma unroll
                for (int nt = 0; nt < 8; nt++){
                    int col = n0 + wn + nt*8 + (lane & 3)*2;
                    float f0 = acc[mt][nt][half*2 + 0] * scale;
                    float f1 = acc[mt][nt][half*2 + 1] * scale;
                    if (bias){ f0 += bias[col]; f1 += bias[col + 1]; }
                    if (doRelu){ f0 = fmaxf(f0, 0.f); f1 = fmaxf(f1, 0.f); }
                    if (rrow){
                        float2 rv = *(const float2*)(rrow + col);
                        f0 += rv.x; f1 += rv.y;
                    }
                    *(float2*)(crow + col) = make_float2(f0, f1);
                }
            }
        }
    } else {
        double lsum = 0.0;
#pragma unroll
        for (int mt = 0; mt < 2; mt++){
#pragma unroll
            for (int half = 0; half < 2; half++){
                int r = m0 + wm + mt*16 + (lane >> 2) + half*8;
                const float* hrow = lossH + (size_t)(r / 10) * 512;
#pragma unroll
                for (int nt = 0; nt < 8; nt++){
                    int col = n0 + wn + nt*8 + (lane & 3)*2;
                    float f0 = fmaxf(acc[mt][nt][half*2 + 0] + bias[col], 0.f);
                    float f1 = fmaxf(acc[mt][nt][half*2 + 1] + bias[col + 1], 0.f);
                    float d0 = f0 - hrow[col];
                    float d1 = f1 - hrow[col + 1];
                    lsum += (double)d0 * d0 + (double)d1 * d1;
                }
            }
        }
#pragma unroll
        for (int o = 16; o > 0; o >>= 1) lsum += __shfl_xor_sync(0xffffffffu, lsum, o);
        __shared__ double ds[8];
        if (lane == 0) ds[wid] = lsum;
        __syncthreads();
        if (tid == 0){
            double t = 0;
            for (int i = 0; i < 8; i++) t += ds[i];
            atomicAdd(&g_rec, t);
        }
    }
}

// =======================================================================
// weight transpose: out[n*K + k] = W[k*N + n]
// =======================================================================
__global__ void transpose_w_kernel(const float* __restrict__ W,
                                   float* __restrict__ out, int K, int N)
{
    __shared__ float t[32][33];
    const int k0 = blockIdx.y * 32, n0 = blockIdx.x * 32;
    for (int i = threadIdx.y; i < 32; i += 8)
        t[i][threadIdx.x] = W[(size_t)(k0 + i) * N + n0 + threadIdx.x];
    __syncthreads();
    for (int i = threadIdx.y; i < 32; i += 8)
        out[(size_t)(n0 + i) * K + k0 + threadIdx.x] = t[threadIdx.x][i];
}

// g_vt[bh][n][k] = g_v[b][k][h*128+n]
__global__ void transpose_v_kernel()
{
    __shared__ float t[32][33];
    const int bh = blockIdx.z, b = bh >> 2, h = bh & 3;
    const int k0 = blockIdx.x * 32;   // seq
    const int n0 = blockIdx.y * 32;   // head-dim
    for (int i = threadIdx.y; i < 32; i += 8)
        t[i][threadIdx.x] = g_v[((size_t)b * 256 + k0 + i) * 512 + h * 128 + n0 + threadIdx.x];
    __syncthreads();
    for (int i = threadIdx.y; i < 32; i += 8)
        g_vt[((size_t)bh * 128 + n0 + i) * 256 + k0 + threadIdx.x] = t[threadIdx.x][i];
}

// =======================================================================
// fp32 SIMT GEMM (precision-sensitive stats projection only)
// =======================================================================
__global__ __launch_bounds__(256, 2) void gemm_kernel(
    const float* __restrict__ A, const float* __restrict__ W,
    float* __restrict__ C, int M, int N, int K,
    const float* __restrict__ bias)
{
    __shared__ float As[8][132];
    __shared__ float Bs[8][128];
    const int tid = threadIdx.x;
    const int m0 = blockIdx.y * 128, n0 = blockIdx.x * 128;
    const int arow = tid >> 1;
    const int aq   = (tid & 1) << 2;
    const int brow = tid >> 5;
    const int bcol = (tid & 31) << 2;
    const float* Ap = A + (size_t)(m0 + arow) * K + aq;
    const float* Wp = W + (size_t)brow * N + n0 + bcol;
    const int tx = tid & 15, ty = tid >> 4;

    float acc[8][8];
#pragma unroll
    for (int i = 0; i < 8; i++)
#pragma unroll
        for (int j = 0; j < 8; j++) acc[i][j] = 0.f;

    for (int k0 = 0; k0 < K; k0 += 8) {
        float4 av = *(const float4*)(Ap + k0);
        float4 bv = *(const float4*)(Wp + (size_t)k0 * N);
        As[aq+0][arow] = av.x; As[aq+1][arow] = av.y;
        As[aq+2][arow] = av.z; As[aq+3][arow] = av.w;
        *(float4*)&Bs[brow][bcol] = bv;
        __syncthreads();
#pragma unroll
        for (int kk = 0; kk < 8; kk++) {
            float fa[8], fb[8];
            *(float4*)&fa[0] = *(const float4*)&As[kk][ty*8];
            *(float4*)&fa[4] = *(const float4*)&As[kk][ty*8+4];
            *(float4*)&fb[0] = *(const float4*)&Bs[kk][tx*8];
            *(float4*)&fb[4] = *(const float4*)&Bs[kk][tx*8+4];
#pragma unroll
            for (int i = 0; i < 8; i++)
#pragma unroll
                for (int j = 0; j < 8; j++)
                    acc[i][j] = fmaf(fa[i], fb[j], acc[i][j]);
        }
        __syncthreads();
    }

    float bl[8];
#pragma unroll
    for (int j = 0; j < 8; j++) bl[j] = bias ? bias[n0 + tx*8 + j] : 0.f;
#pragma unroll
    for (int i = 0; i < 8; i++) {
        int m = m0 + ty*8 + i;
        float* cp = C + (size_t)m * N + n0 + tx*8;
        *(float4*)cp     = make_float4(acc[i][0]+bl[0], acc[i][1]+bl[1], acc[i][2]+bl[2], acc[i][3]+bl[3]);
        *(float4*)(cp+4) = make_float4(acc[i][4]+bl[4], acc[i][5]+bl[5], acc[i][6]+bl[6], acc[i][7]+bl[7]);
    }
}

// softmax over rows of g_att
__global__ void softmax_kernel()
{
    const int row = blockIdx.x;
    float* p = g_att + (size_t)row * SSQ;
    const int tid = threadIdx.x, lane = tid & 31, w = tid >> 5;
    __shared__ float sm[8];
    float v = p[tid];
    float m = v;
#pragma unroll
    for (int o = 16; o > 0; o >>= 1) m = fmaxf(m, __shfl_xor_sync(0xffffffffu, m, o));
    if (lane == 0) sm[w] = m;
    __syncthreads();
    float bm = sm[0];
#pragma unroll
    for (int i = 1; i < 8; i++) bm = fmaxf(bm, sm[i]);
    float e = expf(v - bm);
    float s = warpRedSum(e);
    __syncthreads();
    if (lane == 0) sm[w] = s;
    __syncthreads();
    float bs = 0.f;
#pragma unroll
    for (int i = 0; i < 8; i++) bs += sm[i];
    p[tid] = e / bs;
}

// z = mean + eps*std ; logqz
__global__ void z_kernel(const float* __restrict__ eps)
{
    const int bs = blockIdx.x, l = threadIdx.x;
    const int lane = l & 31, w = l >> 5;
    const float mean = g_stats[(size_t)bs*128 + l];
    const float lv   = g_stats[(size_t)bs*128 + 64 + l];
    const float sd = expf(0.5f * lv);
    __shared__ float sm[2];
    for (int m = 0; m < 10; m++) {
        size_t off = ((size_t)bs*10 + m)*64 + l;
        float e = eps[off];
        g_z[off] = mean + e * sd;
        float qv = warpRedSum(lv + e*e);
        if (lane == 0) sm[w] = qv;
        __syncthreads();
        if (l == 0) g_logqz[(size_t)bs*10 + m] = -0.5f*(sm[0] + sm[1]) + 64.f*LOG_NORM_F;
        __syncthreads();
    }
}

__global__ void init_mu_kernel(const int* __restrict__ idx)
{
    const int b = blockIdx.x, k = blockIdx.y, l = threadIdx.x;
    const int lane = l & 31, w = l >> 5;
    const int n = idx[b*KCL + k];
    float v = g_z[((size_t)b*NPB + n)*64 + l];
    g_mu[((size_t)b*KCL + k)*64 + l] = v;
    float s = warpRedSum(v*v);
    __shared__ float sm[2];
    if (lane == 0) sm[w] = s;
    __syncthreads();
    if (l == 0) {
        g_m2[b*KCL + k] = sm[0] + sm[1];
        g_logpi[b*KCL + k] = -2.9957322735539909f;
    }
}

// zero Nk (320) + muacc (20480)
__global__ void zero_em_kernel()
{
    int i = blockIdx.x * 256 + threadIdx.x;
    if (i < BB*KCL) g_Nk[i] = 0.f;
    if (i < BB*KCL*64) g_muacc[i] = 0.f;
}

__global__ __launch_bounds__(256) void em_post_kernel()
{
    const int b = blockIdx.y;
    const int tid = threadIdx.x, lane = tid & 31, w = tid >> 5;
    __shared__ float mus[KCL*64];
    __shared__ float sc[KCL];
    __shared__ float nkacc[KCL];
    for (int i = tid; i < KCL*64; i += 256) mus[i] = g_mu[(size_t)b*KCL*64 + i];
    if (tid < KCL) { sc[tid] = -0.5f*g_m2[b*KCL+tid] + g_logpi[b*KCL+tid]; nkacc[tid] = 0.f; }
    __syncthreads();

    float nkloc = 0.f;
    const int nbase = blockIdx.x*64 + w*8;
    for (int t = 0; t < 8; t++) {
        int n = nbase + t;
        const float* zp = g_z + ((size_t)b*NPB + n)*64;
        float z0 = zp[lane], z1 = zp[lane+32];
        float mx = -1e30f, s = 0.f, myll = 0.f;
#pragma unroll
        for (int k2 = 0; k2 < KCL; k2++) {
            float p = z0*mus[k2*64+lane] + z1*mus[k2*64+32+lane];
            p = warpRedSum(p) + sc[k2];
            if (lane == k2) myll = p;
            float nm = fmaxf(mx, p);
            s = s*expf(mx - nm) + expf(p - nm);
            mx = nm;
        }
        if (lane < KCL) {
            float pk = expf(myll - mx) / s;
            g_post[((size_t)b*NPB + n)*KCL + lane] = pk;
            nkloc += pk;
        }
    }
    if (lane < KCL) atomicAdd(&nkacc[lane], nkloc);
    __syncthreads();
    if (tid < KCL) atomicAdd(&g_Nk[b*KCL + tid], nkacc[tid]);
}

// EM accumulate: muacc[b][k][l] += sum_n post[n][k] * z[n][l]  (split over n)
__global__ __launch_bounds__(256) void em_acc_kernel()
{
    const int b = blockIdx.y, s = blockIdx.x;
    const int tid = threadIdx.x;
    const int l = tid & 63, kq = tid >> 6;   // kq 0..3 -> k = kq*5 + j
    __shared__ float zt[16][64];
    __shared__ float pt[16][20];
    float acc[5] = {0.f, 0.f, 0.f, 0.f, 0.f};
    const int n0 = s * 320;
    for (int g = 0; g < 20; g++){
        const int nb = n0 + g * 16;
        const float* zsrc = g_z + ((size_t)b*NPB + nb)*64;
        for (int i = tid; i < 1024; i += 256) ((float*)zt)[i] = zsrc[i];
        const float* psrc = g_post + ((size_t)b*NPB + nb)*KCL;
        for (int i = tid; i < 320; i += 256) ((float*)pt)[i] = psrc[i];
        __syncthreads();
#pragma unroll
        for (int nn = 0; nn < 16; nn++){
            float zv = zt[nn][l];
#pragma unroll
            for (int j = 0; j < 5; j++)
                acc[j] = fmaf(pt[nn][kq*5 + j], zv, acc[j]);
        }
        __syncthreads();
    }
#pragma unroll
    for (int j = 0; j < 5; j++)
        atomicAdd(&g_muacc[((size_t)b*KCL + kq*5 + j)*64 + l], acc[j]);
}

// EM finalize: mu = muacc/Nk, m2, logpi
__global__ void em_fin_kernel()
{
    const int k = blockIdx.x, b = blockIdx.y, l = threadIdx.x;
    const int lane = l & 31, w = l >> 5;
    float nk = g_Nk[b*KCL + k];
    float m = g_muacc[((size_t)b*KCL + k)*64 + l] / nk;
    g_mu[((size_t)b*KCL + k)*64 + l] = m;
    float s = warpRedSum(m*m);
    __shared__ float sm[2];
    if (lane == 0) sm[w] = s;
    __syncthreads();
    if (l == 0) {
        g_m2[b*KCL + k] = sm[0] + sm[1];
        float tot = 0.f;
        for (int j = 0; j < KCL; j++) tot += g_Nk[b*KCL + j];
        g_logpi[b*KCL + k] = logf(nk / tot);
    }
}

__global__ __launch_bounds__(256) void kl_kernel()
{
    const int b = blockIdx.y;
    const int tid = threadIdx.x, lane = tid & 31, w = tid >> 5;
    __shared__ float mus[KCL*64];
    __shared__ float sc[KCL];
    for (int i = tid; i < KCL*64; i += 256) mus[i] = g_mu[(size_t)b*KCL*64 + i];
    if (tid < KCL) sc[tid] = -0.5f*g_m2[b*KCL+tid] + g_logpi[b*KCL+tid];
    __syncthreads();

    double loc = 0.0;
    const int nbase = blockIdx.x*64 + w*8;
    for (int t = 0; t < 8; t++) {
        int n = nbase + t;
        const float* zp = g_z + ((size_t)b*NPB + n)*64;
        float z0 = zp[lane], z1 = zp[lane+32];
        float sq = warpRedSum(z0*z0 + z1*z1);
        float mx = -1e30f, s = 0.f;
#pragma unroll
        for (int k2 = 0; k2 < KCL; k2++) {
            float p = z0*mus[k2*64+lane] + z1*mus[k2*64+32+lane];
            p = warpRedSum(p) + sc[k2];
            float nm = fmaxf(mx, p);
            s = s*expf(mx - nm) + expf(p - nm);
            mx = nm;
        }
        float lpz = mx + logf(s) - 0.5f*sq + 64.f*LOG_NORM_F;
        if (lane == 0) loc += (double)(g_logqz[(size_t)b*NPB + n] - lpz);
    }
    __shared__ double dacc[8];
    if (lane == 0) dacc[w] = loc;
    __syncthreads();
    if (tid == 0) {
        double t = 0;
        for (int i = 0; i < 8; i++) t += dacc[i];
        atomicAdd(&g_kl, t);
    }
}

__global__ void zero_accum_kernel() { g_rec = 0.0; g_kl = 0.0; }

__global__ void finalize_kernel(float* __restrict__ out)
{
    out[0] = (float)(g_rec / 40960.0);
    out[1] = (float)(g_kl / 40960.0);
}

// ---------------- host ----------------
static void* symaddr(const void* s)
{
    void* p = nullptr;
    cudaGetSymbolAddress(&p, s);
    return p;
}

#define GEMM_SMEM 98304

extern "C" void kernel_launch(void* const* d_in, const int* in_sizes, int n_in,
                              void* d_out, int out_size)
{
    const float *H, *eps, *wq, *bq, *wk, *bk, *wv, *bv, *wo, *bo, *wz, *bz;
    const float *w1, *b1, *w2, *b2, *w3, *b3;
    const int* init_idx;

    if (n_in >= 3 && in_sizes[2] == 320) {
        H = (const float*)d_in[0];  eps = (const float*)d_in[1]; init_idx = (const int*)d_in[2];
        wq = (const float*)d_in[3]; bq = (const float*)d_in[4];
        wk = (const float*)d_in[5]; bk = (const float*)d_in[6];
        wv = (const float*)d_in[7]; bv = (const float*)d_in[8];
        wo = (const float*)d_in[9]; bo = (const float*)d_in[10];
        wz = (const float*)d_in[11]; bz = (const float*)d_in[12];
        w1 = (const float*)d_in[13]; b1 = (const float*)d_in[14];
        w2 = (const float*)d_in[15]; b2 = (const float*)d_in[16];
        w3 = (const float*)d_in[17]; b3 = (const float*)d_in[18];
    } else {
        H = (const float*)d_in[0];  eps = (const float*)d_in[1];
        wq = (const float*)d_in[2]; bq = (const float*)d_in[3];
        wk = (const float*)d_in[4]; bk = (const float*)d_in[5];
        wv = (const float*)d_in[6]; bv = (const float*)d_in[7];
        wo = (const float*)d_in[8]; bo = (const float*)d_in[9];
        wz = (const float*)d_in[10]; bz = (const float*)d_in[11];
        w1 = (const float*)d_in[12]; b1 = (const float*)d_in[13];
        w2 = (const float*)d_in[14]; b2 = (const float*)d_in[15];
        w3 = (const float*)d_in[16]; b3 = (const float*)d_in[17];
        init_idx = (const int*)d_in[18];
    }

    cudaFuncSetAttribute(gemm_mma_kernel,
                         cudaFuncAttributeMaxDynamicSharedMemorySize, GEMM_SMEM);

    float* qp  = (float*)symaddr(g_q);
    float* kp  = (float*)symaddr(g_k);
    float* vp  = (float*)symaddr(g_v);
    float* op  = (float*)symaddr(g_o);
    float* hA  = (float*)symaddr(g_hA);
    float* hB  = (float*)symaddr(g_hB);
    float* attp= (float*)symaddr(g_att);
    float* st  = (float*)symaddr(g_stats);
    float* zp  = (float*)symaddr(g_z);
    float* wt  = (float*)symaddr(g_wt);
    float* d1p = (float*)symaddr(g_d1);
    float* d2p = (float*)symaddr(g_d2);
    float* vtp = (float*)symaddr(g_vt);

    zero_accum_kernel<<<1, 1>>>();

    const float scl = 0.044194173824159216f; // 1/sqrt(512)
    const float* xin = H;
    float* layer_out[2] = { hA, hB };
    for (int i = 0; i < 2; i++) {
        const size_t woff = (size_t)i * DD * DD;
        const size_t boff = (size_t)i * DD;

        transpose_w_kernel<<<dim3(16,16), dim3(32,8)>>>(wq + woff, wt, 512, 512);
        gemm_mma_kernel<<<dim3(4,32,1), 256, GEMM_SMEM>>>(xin,512,0,0, wt,512,0,0, qp,512,0,0, 512,
                                              bq+boff, nullptr,0, 1.f,0,0,nullptr);
        transpose_w_kernel<<<dim3(16,16), dim3(32,8)>>>(wk + woff, wt, 512, 512);
        gemm_mma_kernel<<<dim3(4,32,1), 256, GEMM_SMEM>>>(xin,512,0,0, wt,512,0,0, kp,512,0,0, 512,
                                              bk+boff, nullptr,0, 1.f,0,0,nullptr);
        transpose_w_kernel<<<dim3(16,16), dim3(32,8)>>>(wv + woff, wt, 512, 512);
        gemm_mma_kernel<<<dim3(4,32,1), 256, GEMM_SMEM>>>(xin,512,0,0, wt,512,0,0, vp,512,0,0, 512,
                                              bv+boff, nullptr,0, 1.f,0,0,nullptr);

        // scores = q k^T / sqrt(D)   (batched over 64 bh)
        gemm_mma_kernel<<<dim3(2,2,64), 256, GEMM_SMEM>>>(qp,512,131072,128, kp,512,131072,128,
                                              attp,256,262144,65536, 128,
                                              nullptr, nullptr,0, scl,0,0,nullptr);
        softmax_kernel<<<64*SSQ, 256>>>();

        // o = q + att @ v
        transpose_v_kernel<<<dim3(8,4,64), dim3(32,8)>>>();
        gemm_mma_kernel<<<dim3(1,2,64), 256, GEMM_SMEM>>>(attp,256,262144,65536, vtp,256,131072,32768,
                                              op,512,131072,128, 256,
                                              nullptr, qp,512, 1.f,0,0,nullptr);

        // out = o + relu(o @ wo + bo)
        transpose_w_kernel<<<dim3(16,16), dim3(32,8)>>>(wo + woff, wt, 512, 512);
        gemm_mma_kernel<<<dim3(4,32,1), 256, GEMM_SMEM>>>(op,512,0,0, wt,512,0,0, layer_out[i],512,0,0, 512,
                                              bo+boff, op,512, 1.f,1,0,nullptr);
        xin = layer_out[i];
    }

    // stats (precision-sensitive): fp32 SIMT
    gemm_kernel<<<dim3(1, 32), 256>>>(xin, wz, st, NTOK, 128, DD, bz);

    z_kernel<<<NTOK, 64>>>(eps);
    init_mu_kernel<<<dim3(BB, KCL), 64>>>(init_idx);

    for (int it = 0; it < 5; it++) {
        zero_em_kernel<<<82, 256>>>();
        em_post_kernel<<<dim3(40, BB), 256>>>();
        em_acc_kernel<<<dim3(8, BB), 256>>>();
        em_fin_kernel<<<dim3(KCL, BB), 64>>>();
    }

    // decoder
    transpose_w_kernel<<<dim3(32,2), dim3(32,8)>>>(w1, wt, 64, 1024);
    gemm_mma_kernel<<<dim3(8,320,1), 256, GEMM_SMEM>>>(zp,64,0,0, wt,64,0,0, d1p,1024,0,0, 64,
                                           b1, nullptr,0, 1.f,1,0,nullptr);
    transpose_w_kernel<<<dim3(32,32), dim3(32,8)>>>(w2, wt, 1024, 1024);
    gemm_mma_kernel<<<dim3(8,320,1), 256, GEMM_SMEM>>>(d1p,1024,0,0, wt,1024,0,0, d2p,1024,0,0, 1024,
                                           b2, nullptr,0, 1.f,1,0,nullptr);
    transpose_w_kernel<<<dim3(16,32), dim3(32,8)>>>(w3, wt, 1024, 512);
    gemm_mma_kernel<<<dim3(4,320,1), 256, GEMM_SMEM>>>(d2p,1024,0,0, wt,1024,0,0, nullptr,512,0,0, 1024,
                                           b3, nullptr,0, 1.f,0,1,H);

    kl_kernel<<<dim3(40, BB), 256>>>();
    finalize_kernel<<<1, 1>>>((float*)d_out);
    (void)in_sizes; (void)n_in; (void)out_size;
}

// round 6
// speedup vs baseline: 2.1298x; 1.0621x over previous
#include <cuda_runtime.h>
#include <math.h>
#include <stdint.h>

// ---------------- problem constants ----------------
#define BB   16
#define SSQ  256
#define DD   512
#define KCL  20
#define NTOK 4096            // B*S
#define NZ   40960           // B*S*MC
#define NPB  2560            // S*MC
#define LOG_NORM_F (-0.91893853320467274178f)

// ---------------- scratch (device globals) ----------------
__device__ float g_Hr[NTOK*DD];          // rounded H (GEMM A input)
__device__ float g_q[NTOK*DD];           // raw q (residual)
__device__ float g_qr[NTOK*DD];          // rounded q (scores A)
__device__ float g_k[NTOK*DD];           // rounded
__device__ float g_v[NTOK*DD];           // rounded
__device__ float g_vt[64*128*256];       // rounded (transposed v)
__device__ float g_o[NTOK*DD];           // raw o (residual)
__device__ float g_or[NTOK*DD];          // rounded o (wo-GEMM A)
__device__ float g_hA[NTOK*DD];          // raw layer out
__device__ float g_hAr[NTOK*DD];         // rounded
__device__ float g_hB[NTOK*DD];
__device__ float g_hBr[NTOK*DD];
__device__ float g_att[64*SSQ*SSQ];      // rounded by softmax
__device__ float g_stats[NTOK*128];
__device__ float g_z[NZ*64];             // raw (EM/KL)
__device__ float g_zr[NZ*64];            // rounded (decoder A)
__device__ float g_logqz[NZ];
__device__ float g_mu[BB*KCL*64];
__device__ float g_muacc[BB*KCL*64];
__device__ float g_m2[BB*KCL];
__device__ float g_logpi[BB*KCL];
__device__ float g_Nk[BB*KCL];
__device__ float g_post[BB*NPB*KCL];
__device__ float g_wt[1024*1024];        // rounded weights (transposed)
__device__ float g_d1[41943040];         // 40960*1024, rounded
__device__ float g_d2[41943040];         // rounded
__device__ double g_rec;
__device__ double g_kl;

// ---------------- helpers ----------------
__device__ __forceinline__ float warpRedSum(float v){
#pragma unroll
    for (int o = 16; o > 0; o >>= 1) v += __shfl_xor_sync(0xffffffffu, v, o);
    return v;
}

__device__ __forceinline__ uint32_t smem_u32(const void* p){
    uint32_t a;
    asm("{ .reg .u64 t; cvta.to.shared.u64 t, %1; cvt.u32.u64 %0, t; }" : "=r"(a) : "l"(p));
    return a;
}

__device__ __forceinline__ float rnaf(float x){
    uint32_t o;
    asm("cvt.rna.tf32.f32 %0, %1;" : "=r"(o) : "f"(x));
    return __uint_as_float(o);
}

__device__ __forceinline__ void ldsm4(uint32_t* r, uint32_t addr){
    asm volatile("ldmatrix.sync.aligned.m8n8.x4.shared.b16 {%0,%1,%2,%3}, [%4];"
        : "=r"(r[0]), "=r"(r[1]), "=r"(r[2]), "=r"(r[3]) : "r"(addr));
}

__device__ __forceinline__ void mma8(float* d, const uint32_t* a, const uint32_t* b){
    asm volatile(
        "mma.sync.aligned.m16n8k8.row.col.f32.tf32.tf32.f32 "
        "{%0,%1,%2,%3}, {%4,%5,%6,%7}, {%8,%9}, {%0,%1,%2,%3};"
        : "+f"(d[0]), "+f"(d[1]), "+f"(d[2]), "+f"(d[3])
        : "r"(a[0]), "r"(a[1]), "r"(a[2]), "r"(a[3]), "r"(b[0]), "r"(b[1]));
}

#define CP16(dst, src) \
    asm volatile("cp.async.cg.shared.global [%0], [%1], 16;" :: "r"(dst), "l"(src))
#define CP_COMMIT() asm volatile("cp.async.commit_group;" ::: "memory")

// =======================================================================
// TF32 tensor-core GEMM: C[m,n] = epi( scale * sum_k A[m,k]*B[n,k] )
// A: [M,K] row-major (lda), B: [N,K] row-major (ldb). BOTH PRE-ROUNDED tf32.
// 128x128 tile, K-chunk 32, 3-stage cp.async pipeline (96KB smem).
// 8 warps (4M x 2N), warp tile 32x64 of m16n8k8 MMAs.
// Fragments loaded via ldmatrix.x4 from XOR-swizzled row-major smem.
// Batch via blockIdx.z: off = (z>>2)*s?b + (z&3)*s?h.
// =======================================================================
__global__ __launch_bounds__(256, 2) void gemm_mma_kernel(
    const float* __restrict__ A, int lda, long long sAb, long long sAh,
    const float* __restrict__ B, int ldb, long long sBb, long long sBh,
    float* __restrict__ C, int ldc, long long sCb, long long sCh,
    float* __restrict__ Cr,
    int K,
    const float* __restrict__ bias,
    const float* __restrict__ residual, int ldres,
    float scale, int doRelu, int roundC, int lossMode,
    const float* __restrict__ lossH)
{
    extern __shared__ __align__(16) char smem[];   // 3 * 32768 bytes
    const int tid = threadIdx.x;
    const int wid = tid >> 5, lane = tid & 31;

    const int zb = blockIdx.z >> 2, zh = blockIdx.z & 3;
    A += (long long)zb * sAb + (long long)zh * sAh;
    B += (long long)zb * sBb + (long long)zh * sBh;
    if (C)        C        += (long long)zb * sCb + (long long)zh * sCh;
    if (Cr)       Cr       += (long long)zb * sCb + (long long)zh * sCh;
    if (residual) residual += (long long)zb * sCb + (long long)zh * sCh;

    const int m0 = blockIdx.y * 128, n0 = blockIdx.x * 128;
    const int kTiles = K >> 5;
    const uint32_t smem0 = smem_u32(smem);

    // ---- staging: thread handles one row of A (tid<128) or B
    const int srow = tid & 127;
    const bool isB = (tid >= 128);
    const float* gsrc = isB ? (B + (size_t)(n0 + srow) * ldb)
                            : (A + (size_t)(m0 + srow) * lda);
    const uint32_t sdst0 = smem0 + (isB ? 16384 : 0) + srow * 128;
    const int rx = srow & 7;

    const int pstages = kTiles < 3 ? kTiles : 3;
    for (int c = 0; c < pstages; c++){
        const float* gs = gsrc + c * 32;
        const uint32_t sd = sdst0 + (c % 3) * 32768;
#pragma unroll
        for (int j = 0; j < 8; j++)
            CP16(sd + ((j ^ rx) << 4), gs + j * 4);
        CP_COMMIT();
    }

    float acc[2][8][4];
#pragma unroll
    for (int i = 0; i < 2; i++)
#pragma unroll
        for (int j = 0; j < 8; j++)
#pragma unroll
            for (int q = 0; q < 4; q++) acc[i][j][q] = 0.f;

    const int wm = (wid & 3) * 32;
    const int wn = (wid >> 2) * 64;

    // ldmatrix lane decomposition
    const int rr = lane & 7;          // row within 8-row matrix
    const int qm = lane >> 3;         // matrix id 0..3
    const int qlow = qm & 1, qhigh = qm >> 1;
    // A x4 for (mt): matrices = {rows M..M+7 g=2t, M+8..M+15 g=2t, M..M+7 g=2t+1, M+8..+15 g=2t+1}
    // lane's row = wm + mt*16 + rr + 8*qlow ; group = 2t + qhigh
    uint32_t rowbaseA[2];
#pragma unroll
    for (int mt = 0; mt < 2; mt++)
        rowbaseA[mt] = (uint32_t)((wm + mt*16 + rr + 8*qlow) * 128);
    // B x4 for nt-pair p: matrices = {nt=2p g=2t, nt=2p g=2t+1, nt=2p+1 g=2t, nt=2p+1 g=2t+1}
    // lane's row = wn + (2p + qhigh)*8 + rr ; group = 2t + qlow
    uint32_t rowbaseB[4];
#pragma unroll
    for (int p = 0; p < 4; p++)
        rowbaseB[p] = (uint32_t)(16384 + (wn + (2*p + qhigh)*8 + rr) * 128);

    for (int c = 0; c < kTiles; c++){
        const int pend = (kTiles - c - 1) < 2 ? (kTiles - c - 1) : 2;
        if (pend == 2)      asm volatile("cp.async.wait_group 2;" ::: "memory");
        else if (pend == 1) asm volatile("cp.async.wait_group 1;" ::: "memory");
        else                asm volatile("cp.async.wait_group 0;" ::: "memory");
        __syncthreads();

        const uint32_t st = smem0 + (c % 3) * 32768;
#pragma unroll
        for (int t = 0; t < 4; t++){
            const uint32_t offA = (uint32_t)(((2*t + qhigh) ^ rr) << 4);
            const uint32_t offB = (uint32_t)(((2*t + qlow) ^ rr) << 4);
            uint32_t a[2][4], bb[4][4];
            ldsm4(a[0], st + rowbaseA[0] + offA);
            ldsm4(a[1], st + rowbaseA[1] + offA);
#pragma unroll
            for (int p = 0; p < 4; p++)
                ldsm4(bb[p], st + rowbaseB[p] + offB);
#pragma unroll
            for (int p = 0; p < 4; p++){
                mma8(acc[0][2*p+0], a[0], &bb[p][0]);
                mma8(acc[1][2*p+0], a[1], &bb[p][0]);
                mma8(acc[0][2*p+1], a[0], &bb[p][2]);
                mma8(acc[1][2*p+1], a[1], &bb[p][2]);
            }
        }
        __syncthreads();

        if (c + 3 < kTiles){
            const float* gs = gsrc + (c + 3) * 32;
            const uint32_t sd = sdst0 + ((c + 3) % 3) * 32768;
#pragma unroll
            for (int j = 0; j < 8; j++)
                CP16(sd + ((j ^ rx) << 4), gs + j * 4);
            CP_COMMIT();
        }
    }

    // ---- epilogue
    if (!lossMode){
#pragma unroll
        for (int mt = 0; mt < 2; mt++){
#pragma unroll
            for (int half = 0; half < 2; half++){
                int r = m0 + wm + mt*16 + (lane >> 2) + half*8;
                float* crow = C + (size_t)r * ldc;
                float* crow2 = Cr ? (Cr + (size_t)r * ldc) : nullptr;
                const float* rrow = residual ? (residual + (size_t)r * ldres) : nullptr;
#pragma unroll
                for (int nt = 0; nt < 8; nt++){
                    int col = n0 + wn + nt*8 + (lane & 3)*2;
                    float f0 = acc[mt][nt][half*2 + 0] * scale;
                    float f1 = acc[mt][nt][half*2 + 1] * scale;
                    if (bias){ f0 += bias[col]; f1 += bias[col + 1]; }
                    if (doRelu){ f0 = fmaxf(f0, 0.f); f1 = fmaxf(f1, 0.f); }
                    if (rrow){
                        float2 rv = *(const float2*)(rrow + col);
                        f0 += rv.x; f1 += rv.y;
                    }
                    if (roundC){ f0 = rnaf(f0); f1 = rnaf(f1); }
                    *(float2*)(crow + col) = make_float2(f0, f1);
                    if (crow2)
                        *(float2*)(crow2 + col) = make_float2(rnaf(f0), rnaf(f1));
                }
            }
        }
    } else {
        double lsum = 0.0;
#pragma unroll
        for (int mt = 0; mt < 2; mt++){
#pragma unroll
            for (int half = 0; half < 2; half++){
                int r = m0 + wm + mt*16 + (lane >> 2) + half*8;
                const float* hrow = lossH + (size_t)(r / 10) * 512;
#pragma unroll
                for (int nt = 0; nt < 8; nt++){
                    int col = n0 + wn + nt*8 + (lane & 3)*2;
                    float f0 = fmaxf(acc[mt][nt][half*2 + 0] + bias[col], 0.f);
                    float f1 = fmaxf(acc[mt][nt][half*2 + 1] + bias[col + 1], 0.f);
                    float d0 = f0 - hrow[col];
                    float d1 = f1 - hrow[col + 1];
                    lsum += (double)d0 * d0 + (double)d1 * d1;
                }
            }
        }
#pragma unroll
        for (int o = 16; o > 0; o >>= 1) lsum += __shfl_xor_sync(0xffffffffu, lsum, o);
        __shared__ double ds[8];
        if (lane == 0) ds[wid] = lsum;
        __syncthreads();
        if (tid == 0){
            double t = 0;
            for (int i = 0; i < 8; i++) t += ds[i];
            atomicAdd(&g_rec, t);
        }
    }
}

// =======================================================================
// weight transpose (+ tf32 RNA rounding): out[n*K + k] = rna(W[k*N + n])
// =======================================================================
__global__ void transpose_w_kernel(const float* __restrict__ W,
                                   float* __restrict__ out, int K, int N)
{
    __shared__ float t[32][33];
    const int k0 = blockIdx.y * 32, n0 = blockIdx.x * 32;
    for (int i = threadIdx.y; i < 32; i += 8)
        t[i][threadIdx.x] = W[(size_t)(k0 + i) * N + n0 + threadIdx.x];
    __syncthreads();
    for (int i = threadIdx.y; i < 32; i += 8)
        out[(size_t)(n0 + i) * K + k0 + threadIdx.x] = rnaf(t[threadIdx.x][i]);
}

// g_vt[bh][n][k] = g_v[b][k][h*128+n]   (v already rounded)
__global__ void transpose_v_kernel()
{
    __shared__ float t[32][33];
    const int bh = blockIdx.z, b = bh >> 2, h = bh & 3;
    const int k0 = blockIdx.x * 32;
    const int n0 = blockIdx.y * 32;
    for (int i = threadIdx.y; i < 32; i += 8)
        t[i][threadIdx.x] = g_v[((size_t)b * 256 + k0 + i) * 512 + h * 128 + n0 + threadIdx.x];
    __syncthreads();
    for (int i = threadIdx.y; i < 32; i += 8)
        g_vt[((size_t)bh * 128 + n0 + i) * 256 + k0 + threadIdx.x] = t[threadIdx.x][i];
}

// rounded copy of H
__global__ void round_h_kernel(const float* __restrict__ H)
{
    int i = blockIdx.x * 256 + threadIdx.x;
    float4 v = *(const float4*)(H + i * 4);
    *(float4*)(g_Hr + i * 4) = make_float4(rnaf(v.x), rnaf(v.y), rnaf(v.z), rnaf(v.w));
}

// =======================================================================
// fp32 SIMT GEMM (precision-sensitive stats projection only)
// =======================================================================
__global__ __launch_bounds__(256, 2) void gemm_kernel(
    const float* __restrict__ A, const float* __restrict__ W,
    float* __restrict__ C, int M, int N, int K,
    const float* __restrict__ bias)
{
    __shared__ float As[8][132];
    __shared__ float Bs[8][128];
    const int tid = threadIdx.x;
    const int m0 = blockIdx.y * 128, n0 = blockIdx.x * 128;
    const int arow = tid >> 1;
    const int aq   = (tid & 1) << 2;
    const int brow = tid >> 5;
    const int bcol = (tid & 31) << 2;
    const float* Ap = A + (size_t)(m0 + arow) * K + aq;
    const float* Wp = W + (size_t)brow * N + n0 + bcol;
    const int tx = tid & 15, ty = tid >> 4;

    float acc[8][8];
#pragma unroll
    for (int i = 0; i < 8; i++)
#pragma unroll
        for (int j = 0; j < 8; j++) acc[i][j] = 0.f;

    for (int k0 = 0; k0 < K; k0 += 8) {
        float4 av = *(const float4*)(Ap + k0);
        float4 bv = *(const float4*)(Wp + (size_t)k0 * N);
        As[aq+0][arow] = av.x; As[aq+1][arow] = av.y;
        As[aq+2][arow] = av.z; As[aq+3][arow] = av.w;
        *(float4*)&Bs[brow][bcol] = bv;
        __syncthreads();
#pragma unroll
        for (int kk = 0; kk < 8; kk++) {
            float fa[8], fb[8];
            *(float4*)&fa[0] = *(const float4*)&As[kk][ty*8];
            *(float4*)&fa[4] = *(const float4*)&As[kk][ty*8+4];
            *(float4*)&fb[0] = *(const float4*)&Bs[kk][tx*8];
            *(float4*)&fb[4] = *(const float4*)&Bs[kk][tx*8+4];
#pragma unroll
            for (int i = 0; i < 8; i++)
#pragma unroll
                for (int j = 0; j < 8; j++)
                    acc[i][j] = fmaf(fa[i], fb[j], acc[i][j]);
        }
        __syncthreads();
    }

    float bl[8];
#pragma unroll
    for (int j = 0; j < 8; j++) bl[j] = bias ? bias[n0 + tx*8 + j] : 0.f;
#pragma unroll
    for (int i = 0; i < 8; i++) {
        int m = m0 + ty*8 + i;
        float* cp = C + (size_t)m * N + n0 + tx*8;
        *(float4*)cp     = make_float4(acc[i][0]+bl[0], acc[i][1]+bl[1], acc[i][2]+bl[2], acc[i][3]+bl[3]);
        *(float4*)(cp+4) = make_float4(acc[i][4]+bl[4], acc[i][5]+bl[5], acc[i][6]+bl[6], acc[i][7]+bl[7]);
    }
}

// softmax over rows of g_att ; output rounded (used only as GEMM A)
__global__ void softmax_kernel()
{
    const int row = blockIdx.x;
    float* p = g_att + (size_t)row * SSQ;
    const int tid = threadIdx.x, lane = tid & 31, w = tid >> 5;
    __shared__ float sm[8];
    float v = p[tid];
    float m = v;
#pragma unroll
    for (int o = 16; o > 0; o >>= 1) m = fmaxf(m, __shfl_xor_sync(0xffffffffu, m, o));
    if (lane == 0) sm[w] = m;
    __syncthreads();
    float bm = sm[0];
#pragma unroll
    for (int i = 1; i < 8; i++) bm = fmaxf(bm, sm[i]);
    float e = expf(v - bm);
    float s = warpRedSum(e);
    __syncthreads();
    if (lane == 0) sm[w] = s;
    __syncthreads();
    float bs = 0.f;
#pragma unroll
    for (int i = 0; i < 8; i++) bs += sm[i];
    p[tid] = rnaf(e / bs);
}

// z = mean + eps*std (raw + rounded) ; logqz
__global__ void z_kernel(const float* __restrict__ eps)
{
    const int bs = blockIdx.x, l = threadIdx.x;
    const int lane = l & 31, w = l >> 5;
    const float mean = g_stats[(size_t)bs*128 + l];
    const float lv   = g_stats[(size_t)bs*128 + 64 + l];
    const float sd = expf(0.5f * lv);
    __shared__ float sm[2];
    for (int m = 0; m < 10; m++) {
        size_t off = ((size_t)bs*10 + m)*64 + l;
        float e = eps[off];
        float zv = mean + e * sd;
        g_z[off] = zv;
        g_zr[off] = rnaf(zv);
        float qv = warpRedSum(lv + e*e);
        if (lane == 0) sm[w] = qv;
        __syncthreads();
        if (l == 0) g_logqz[(size_t)bs*10 + m] = -0.5f*(sm[0] + sm[1]) + 64.f*LOG_NORM_F;
        __syncthreads();
    }
}

__global__ void init_mu_kernel(const int* __restrict__ idx)
{
    const int b = blockIdx.x, k = blockIdx.y, l = threadIdx.x;
    const int lane = l & 31, w = l >> 5;
    const int n = idx[b*KCL + k];
    float v = g_z[((size_t)b*NPB + n)*64 + l];
    g_mu[((size_t)b*KCL + k)*64 + l] = v;
    float s = warpRedSum(v*v);
    __shared__ float sm[2];
    if (lane == 0) sm[w] = s;
    __syncthreads();
    if (l == 0) {
        g_m2[b*KCL + k] = sm[0] + sm[1];
        g_logpi[b*KCL + k] = -2.9957322735539909f;
    }
}

// zero Nk (320) + muacc (20480)
__global__ void zero_em_kernel()
{
    int i = blockIdx.x * 256 + threadIdx.x;
    if (i < BB*KCL) g_Nk[i] = 0.f;
    if (i < BB*KCL*64) g_muacc[i] = 0.f;
}

__global__ __launch_bounds__(256) void em_post_kernel()
{
    const int b = blockIdx.y;
    const int tid = threadIdx.x, lane = tid & 31, w = tid >> 5;
    __shared__ float mus[KCL*64];
    __shared__ float sc[KCL];
    __shared__ float nkacc[KCL];
    for (int i = tid; i < KCL*64; i += 256) mus[i] = g_mu[(size_t)b*KCL*64 + i];
    if (tid < KCL) { sc[tid] = -0.5f*g_m2[b*KCL+tid] + g_logpi[b*KCL+tid]; nkacc[tid] = 0.f; }
    __syncthreads();

    float nkloc = 0.f;
    const int nbase = blockIdx.x*64 + w*8;
    for (int t = 0; t < 8; t++) {
        int n = nbase + t;
        const float* zp = g_z + ((size_t)b*NPB + n)*64;
        float z0 = zp[lane], z1 = zp[lane+32];
        float mx = -1e30f, s = 0.f, myll = 0.f;
#pragma unroll
        for (int k2 = 0; k2 < KCL; k2++) {
            float p = z0*mus[k2*64+lane] + z1*mus[k2*64+32+lane];
            p = warpRedSum(p) + sc[k2];
            if (lane == k2) myll = p;
            float nm = fmaxf(mx, p);
            s = s*expf(mx - nm) + expf(p - nm);
            mx = nm;
        }
        if (lane < KCL) {
            float pk = expf(myll - mx) / s;
            g_post[((size_t)b*NPB + n)*KCL + lane] = pk;
            nkloc += pk;
        }
    }
    if (lane < KCL) atomicAdd(&nkacc[lane], nkloc);
    __syncthreads();
    if (tid < KCL) atomicAdd(&g_Nk[b*KCL + tid], nkacc[tid]);
}

// EM accumulate: muacc[b][k][l] += sum_n post[n][k] * z[n][l]
__global__ __launch_bounds__(256) void em_acc_kernel()
{
    const int b = blockIdx.y, s = blockIdx.x;
    const int tid = threadIdx.x;
    const int l = tid & 63, kq = tid >> 6;
    __shared__ float zt[16][64];
    __shared__ float pt[16][20];
    float acc[5] = {0.f, 0.f, 0.f, 0.f, 0.f};
    const int n0 = s * 320;
    for (int g = 0; g < 20; g++){
        const int nb = n0 + g * 16;
        const float* zsrc = g_z + ((size_t)b*NPB + nb)*64;
        for (int i = tid; i < 1024; i += 256) ((float*)zt)[i] = zsrc[i];
        const float* psrc = g_post + ((size_t)b*NPB + nb)*KCL;
        for (int i = tid; i < 320; i += 256) ((float*)pt)[i] = psrc[i];
        __syncthreads();
#pragma unroll
        for (int nn = 0; nn < 16; nn++){
            float zv = zt[nn][l];
#pragma unroll
            for (int j = 0; j < 5; j++)
                acc[j] = fmaf(pt[nn][kq*5 + j], zv, acc[j]);
        }
        __syncthreads();
    }
#pragma unroll
    for (int j = 0; j < 5; j++)
        atomicAdd(&g_muacc[((size_t)b*KCL + kq*5 + j)*64 + l], acc[j]);
}

// EM finalize: mu = muacc/Nk, m2, logpi
__global__ void em_fin_kernel()
{
    const int k = blockIdx.x, b = blockIdx.y, l = threadIdx.x;
    const int lane = l & 31, w = l >> 5;
    float nk = g_Nk[b*KCL + k];
    float m = g_muacc[((size_t)b*KCL + k)*64 + l] / nk;
    g_mu[((size_t)b*KCL + k)*64 + l] = m;
    float s = warpRedSum(m*m);
    __shared__ float sm[2];
    if (lane == 0) sm[w] = s;
    __syncthreads();
    if (l == 0) {
        g_m2[b*KCL + k] = sm[0] + sm[1];
        float tot = 0.f;
        for (int j = 0; j < KCL; j++) tot += g_Nk[b*KCL + j];
        g_logpi[b*KCL + k] = logf(nk / tot);
    }
}

__global__ __launch_bounds__(256) void kl_kernel()
{
    const int b = blockIdx.y;
    const int tid = threadIdx.x, lane = tid & 31, w = tid >> 5;
    __shared__ float mus[KCL*64];
    __shared__ float sc[KCL];
    for (int i = tid; i < KCL*64; i += 256) mus[i] = g_mu[(size_t)b*KCL*64 + i];
    if (tid < KCL) sc[tid] = -0.5f*g_m2[b*KCL+tid] + g_logpi[b*KCL+tid];
    __syncthreads();

    double loc = 0.0;
    const int nbase = blockIdx.x*64 + w*8;
    for (int t = 0; t < 8; t++) {
        int n = nbase + t;
        const float* zp = g_z + ((size_t)b*NPB + n)*64;
        float z0 = zp[lane], z1 = zp[lane+32];
        float sq = warpRedSum(z0*z0 + z1*z1);
        float mx = -1e30f, s = 0.f;
#pragma unroll
        for (int k2 = 0; k2 < KCL; k2++) {
            float p = z0*mus[k2*64+lane] + z1*mus[k2*64+32+lane];
            p = warpRedSum(p) + sc[k2];
            float nm = fmaxf(mx, p);
            s = s*expf(mx - nm) + expf(p - nm);
            mx = nm;
        }
        float lpz = mx + logf(s) - 0.5f*sq + 64.f*LOG_NORM_F;
        if (lane == 0) loc += (double)(g_logqz[(size_t)b*NPB + n] - lpz);
    }
    __shared__ double dacc[8];
    if (lane == 0) dacc[w] = loc;
    __syncthreads();
    if (tid == 0) {
        double t = 0;
        for (int i = 0; i < 8; i++) t += dacc[i];
        atomicAdd(&g_kl, t);
    }
}

__global__ void zero_accum_kernel() { g_rec = 0.0; g_kl = 0.0; }

__global__ void finalize_kernel(float* __restrict__ out)
{
    out[0] = (float)(g_rec / 40960.0);
    out[1] = (float)(g_kl / 40960.0);
}

// ---------------- host ----------------
static void* symaddr(const void* s)
{
    void* p = nullptr;
    cudaGetSymbolAddress(&p, s);
    return p;
}

#define GEMM_SMEM 98304

extern "C" void kernel_launch(void* const* d_in, const int* in_sizes, int n_in,
                              void* d_out, int out_size)
{
    const float *H, *eps, *wq, *bq, *wk, *bk, *wv, *bv, *wo, *bo, *wz, *bz;
    const float *w1, *b1, *w2, *b2, *w3, *b3;
    const int* init_idx;

    if (n_in >= 3 && in_sizes[2] == 320) {
        H = (const float*)d_in[0];  eps = (const float*)d_in[1]; init_idx = (const int*)d_in[2];
        wq = (const float*)d_in[3]; bq = (const float*)d_in[4];
        wk = (const float*)d_in[5]; bk = (const float*)d_in[6];
        wv = (const float*)d_in[7]; bv = (const float*)d_in[8];
        wo = (const float*)d_in[9]; bo = (const float*)d_in[10];
        wz = (const float*)d_in[11]; bz = (const float*)d_in[12];
        w1 = (const float*)d_in[13]; b1 = (const float*)d_in[14];
        w2 = (const float*)d_in[15]; b2 = (const float*)d_in[16];
        w3 = (const float*)d_in[17]; b3 = (const float*)d_in[18];
    } else {
        H = (const float*)d_in[0];  eps = (const float*)d_in[1];
        wq = (const float*)d_in[2]; bq = (const float*)d_in[3];
        wk = (const float*)d_in[4]; bk = (const float*)d_in[5];
        wv = (const float*)d_in[6]; bv = (const float*)d_in[7];
        wo = (const float*)d_in[8]; bo = (const float*)d_in[9];
        wz = (const float*)d_in[10]; bz = (const float*)d_in[11];
        w1 = (const float*)d_in[12]; b1 = (const float*)d_in[13];
        w2 = (const float*)d_in[14]; b2 = (const float*)d_in[15];
        w3 = (const float*)d_in[16]; b3 = (const float*)d_in[17];
        init_idx = (const int*)d_in[18];
    }

    cudaFuncSetAttribute(gemm_mma_kernel,
                         cudaFuncAttributeMaxDynamicSharedMemorySize, GEMM_SMEM);

    float* Hr  = (float*)symaddr(g_Hr);
    float* qp  = (float*)symaddr(g_q);
    float* qrp = (float*)symaddr(g_qr);
    float* kp  = (float*)symaddr(g_k);
    float* vp  = (float*)symaddr(g_v);
    float* op  = (float*)symaddr(g_o);
    float* orp = (float*)symaddr(g_or);
    float* hA  = (float*)symaddr(g_hA);
    float* hAr = (float*)symaddr(g_hAr);
    float* hB  = (float*)symaddr(g_hB);
    float* hBr = (float*)symaddr(g_hBr);
    float* attp= (float*)symaddr(g_att);
    float* st  = (float*)symaddr(g_stats);
    float* zrp = (float*)symaddr(g_zr);
    float* wt  = (float*)symaddr(g_wt);
    float* d1p = (float*)symaddr(g_d1);
    float* d2p = (float*)symaddr(g_d2);
    float* vtp = (float*)symaddr(g_vt);

    zero_accum_kernel<<<1, 1>>>();
    round_h_kernel<<<2048, 256>>>(H);

    const float scl = 0.044194173824159216f; // 1/sqrt(512)
    const float* xinr = Hr;                  // rounded A input
    float* layer_out[2]  = { hA, hB };
    float* layer_outr[2] = { hAr, hBr };
    for (int i = 0; i < 2; i++) {
        const size_t woff = (size_t)i * DD * DD;
        const size_t boff = (size_t)i * DD;

        // q: raw (residual) + rounded (scores A)
        transpose_w_kernel<<<dim3(16,16), dim3(32,8)>>>(wq + woff, wt, 512, 512);
        gemm_mma_kernel<<<dim3(4,32,1), 256, GEMM_SMEM>>>(xinr,512,0,0, wt,512,0,0, qp,512,0,0, qrp,
                                              512, bq+boff, nullptr,0, 1.f,0,0,0,nullptr);
        // k: rounded only
        transpose_w_kernel<<<dim3(16,16), dim3(32,8)>>>(wk + woff, wt, 512, 512);
        gemm_mma_kernel<<<dim3(4,32,1), 256, GEMM_SMEM>>>(xinr,512,0,0, wt,512,0,0, kp,512,0,0, nullptr,
                                              512, bk+boff, nullptr,0, 1.f,0,1,0,nullptr);
        // v: rounded only
        transpose_w_kernel<<<dim3(16,16), dim3(32,8)>>>(wv + woff, wt, 512, 512);
        gemm_mma_kernel<<<dim3(4,32,1), 256, GEMM_SMEM>>>(xinr,512,0,0, wt,512,0,0, vp,512,0,0, nullptr,
                                              512, bv+boff, nullptr,0, 1.f,0,1,0,nullptr);

        // scores = qr k^T / sqrt(D)   (batched over 64 bh)
        gemm_mma_kernel<<<dim3(2,2,64), 256, GEMM_SMEM>>>(qrp,512,131072,128, kp,512,131072,128,
                                              attp,256,262144,65536, nullptr, 128,
                                              nullptr, nullptr,0, scl,0,0,0,nullptr);
        softmax_kernel<<<64*SSQ, 256>>>();

        // o = q + att @ v : raw + rounded
        transpose_v_kernel<<<dim3(8,4,64), dim3(32,8)>>>();
        gemm_mma_kernel<<<dim3(1,2,64), 256, GEMM_SMEM>>>(attp,256,262144,65536, vtp,256,131072,32768,
                                              op,512,131072,128, orp, 256,
                                              nullptr, qp,512, 1.f,0,0,0,nullptr);

        // out = o + relu(or @ wo + bo) : raw (stats) + rounded (next layer A)
        transpose_w_kernel<<<dim3(16,16), dim3(32,8)>>>(wo + woff, wt, 512, 512);
        gemm_mma_kernel<<<dim3(4,32,1), 256, GEMM_SMEM>>>(orp,512,0,0, wt,512,0,0, layer_out[i],512,0,0,
                                              layer_outr[i], 512, bo+boff, op,512, 1.f,1,0,0,nullptr);
        xinr = layer_outr[i];
    }

    // stats (precision-sensitive): fp32 SIMT on raw hB
    gemm_kernel<<<dim3(1, 32), 256>>>(hB, wz, st, NTOK, 128, DD, bz);

    z_kernel<<<NTOK, 64>>>(eps);
    init_mu_kernel<<<dim3(BB, KCL), 64>>>(init_idx);

    for (int it = 0; it < 5; it++) {
        zero_em_kernel<<<82, 256>>>();
        em_post_kernel<<<dim3(40, BB), 256>>>();
        em_acc_kernel<<<dim3(8, BB), 256>>>();
        em_fin_kernel<<<dim3(KCL, BB), 64>>>();
    }

    // decoder (all A/B operands pre-rounded)
    transpose_w_kernel<<<dim3(32,2), dim3(32,8)>>>(w1, wt, 64, 1024);
    gemm_mma_kernel<<<dim3(8,320,1), 256, GEMM_SMEM>>>(zrp,64,0,0, wt,64,0,0, d1p,1024,0,0, nullptr,
                                           64, b1, nullptr,0, 1.f,1,1,0,nullptr);
    transpose_w_kernel<<<dim3(32,32), dim3(32,8)>>>(w2, wt, 1024, 1024);
    gemm_mma_kernel<<<dim3(8,320,1), 256, GEMM_SMEM>>>(d1p,1024,0,0, wt,1024,0,0, d2p,1024,0,0, nullptr,
                                           1024, b2, nullptr,0, 1.f,1,1,0,nullptr);
    transpose_w_kernel<<<dim3(16,32), dim3(32,8)>>>(w3, wt, 1024, 512);
    gemm_mma_kernel<<<dim3(4,320,1), 256, GEMM_SMEM>>>(d2p,1024,0,0, wt,1024,0,0, nullptr,512,0,0, nullptr,
                                           1024, b3, nullptr,0, 1.f,0,0,1,H);

    kl_kernel<<<dim3(40, BB), 256>>>();
    finalize_kernel<<<1, 1>>>((float*)d_out);
    (void)in_sizes; (void)n_in; (void)out_size;
}

// round 8
// speedup vs baseline: 2.2218x; 1.0432x over previous
#include <cuda_runtime.h>
#include <math.h>
#include <stdint.h>

#define BB   16
#define SSQ  256
#define DD   512
#define KCL  20
#define NTOK 4096
#define NZ   40960
#define NPB  2560
#define LOG_NORM_F (-0.91893853320467274178f)

__device__ float g_Hr[NTOK*DD];
__device__ float g_qkv[NTOK*1536];
__device__ float g_qkvr[NTOK*1536];
__device__ float g_vt[64*128*256];
__device__ float g_o[NTOK*DD];
__device__ float g_or[NTOK*DD];
__device__ float g_hA[NTOK*DD];
__device__ float g_hAr[NTOK*DD];
__device__ float g_hB[NTOK*DD];
__device__ float g_hBr[NTOK*DD];
__device__ float g_att[64*SSQ*SSQ];
__device__ float g_stats[NTOK*128];
__device__ float g_z[NZ*64];
__device__ float g_zr[NZ*64];
__device__ float g_logqz[NZ];
__device__ float g_mu[BB*KCL*64];
__device__ float g_muacc[BB*KCL*64];
__device__ float g_m2[BB*KCL];
__device__ float g_logpi[BB*KCL];
__device__ float g_Nk[BB*KCL];
__device__ float g_post[BB*NPB*KCL];
__device__ float g_wqkv0[1536*512];
__device__ float g_wo0[512*512];
__device__ float g_wqkv1[1536*512];
__device__ float g_wo1[512*512];
__device__ float g_w1t[1024*64];
__device__ float g_w2t[1024*1024];
__device__ float g_w3t[512*1024];
__device__ float g_bqkv[2*1536];
__device__ float g_d1[41943040];
__device__ float g_d2[41943040];
__device__ double g_rec;
__device__ double g_kl;

__device__ __forceinline__ float warpRedSum(float v){
#pragma unroll
    for (int o = 16; o > 0; o >>= 1) v += __shfl_xor_sync(0xffffffffu, v, o);
    return v;
}
__device__ __forceinline__ uint32_t smem_u32(const void* p){
    uint32_t a;
    asm("{ .reg .u64 t; cvta.to.shared.u64 t, %1; cvt.u32.u64 %0, t; }" : "=r"(a) : "l"(p));
    return a;
}
__device__ __forceinline__ float rnaf(float x){
    uint32_t o;
    asm("cvt.rna.tf32.f32 %0, %1;" : "=r"(o) : "f"(x));
    return __uint_as_float(o);
}
__device__ __forceinline__ void ldsm4(uint32_t* r, uint32_t addr){
    asm volatile("ldmatrix.sync.aligned.m8n8.x4.shared.b16 {%0,%1,%2,%3}, [%4];"
        : "=r"(r[0]), "=r"(r[1]), "=r"(r[2]), "=r"(r[3]) : "r"(addr));
}
__device__ __forceinline__ void mma8(float* d, const uint32_t* a, const uint32_t* b){
    asm volatile(
        "mma.sync.aligned.m16n8k8.row.col.f32.tf32.tf32.f32 "
        "{%0,%1,%2,%3}, {%4,%5,%6,%7}, {%8,%9}, {%0,%1,%2,%3};"
        : "+f"(d[0]), "+f"(d[1]), "+f"(d[2]), "+f"(d[3])
        : "r"(a[0]), "r"(a[1]), "r"(a[2]), "r"(a[3]), "r"(b[0]), "r"(b[1]));
}
#define CP16(dst, src) \
    asm volatile("cp.async.cg.shared.global [%0], [%1], 16;" :: "r"(dst), "l"(src))
#define CP_COMMIT() asm volatile("cp.async.commit_group;" ::: "memory")

__global__ __launch_bounds__(256, 2) void gemm_mma_kernel(
    const float* __restrict__ A, int lda, long long sAb, long long sAh,
    const float* __restrict__ B, int ldb, long long sBb, long long sBh,
    float* __restrict__ C, int ldc, long long sCb, long long sCh,
    float* __restrict__ Cr,
    int K,
    const float* __restrict__ bias,
    const float* __restrict__ residual, int ldres, long long sRb, long long sRh,
    float scale, int doRelu, int roundC, int lossMode,
    const float* __restrict__ lossH)
{
    extern __shared__ __align__(16) char smem[];
    const int tid = threadIdx.x;
    const int wid = tid >> 5, lane = tid & 31;

    const int zb = blockIdx.z >> 2, zh = blockIdx.z & 3;
    A += (long long)zb * sAb + (long long)zh * sAh;
    B += (long long)zb * sBb + (long long)zh * sBh;
    if (C)        C        += (long long)zb * sCb + (long long)zh * sCh;
    if (Cr)       Cr       += (long long)zb * sCb + (long long)zh * sCh;
    if (residual) residual += (long long)zb * sRb + (long long)zh * sRh;

    const int m0 = blockIdx.y * 128, n0 = blockIdx.x * 128;
    const int kTiles = K >> 5;
    const uint32_t smem0 = smem_u32(smem);

    const int srow = tid & 127;
    const bool isB = (tid >= 128);
    const float* gsrc = isB ? (B + (size_t)(n0 + srow) * ldb)
                            : (A + (size_t)(m0 + srow) * lda);
    const uint32_t sdst0 = smem0 + (isB ? 16384 : 0) + srow * 128;
    const int rx = srow & 7;

    const int pstages = kTiles < 2 ? kTiles : 2;
    for (int c = 0; c < pstages; c++){
        const float* gs = gsrc + c * 32;
        const uint32_t sd = sdst0 + c * 32768;
#pragma unroll
        for (int j = 0; j < 8; j++)
            CP16(sd + ((j ^ rx) << 4), gs + j * 4);
        CP_COMMIT();
    }

    float acc[2][8][4];
#pragma unroll
    for (int i = 0; i < 2; i++)
#pragma unroll
        for (int j = 0; j < 8; j++)
#pragma unroll
            for (int q = 0; q < 4; q++) acc[i][j][q] = 0.f;

    const int wm = (wid & 3) * 32;
    const int wn = (wid >> 2) * 64;
    const int rr = lane & 7;
    const int qm = lane >> 3;
    const int qlow = qm & 1, qhigh = qm >> 1;
    uint32_t rowbaseA[2];
#pragma unroll
    for (int mt = 0; mt < 2; mt++)
        rowbaseA[mt] = (uint32_t)((wm + mt*16 + rr + 8*qlow) * 128);
    uint32_t rowbaseB[4];
#pragma unroll
    for (int p = 0; p < 4; p++)
        rowbaseB[p] = (uint32_t)(16384 + (wn + (2*p + qhigh)*8 + rr) * 128);

    for (int c = 0; c < kTiles; c++){
        if (c + 1 < kTiles) asm volatile("cp.async.wait_group 1;" ::: "memory");
        else                asm volatile("cp.async.wait_group 0;" ::: "memory");
        __syncthreads();

        if (c + 2 < kTiles){
            const float* gs = gsrc + (c + 2) * 32;
            const uint32_t sd = sdst0 + ((c + 2) % 3) * 32768;
#pragma unroll
            for (int j = 0; j < 8; j++)
                CP16(sd + ((j ^ rx) << 4), gs + j * 4);
            CP_COMMIT();
        }

        const uint32_t st = smem0 + (c % 3) * 32768;
#pragma unroll
        for (int t = 0; t < 4; t++){
            const uint32_t offA = (uint32_t)(((2*t + qhigh) ^ rr) << 4);
            const uint32_t offB = (uint32_t)(((2*t + qlow) ^ rr) << 4);
            uint32_t a[2][4], bb[4][4];
            ldsm4(a[0], st + rowbaseA[0] + offA);
            ldsm4(a[1], st + rowbaseA[1] + offA);
#pragma unroll
            for (int p = 0; p < 4; p++)
                ldsm4(bb[p], st + rowbaseB[p] + offB);
#pragma unroll
            for (int p = 0; p < 4; p++){
                mma8(acc[0][2*p+0], a[0], &bb[p][0]);
                mma8(acc[1][2*p+0], a[1], &bb[p][0]);
                mma8(acc[0][2*p+1], a[0], &bb[p][2]);
                mma8(acc[1][2*p+1], a[1], &bb[p][2]);
            }
        }
    }

    if (!lossMode){
#pragma unroll
        for (int mt = 0; mt < 2; mt++){
#pragma unroll
            for (int half = 0; half < 2; half++){
                int r = m0 + wm + mt*16 + (lane >> 2) + half*8;
                float* crow = C + (size_t)r * ldc;
                float* crow2 = Cr ? (Cr + (size_t)r * ldc) : nullptr;
                const float* rrow = residual ? (residual + (size_t)r * ldres) : nullptr;
#pragma unroll
                for (int nt = 0; nt < 8; nt++){
                    int col = n0 + wn + nt*8 + (lane & 3)*2;
                    float f0 = acc[mt][nt][half*2 + 0] * scale;
                    float f1 = acc[mt][nt][half*2 + 1] * scale;
                    if (bias){ f0 += bias[col]; f1 += bias[col + 1]; }
                    if (doRelu){ f0 = fmaxf(f0, 0.f); f1 = fmaxf(f1, 0.f); }
                    if (rrow){
                        float2 rv = *(const float2*)(rrow + col);
                        f0 += rv.x; f1 += rv.y;
                    }
                    if (roundC){ f0 = rnaf(f0); f1 = rnaf(f1); }
                    *(float2*)(crow + col) = make_float2(f0, f1);
                    if (crow2)
                        *(float2*)(crow2 + col) = make_float2(rnaf(f0), rnaf(f1));
                }
            }
        }
    } else {
        double lsum = 0.0;
#pragma unroll
        for (int mt = 0; mt < 2; mt++){
#pragma unroll
            for (int half = 0; half < 2; half++){
                int r = m0 + wm + mt*16 + (lane >> 2) + half*8;
                const float* hrow = lossH + (size_t)(r / 10) * 512;
#pragma unroll
                for (int nt = 0; nt < 8; nt++){
                    int col = n0 + wn + nt*8 + (lane & 3)*2;
                    float f0 = fmaxf(acc[mt][nt][half*2 + 0] + bias[col], 0.f);
                    float f1 = fmaxf(acc[mt][nt][half*2 + 1] + bias[col + 1], 0.f);
                    float d0 = f0 - hrow[col];
                    float d1 = f1 - hrow[col + 1];
                    lsum += (double)d0 * d0 + (double)d1 * d1;
                }
            }
        }
#pragma unroll
        for (int o = 16; o > 0; o >>= 1) lsum += __shfl_xor_sync(0xffffffffu, lsum, o);
        __shared__ double ds[8];
        if (lane == 0) ds[wid] = lsum;
        __syncthreads();
        if (tid == 0){
            double t = 0;
            for (int i = 0; i < 8; i++) t += ds[i];
            atomicAdd(&g_rec, t);
        }
    }
}

__global__ void transpose_w_kernel(const float* __restrict__ W,
                                   float* __restrict__ out, int K, int N)
{
    __shared__ float t[32][33];
    const int k0 = blockIdx.y * 32, n0 = blockIdx.x * 32;
    for (int i = threadIdx.y; i < 32; i += 8)
        t[i][threadIdx.x] = W[(size_t)(k0 + i) * N + n0 + threadIdx.x];
    __syncthreads();
    for (int i = threadIdx.y; i < 32; i += 8)
        out[(size_t)(n0 + i) * K + k0 + threadIdx.x] = rnaf(t[threadIdx.x][i]);
}

__global__ void transpose_qkv_kernel(const float* __restrict__ Wq,
                                     const float* __restrict__ Wk,
                                     const float* __restrict__ Wv,
                                     float* __restrict__ out)
{
    __shared__ float t[32][33];
    const float* W = blockIdx.z == 0 ? Wq : (blockIdx.z == 1 ? Wk : Wv);
    const int k0 = blockIdx.y * 32, n0 = blockIdx.x * 32;
    for (int i = threadIdx.y; i < 32; i += 8)
        t[i][threadIdx.x] = W[(size_t)(k0 + i) * 512 + n0 + threadIdx.x];
    __syncthreads();
    const int nout = blockIdx.z * 512 + n0;
    for (int i = threadIdx.y; i < 32; i += 8)
        out[(size_t)(nout + i) * 512 + k0 + threadIdx.x] = rnaf(t[threadIdx.x][i]);
}

__global__ void pack_bias_kernel(const float* __restrict__ bq,
                                 const float* __restrict__ bk,
                                 const float* __restrict__ bv)
{
    int i = blockIdx.x * 256 + threadIdx.x;
    if (i < 2*1536){
        int layer = i / 1536, col = i % 1536;
        const float* src = col < 512 ? bq : (col < 1024 ? bk : bv);
        g_bqkv[i] = src[layer*512 + (col & 511)];
    }
}

__global__ void transpose_v_kernel()
{
    __shared__ float t[32][33];
    const int bh = blockIdx.z, b = bh >> 2, h = bh & 3;
    const int k0 = blockIdx.x * 32;
    const int n0 = blockIdx.y * 32;
    for (int i = threadIdx.y; i < 32; i += 8)
        t[i][threadIdx.x] = g_qkvr[((size_t)b * 256 + k0 + i) * 1536 + 1024 + h * 128 + n0 + threadIdx.x];
    __syncthreads();
    for (int i = threadIdx.y; i < 32; i += 8)
        g_vt[((size_t)bh * 128 + n0 + i) * 256 + k0 + threadIdx.x] = t[threadIdx.x][i];
}

__global__ void round_h_kernel(const float* __restrict__ H)
{
    int i = blockIdx.x * 256 + threadIdx.x;
    float4 v = *(const float4*)(H + i * 4);
    *(float4*)(g_Hr + i * 4) = make_float4(rnaf(v.x), rnaf(v.y), rnaf(v.z), rnaf(v.w));
}

__global__ __launch_bounds__(256, 2) void gemm_kernel(
    const float* __restrict__ A, const float* __restrict__ W,
    float* __restrict__ C, int M, int N, int K,
    const float* __restrict__ bias)
{
    __shared__ float As[8][132];
    __shared__ float Bs[8][128];
    const int tid = threadIdx.x;
    const int m0 = blockIdx.y * 128, n0 = blockIdx.x * 128;
    const int arow = tid >> 1;
    const int aq   = (tid & 1) << 2;
    const int brow = tid >> 5;
    const int bcol = (tid & 31) << 2;
    const float* Ap = A + (size_t)(m0 + arow) * K + aq;
    const float* Wp = W + (size_t)brow * N + n0 + bcol;
    const int tx = tid & 15, ty = tid >> 4;

    float acc[8][8];
#pragma unroll
    for (int i = 0; i < 8; i++)
#pragma unroll
        for (int j = 0; j < 8; j++) acc[i][j] = 0.f;

    for (int k0 = 0; k0 < K; k0 += 8) {
        float4 av = *(const float4*)(Ap + k0);
        float4 bv = *(const float4*)(Wp + (size_t)k0 * N);
        As[aq+0][arow] = av.x; As[aq+1][arow] = av.y;
        As[aq+2][arow] = av.z; As[aq+3][arow] = av.w;
        *(float4*)&Bs[brow][bcol] = bv;
        __syncthreads();
#pragma unroll
        for (int kk = 0; kk < 8; kk++) {
            float fa[8], fb[8];
            *(float4*)&fa[0] = *(const float4*)&As[kk][ty*8];
            *(float4*)&fa[4] = *(const float4*)&As[kk][ty*8+4];
            *(float4*)&fb[0] = *(const float4*)&Bs[kk][tx*8];
            *(float4*)&fb[4] = *(const float4*)&Bs[kk][tx*8+4];
#pragma unroll
            for (int i = 0; i < 8; i++)
#pragma unroll
                for (int j = 0; j < 8; j++)
                    acc[i][j] = fmaf(fa[i], fb[j], acc[i][j]);
        }
        __syncthreads();
    }

    float bl[8];
#pragma unroll
    for (int j = 0; j < 8; j++) bl[j] = bias ? bias[n0 + tx*8 + j] : 0.f;
#pragma unroll
    for (int i = 0; i < 8; i++) {
        int m = m0 + ty*8 + i;
        float* cp = C + (size_t)m * N + n0 + tx*8;
        *(float4*)cp     = make_float4(acc[i][0]+bl[0], acc[i][1]+bl[1], acc[i][2]+bl[2], acc[i][3]+bl[3]);
        *(float4*)(cp+4) = make_float4(acc[i][4]+bl[4], acc[i][5]+bl[5], acc[i][6]+bl[6], acc[i][7]+bl[7]);
    }
}

__global__ void softmax_kernel()
{
    const int row = blockIdx.x;
    float* p = g_att + (size_t)row * SSQ;
    const int tid = threadIdx.x, lane = tid & 31, w = tid >> 5;
    __shared__ float sm[8];
    float v = p[tid];
    float m = v;
#pragma unroll
    for (int o = 16; o > 0; o >>= 1) m = fmaxf(m, __shfl_xor_sync(0xffffffffu, m, o));
    if (lane == 0) sm[w] = m;
    __syncthreads();
    float bm = sm[0];
#pragma unroll
    for (int i = 1; i < 8; i++) bm = fmaxf(bm, sm[i]);
    float e = expf(v - bm);
    float s = warpRedSum(e);
    __syncthreads();
    if (lane == 0) sm[w] = s;
    __syncthreads();
    float bs = 0.f;
#pragma unroll
    for (int i = 0; i < 8; i++) bs += sm[i];
    p[tid] = rnaf(e / bs);
}

__global__ __launch_bounds__(256) void z_kernel(const float* __restrict__ eps)
{
    const int lane = threadIdx.x & 31;
    const int bs = blockIdx.x * 8 + (threadIdx.x >> 5);
    const float mean0 = g_stats[(size_t)bs*128 + lane];
    const float mean1 = g_stats[(size_t)bs*128 + 32 + lane];
    const float lv0   = g_stats[(size_t)bs*128 + 64 + lane];
    const float lv1   = g_stats[(size_t)bs*128 + 96 + lane];
    const float sd0 = expf(0.5f * lv0), sd1 = expf(0.5f * lv1);
    const float lvs = lv0 + lv1;
    for (int m = 0; m < 10; m++) {
        size_t off = ((size_t)bs*10 + m)*64;
        float e0 = eps[off + lane], e1 = eps[off + 32 + lane];
        float z0 = mean0 + e0 * sd0, z1 = mean1 + e1 * sd1;
        g_z[off + lane] = z0;        g_z[off + 32 + lane] = z1;
        g_zr[off + lane] = rnaf(z0); g_zr[off + 32 + lane] = rnaf(z1);
        float qv = warpRedSum(lvs + e0*e0 + e1*e1);
        if (lane == 0) g_logqz[(size_t)bs*10 + m] = -0.5f*qv + 64.f*LOG_NORM_F;
    }
}

__global__ void init_mu_kernel(const int* __restrict__ idx)
{
    const int b = blockIdx.x, k = blockIdx.y, l = threadIdx.x;
    const int lane = l & 31, w = l >> 5;
    const int n = idx[b*KCL + k];
    float v = g_z[((size_t)b*NPB + n)*64 + l];
    g_mu[((size_t)b*KCL + k)*64 + l] = v;
    float s = warpRedSum(v*v);
    __shared__ float sm[2];
    if (lane == 0) sm[w] = s;
    __syncthreads();
    if (l == 0) {
        g_m2[b*KCL + k] = sm[0] + sm[1];
        g_logpi[b*KCL + k] = -2.9957322735539909f;
    }
}

__global__ void zero_em_kernel()
{
    int i = blockIdx.x * 256 + threadIdx.x;
    if (i < BB*KCL) g_Nk[i] = 0.f;
    if (i < BB*KCL*64) g_muacc[i] = 0.f;
}

__global__ __launch_bounds__(256) void em_post_kernel()
{
    const int b = blockIdx.y;
    const int tid = threadIdx.x, lane = tid & 31, w = tid >> 5;
    __shared__ float mus[KCL*64];
    __shared__ float sc[KCL];
    __shared__ float nkacc[KCL];
    for (int i = tid; i < KCL*64; i += 256) mus[i] = g_mu[(size_t)b*KCL*64 + i];
    if (tid < KCL) { sc[tid] = -0.5f*g_m2[b*KCL+tid] + g_logpi[b*KCL+tid]; nkacc[tid] = 0.f; }
    __syncthreads();

    float nkloc = 0.f;
    const int nbase = blockIdx.x*64 + w*8;
    for (int t = 0; t < 8; t++) {
        int n = nbase + t;
        const float* zp = g_z + ((size_t)b*NPB + n)*64;
        float z0 = zp[lane], z1 = zp[lane+32];
        float mx = -1e30f, s = 0.f, myll = 0.f;
#pragma unroll
        for (int k2 = 0; k2 < KCL; k2++) {
            float p = z0*mus[k2*64+lane] + z1*mus[k2*64+32+lane];
            p = warpRedSum(p) + sc[k2];
            if (lane == k2) myll = p;
            float nm = fmaxf(mx, p);
            s = s*expf(mx - nm) + expf(p - nm);
            mx = nm;
        }
        if (lane < KCL) {
            float pk = expf(myll - mx) / s;
            g_post[((size_t)b*NPB + n)*KCL + lane] = pk;
            nkloc += pk;
        }
    }
    if (lane < KCL) atomicAdd(&nkacc[lane], nkloc);
    __syncthreads();
    if (tid < KCL) atomicAdd(&g_Nk[b*KCL + tid], nkacc[tid]);
}

__global__ __launch_bounds__(256) void em_acc_kernel()
{
    const int b = blockIdx.y, s = blockIdx.x;
    const int tid = threadIdx.x;
    const int l = tid & 63, kq = tid >> 6;
    __shared__ float zt[16][64];
    __shared__ float pt[16][20];
    float acc[5] = {0.f, 0.f, 0.f, 0.f, 0.f};
    const int n0 = s * 320;
    for (int g = 0; g < 20; g++){
        const int nb = n0 + g * 16;
        const float* zsrc = g_z + ((size_t)b*NPB + nb)*64;
        for (int i = tid; i < 1024; i += 256) ((float*)zt)[i] = zsrc[i];
        const float* psrc = g_post + ((size_t)b*NPB + nb)*KCL;
        for (int i = tid; i < 320; i += 256) ((float*)pt)[i] = psrc[i];
        __syncthreads();
#pragma unroll
        for (int nn = 0; nn < 16; nn++){
            float zv = zt[nn][l];
#pragma unroll
            for (int j = 0; j < 5; j++)
                acc[j] = fmaf(pt[nn][kq*5 + j], zv, acc[j]);
        }
        __syncthreads();
    }
#pragma unroll
    for (int j = 0; j < 5; j++)
        atomicAdd(&g_muacc[((size_t)b*KCL + kq*5 + j)*64 + l], acc[j]);
}

__global__ void em_fin_kernel()
{
    const int k = blockIdx.x, b = blockIdx.y, l = threadIdx.x;
    const int lane = l & 31, w = l >> 5;
    float nk = g_Nk[b*KCL + k];
    float m = g_muacc[((size_t)b*KCL + k)*64 + l] / nk;
    g_mu[((size_t)b*KCL + k)*64 + l] = m;
    float s = warpRedSum(m*m);
    __shared__ float sm[2];
    if (lane == 0) sm[w] = s;
    __syncthreads();
    if (l == 0) {
        g_m2[b*KCL + k] = sm[0] + sm[1];
        float tot = 0.f;
        for (int j = 0; j < KCL; j++) tot += g_Nk[b*KCL + j];
        g_logpi[b*KCL + k] = logf(nk / tot);
    }
}

__global__ __launch_bounds__(256) void kl_kernel()
{
    const int b = blockIdx.y;
    const int tid = threadIdx.x, lane = tid & 31, w = tid >> 5;
    __shared__ float mus[KCL*64];
    __shared__ float sc[KCL];
    for (int i = tid; i < KCL*64; i += 256) mus[i] = g_mu[(size_t)b*KCL*64 + i];
    if (tid < KCL) sc[tid] = -0.5f*g_m2[b*KCL+tid] + g_logpi[b*KCL+tid];
    __syncthreads();

    double loc = 0.0;
    const int nbase = blockIdx.x*64 + w*8;
    for (int t = 0; t < 8; t++) {
        int n = nbase + t;
        const float* zp = g_z + ((size_t)b*NPB + n)*64;
        float z0 = zp[lane], z1 = zp[lane+32];
        float sq = warpRedSum(z0*z0 + z1*z1);
        float mx = -1e30f, s = 0.f;
#pragma unroll
        for (int k2 = 0; k2 < KCL; k2++) {
            float p = z0*mus[k2*64+lane] + z1*mus[k2*64+32+lane];
            p = warpRedSum(p) + sc[k2];
            float nm = fmaxf(mx, p);
            s = s*expf(mx - nm) + expf(p - nm);
            mx = nm;
        }
        float lpz = mx + logf(s) - 0.5f*sq + 64.f*LOG_NORM_F;
        if (lane == 0) loc += (double)(g_logqz[(size_t)b*NPB + n] - lpz);
    }
    __shared__ double dacc[8];
    if (lane == 0) dacc[w] = loc;
    __syncthreads();
    if (tid == 0) {
        double t = 0;
        for (int i = 0; i < 8; i++) t += dacc[i];
        atomicAdd(&g_kl, t);
    }
}

__global__ void zero_accum_kernel() { g_rec = 0.0; g_kl = 0.0; }

__global__ void finalize_kernel(float* __restrict__ out)
{
    out[0] = (float)(g_rec / 40960.0);
    out[1] = (float)(g_kl / 40960.0);
}

static void* symaddr(const void* s)
{
    void* p = nullptr;
    cudaGetSymbolAddress(&p, s);
    return p;
}

#define GEMM_SMEM 98304

extern "C" void kernel_launch(void* const* d_in, const int* in_sizes, int n_in,
                              void* d_out, int out_size)
{
    const float *H, *eps, *wq, *bq, *wk, *bk, *wv, *bv, *wo, *bo, *wz, *bz;
    const float *w1, *b1, *w2, *b2, *w3, *b3;
    const int* init_idx;

    if (n_in >= 3 && in_sizes[2] == 320) {
        H = (const float*)d_in[0];  eps = (const float*)d_in[1]; init_idx = (const int*)d_in[2];
        wq = (const float*)d_in[3]; bq = (const float*)d_in[4];
        wk = (const float*)d_in[5]; bk = (const float*)d_in[6];
        wv = (const float*)d_in[7]; bv = (const float*)d_in[8];
        wo = (const float*)d_in[9]; bo = (const float*)d_in[10];
        wz = (const float*)d_in[11]; bz = (const float*)d_in[12];
        w1 = (const float*)d_in[13]; b1 = (const float*)d_in[14];
        w2 = (const float*)d_in[15]; b2 = (const float*)d_in[16];
        w3 = (const float*)d_in[17]; b3 = (const float*)d_in[18];
    } else {
        H = (const float*)d_in[0];  eps = (const float*)d_in[1];
        wq = (const float*)d_in[2]; bq = (const float*)d_in[3];
        wk = (const float*)d_in[4]; bk = (const float*)d_in[5];
        wv = (const float*)d_in[6]; bv = (const float*)d_in[7];
        wo = (const float*)d_in[8]; bo = (const float*)d_in[9];
        wz = (const float*)d_in[10]; bz = (const float*)d_in[11];
        w1 = (const float*)d_in[12]; b1 = (const float*)d_in[13];
        w2 = (const float*)d_in[14]; b2 = (const float*)d_in[15];
        w3 = (const float*)d_in[16]; b3 = (const float*)d_in[17];
        init_idx = (const int*)d_in[18];
    }

    cudaFuncSetAttribute(gemm_mma_kernel,
                         cudaFuncAttributeMaxDynamicSharedMemorySize, GEMM_SMEM);

    float* Hr    = (float*)symaddr(g_Hr);
    float* qkv   = (float*)symaddr(g_qkv);
    float* qkvr  = (float*)symaddr(g_qkvr);
    float* op    = (float*)symaddr(g_o);
    float* orp   = (float*)symaddr(g_or);
    float* hA    = (float*)symaddr(g_hA);
    float* hAr   = (float*)symaddr(g_hAr);
    float* hB    = (float*)symaddr(g_hB);
    float* hBr   = (float*)symaddr(g_hBr);
    float* attp  = (float*)symaddr(g_att);
    float* st    = (float*)symaddr(g_stats);
    float* zrp   = (float*)symaddr(g_zr);
    float* vtp   = (float*)symaddr(g_vt);
    float* wqkv0 = (float*)symaddr(g_wqkv0);
    float* wo0t  = (float*)symaddr(g_wo0);
    float* wqkv1 = (float*)symaddr(g_wqkv1);
    float* wo1t  = (float*)symaddr(g_wo1);
    float* w1t   = (float*)symaddr(g_w1t);
    float* w2t   = (float*)symaddr(g_w2t);
    float* w3t   = (float*)symaddr(g_w3t);
    float* bqkv  = (float*)symaddr(g_bqkv);
    float* d1p   = (float*)symaddr(g_d1);
    float* d2p   = (float*)symaddr(g_d2);

    zero_accum_kernel<<<1, 1>>>();
    round_h_kernel<<<2048, 256>>>(H);
    pack_bias_kernel<<<12, 256>>>(bq, bk, bv);
    transpose_qkv_kernel<<<dim3(16,16,3), dim3(32,8)>>>(wq, wk, wv, wqkv0);
    transpose_w_kernel<<<dim3(16,16), dim3(32,8)>>>(wo, wo0t, 512, 512);

    const float scl = 0.044194173824159216f;
    const float* wqkvT[2] = { wqkv0, wqkv1 };
    const float* woT[2]   = { wo0t, wo1t };
    const float* xinr = Hr;
    float* layer_out[2]  = { hA, hB };
    float* layer_outr[2] = { hAr, hBr };

    for (int i = 0; i < 2; i++) {
        const size_t boff = (size_t)i * DD;

        // fused qkv
        gemm_mma_kernel<<<dim3(12,32,1), 256, GEMM_SMEM>>>(
            xinr,512,0,0, wqkvT[i],512,0,0, qkv,1536,0,0, qkvr, 512,
            bqkv + (size_t)i*1536, nullptr,0,0,0, 1.f,0,0,0,nullptr);

        if (i == 0) {
            transpose_qkv_kernel<<<dim3(16,16,3), dim3(32,8)>>>(wq + DD*DD, wk + DD*DD, wv + DD*DD, wqkv1);
            transpose_w_kernel<<<dim3(16,16), dim3(32,8)>>>(wo + DD*DD, wo1t, 512, 512);
            transpose_w_kernel<<<dim3(32,2), dim3(32,8)>>>(w1, w1t, 64, 1024);
            transpose_w_kernel<<<dim3(32,32), dim3(32,8)>>>(w2, w2t, 1024, 1024);
            transpose_w_kernel<<<dim3(16,32), dim3(32,8)>>>(w3, w3t, 1024, 512);
        }

        // scores = qr k^T / sqrt(D)   *** K = 128 (head dim) — the R7 bug was 512 here ***
        gemm_mma_kernel<<<dim3(2,2,64), 256, GEMM_SMEM>>>(
            qkvr,1536,393216,128, qkvr+512,1536,393216,128,
            attp,256,262144,65536, nullptr, 128,
            nullptr, nullptr,0,0,0, scl,0,0,0,nullptr);
        softmax_kernel<<<64*SSQ, 256>>>();

        transpose_v_kernel<<<dim3(8,4,64), dim3(32,8)>>>();
        gemm_mma_kernel<<<dim3(1,2,64), 256, GEMM_SMEM>>>(
            attp,256,262144,65536, vtp,256,131072,32768,
            op,512,131072,128, orp, 256,
            nullptr, qkv,1536,393216,128, 1.f,0,0,0,nullptr);

        gemm_mma_kernel<<<dim3(4,32,1), 256, GEMM_SMEM>>>(
            orp,512,0,0, woT[i],512,0,0, layer_out[i],512,0,0,
            layer_outr[i], 512, bo+boff, op,512,0,0, 1.f,1,0,0,nullptr);
        xinr = layer_outr[i];
    }

    gemm_kernel<<<dim3(1, 32), 256>>>(hB, wz, st, NTOK, 128, DD, bz);

    z_kernel<<<512, 256>>>(eps);
    init_mu_kernel<<<dim3(BB, KCL), 64>>>(init_idx);

    for (int it = 0; it < 5; it++) {
        zero_em_kernel<<<82, 256>>>();
        em_post_kernel<<<dim3(40, BB), 256>>>();
        em_acc_kernel<<<dim3(8, BB), 256>>>();
        em_fin_kernel<<<dim3(KCL, BB), 64>>>();
    }

    gemm_mma_kernel<<<dim3(8,320,1), 256, GEMM_SMEM>>>(
        zrp,64,0,0, w1t,64,0,0, d1p,1024,0,0, nullptr,
        64, b1, nullptr,0,0,0, 1.f,1,1,0,nullptr);
    gemm_mma_kernel<<<dim3(8,320,1), 256, GEMM_SMEM>>>(
        d1p,1024,0,0, w2t,1024,0,0, d2p,1024,0,0, nullptr,
        1024, b2, nullptr,0,0,0, 1.f,1,1,0,nullptr);
    gemm_mma_kernel<<<dim3(4,320,1), 256, GEMM_SMEM>>>(
        d2p,1024,0,0, w3t,1024,0,0, nullptr,512,0,0, nullptr,
        1024, b3, nullptr,0,0,0, 1.f,0,0,1,H);

    kl_kernel<<<dim3(40, BB), 256>>>();
    finalize_kernel<<<1, 1>>>((float*)d_out);
    (void)in_sizes; (void)n_in; (void)out_size;
}

// round 9
// speedup vs baseline: 2.3929x; 1.0770x over previous
#include <cuda_runtime.h>
#include <math.h>
#include <stdint.h>

#define BB   16
#define SSQ  256
#define DD   512
#define KCL  20
#define NTOK 4096
#define NZ   40960
#define NPB  2560
#define LOG_NORM_F (-0.91893853320467274178f)

__device__ float g_Hr[NTOK*DD];
__device__ float g_qkv[NTOK*1536];
__device__ float g_qkvr[NTOK*1536];
__device__ float g_vt[64*128*256];
__device__ float g_o[NTOK*DD];
__device__ float g_or[NTOK*DD];
__device__ float g_hA[NTOK*DD];
__device__ float g_hAr[NTOK*DD];
__device__ float g_hB[NTOK*DD];
__device__ float g_hBr[NTOK*DD];
__device__ float g_att[64*SSQ*SSQ];
__device__ float g_stats[NTOK*128];
__device__ float g_z[NZ*64];
__device__ float g_zr[NZ*64];
__device__ float g_logqz[NZ];
__device__ float g_mu[BB*KCL*64];
__device__ float g_muacc[2*BB*KCL*64];   // parity double-buffered
__device__ float g_m2[BB*KCL];
__device__ float g_logpi[BB*KCL];
__device__ float g_Nk[2*BB*KCL];         // parity double-buffered
__device__ float g_wqkv0[1536*512];
__device__ float g_wo0[512*512];
__device__ float g_wqkv1[1536*512];
__device__ float g_wo1[512*512];
__device__ float g_w1t[1024*64];
__device__ float g_w2t[1024*1024];
__device__ float g_w3t[512*1024];
__device__ float g_bqkv[2*1536];
__device__ float g_d1[41943040];
__device__ float g_d2[41943040];
__device__ double g_rec;
__device__ double g_kl;

__device__ __forceinline__ float warpRedSum(float v){
#pragma unroll
    for (int o = 16; o > 0; o >>= 1) v += __shfl_xor_sync(0xffffffffu, v, o);
    return v;
}
__device__ __forceinline__ float warpRedMax(float v){
#pragma unroll
    for (int o = 16; o > 0; o >>= 1) v = fmaxf(v, __shfl_xor_sync(0xffffffffu, v, o));
    return v;
}
__device__ __forceinline__ uint32_t smem_u32(const void* p){
    uint32_t a;
    asm("{ .reg .u64 t; cvta.to.shared.u64 t, %1; cvt.u32.u64 %0, t; }" : "=r"(a) : "l"(p));
    return a;
}
__device__ __forceinline__ float rnaf(float x){
    uint32_t o;
    asm("cvt.rna.tf32.f32 %0, %1;" : "=r"(o) : "f"(x));
    return __uint_as_float(o);
}
__device__ __forceinline__ void ldsm4(uint32_t* r, uint32_t addr){
    asm volatile("ldmatrix.sync.aligned.m8n8.x4.shared.b16 {%0,%1,%2,%3}, [%4];"
        : "=r"(r[0]), "=r"(r[1]), "=r"(r[2]), "=r"(r[3]) : "r"(addr));
}
__device__ __forceinline__ void mma8(float* d, const uint32_t* a, const uint32_t* b){
    asm volatile(
        "mma.sync.aligned.m16n8k8.row.col.f32.tf32.tf32.f32 "
        "{%0,%1,%2,%3}, {%4,%5,%6,%7}, {%8,%9}, {%0,%1,%2,%3};"
        : "+f"(d[0]), "+f"(d[1]), "+f"(d[2]), "+f"(d[3])
        : "r"(a[0]), "r"(a[1]), "r"(a[2]), "r"(a[3]), "r"(b[0]), "r"(b[1]));
}
#define CP16(dst, src) \
    asm volatile("cp.async.cg.shared.global [%0], [%1], 16;" :: "r"(dst), "l"(src))
#define CP_COMMIT() asm volatile("cp.async.commit_group;" ::: "memory")

__global__ __launch_bounds__(256, 2) void gemm_mma_kernel(
    const float* __restrict__ A, int lda, long long sAb, long long sAh,
    const float* __restrict__ B, int ldb, long long sBb, long long sBh,
    float* __restrict__ C, int ldc, long long sCb, long long sCh,
    float* __restrict__ Cr,
    int K,
    const float* __restrict__ bias,
    const float* __restrict__ residual, int ldres, long long sRb, long long sRh,
    float scale, int doRelu, int roundC, int lossMode,
    const float* __restrict__ lossH)
{
    extern __shared__ __align__(16) char smem[];
    const int tid = threadIdx.x;
    const int wid = tid >> 5, lane = tid & 31;

    const int zb = blockIdx.z >> 2, zh = blockIdx.z & 3;
    A += (long long)zb * sAb + (long long)zh * sAh;
    B += (long long)zb * sBb + (long long)zh * sBh;
    if (C)        C        += (long long)zb * sCb + (long long)zh * sCh;
    if (Cr)       Cr       += (long long)zb * sCb + (long long)zh * sCh;
    if (residual) residual += (long long)zb * sRb + (long long)zh * sRh;

    const int m0 = blockIdx.y * 128, n0 = blockIdx.x * 128;
    const int kTiles = K >> 5;
    const uint32_t smem0 = smem_u32(smem);

    const int srow = tid & 127;
    const bool isB = (tid >= 128);
    const float* gsrc = isB ? (B + (size_t)(n0 + srow) * ldb)
                            : (A + (size_t)(m0 + srow) * lda);
    const uint32_t sdst0 = smem0 + (isB ? 16384 : 0) + srow * 128;
    const int rx = srow & 7;

    const int pstages = kTiles < 2 ? kTiles : 2;
    for (int c = 0; c < pstages; c++){
        const float* gs = gsrc + c * 32;
        const uint32_t sd = sdst0 + c * 32768;
#pragma unroll
        for (int j = 0; j < 8; j++)
            CP16(sd + ((j ^ rx) << 4), gs + j * 4);
        CP_COMMIT();
    }

    float acc[2][8][4];
#pragma unroll
    for (int i = 0; i < 2; i++)
#pragma unroll
        for (int j = 0; j < 8; j++)
#pragma unroll
            for (int q = 0; q < 4; q++) acc[i][j][q] = 0.f;

    const int wm = (wid & 3) * 32;
    const int wn = (wid >> 2) * 64;
    const int rr = lane & 7;
    const int qm = lane >> 3;
    const int qlow = qm & 1, qhigh = qm >> 1;
    uint32_t rowbaseA[2];
#pragma unroll
    for (int mt = 0; mt < 2; mt++)
        rowbaseA[mt] = (uint32_t)((wm + mt*16 + rr + 8*qlow) * 128);
    uint32_t rowbaseB[4];
#pragma unroll
    for (int p = 0; p < 4; p++)
        rowbaseB[p] = (uint32_t)(16384 + (wn + (2*p + qhigh)*8 + rr) * 128);

    for (int c = 0; c < kTiles; c++){
        if (c + 1 < kTiles) asm volatile("cp.async.wait_group 1;" ::: "memory");
        else                asm volatile("cp.async.wait_group 0;" ::: "memory");
        __syncthreads();

        if (c + 2 < kTiles){
            const float* gs = gsrc + (c + 2) * 32;
            const uint32_t sd = sdst0 + ((c + 2) % 3) * 32768;
#pragma unroll
            for (int j = 0; j < 8; j++)
                CP16(sd + ((j ^ rx) << 4), gs + j * 4);
            CP_COMMIT();
        }

        const uint32_t st = smem0 + (c % 3) * 32768;
#pragma unroll
        for (int t = 0; t < 4; t++){
            const uint32_t offA = (uint32_t)(((2*t + qhigh) ^ rr) << 4);
            const uint32_t offB = (uint32_t)(((2*t + qlow) ^ rr) << 4);
            uint32_t a[2][4], bb[4][4];
            ldsm4(a[0], st + rowbaseA[0] + offA);
            ldsm4(a[1], st + rowbaseA[1] + offA);
#pragma unroll
            for (int p = 0; p < 4; p++)
                ldsm4(bb[p], st + rowbaseB[p] + offB);
#pragma unroll
            for (int p = 0; p < 4; p++){
                mma8(acc[0][2*p+0], a[0], &bb[p][0]);
                mma8(acc[1][2*p+0], a[1], &bb[p][0]);
                mma8(acc[0][2*p+1], a[0], &bb[p][2]);
                mma8(acc[1][2*p+1], a[1], &bb[p][2]);
            }
        }
    }

    if (!lossMode){
#pragma unroll
        for (int mt = 0; mt < 2; mt++){
#pragma unroll
            for (int half = 0; half < 2; half++){
                int r = m0 + wm + mt*16 + (lane >> 2) + half*8;
                float* crow = C + (size_t)r * ldc;
                float* crow2 = Cr ? (Cr + (size_t)r * ldc) : nullptr;
                const float* rrow = residual ? (residual + (size_t)r * ldres) : nullptr;
#pragma unroll
                for (int nt = 0; nt < 8; nt++){
                    int col = n0 + wn + nt*8 + (lane & 3)*2;
                    float f0 = acc[mt][nt][half*2 + 0] * scale;
                    float f1 = acc[mt][nt][half*2 + 1] * scale;
                    if (bias){ f0 += bias[col]; f1 += bias[col + 1]; }
                    if (doRelu){ f0 = fmaxf(f0, 0.f); f1 = fmaxf(f1, 0.f); }
                    if (rrow){
                        float2 rv = *(const float2*)(rrow + col);
                        f0 += rv.x; f1 += rv.y;
                    }
                    if (roundC){ f0 = rnaf(f0); f1 = rnaf(f1); }
                    *(float2*)(crow + col) = make_float2(f0, f1);
                    if (crow2)
                        *(float2*)(crow2 + col) = make_float2(rnaf(f0), rnaf(f1));
                }
            }
        }
    } else {
        double lsum = 0.0;
#pragma unroll
        for (int mt = 0; mt < 2; mt++){
#pragma unroll
            for (int half = 0; half < 2; half++){
                int r = m0 + wm + mt*16 + (lane >> 2) + half*8;
                const float* hrow = lossH + (size_t)(r / 10) * 512;
#pragma unroll
                for (int nt = 0; nt < 8; nt++){
                    int col = n0 + wn + nt*8 + (lane & 3)*2;
                    float f0 = fmaxf(acc[mt][nt][half*2 + 0] + bias[col], 0.f);
                    float f1 = fmaxf(acc[mt][nt][half*2 + 1] + bias[col + 1], 0.f);
                    float d0 = f0 - hrow[col];
                    float d1 = f1 - hrow[col + 1];
                    lsum += (double)d0 * d0 + (double)d1 * d1;
                }
            }
        }
#pragma unroll
        for (int o = 16; o > 0; o >>= 1) lsum += __shfl_xor_sync(0xffffffffu, lsum, o);
        __shared__ double ds[8];
        if (lane == 0) ds[wid] = lsum;
        __syncthreads();
        if (tid == 0){
            double t = 0;
            for (int i = 0; i < 8; i++) t += ds[i];
            atomicAdd(&g_rec, t);
        }
    }
}

__global__ void transpose_w_kernel(const float* __restrict__ W,
                                   float* __restrict__ out, int K, int N)
{
    __shared__ float t[32][33];
    const int k0 = blockIdx.y * 32, n0 = blockIdx.x * 32;
    for (int i = threadIdx.y; i < 32; i += 8)
        t[i][threadIdx.x] = W[(size_t)(k0 + i) * N + n0 + threadIdx.x];
    __syncthreads();
    for (int i = threadIdx.y; i < 32; i += 8)
        out[(size_t)(n0 + i) * K + k0 + threadIdx.x] = rnaf(t[threadIdx.x][i]);
}

__global__ void transpose_qkv_kernel(const float* __restrict__ Wq,
                                     const float* __restrict__ Wk,
                                     const float* __restrict__ Wv,
                                     float* __restrict__ out)
{
    __shared__ float t[32][33];
    const float* W = blockIdx.z == 0 ? Wq : (blockIdx.z == 1 ? Wk : Wv);
    const int k0 = blockIdx.y * 32, n0 = blockIdx.x * 32;
    for (int i = threadIdx.y; i < 32; i += 8)
        t[i][threadIdx.x] = W[(size_t)(k0 + i) * 512 + n0 + threadIdx.x];
    __syncthreads();
    const int nout = blockIdx.z * 512 + n0;
    for (int i = threadIdx.y; i < 32; i += 8)
        out[(size_t)(nout + i) * 512 + k0 + threadIdx.x] = rnaf(t[threadIdx.x][i]);
}

__global__ void pack_bias_kernel(const float* __restrict__ bq,
                                 const float* __restrict__ bk,
                                 const float* __restrict__ bv)
{
    int i = blockIdx.x * 256 + threadIdx.x;
    if (i < 2*1536){
        int layer = i / 1536, col = i % 1536;
        const float* src = col < 512 ? bq : (col < 1024 ? bk : bv);
        g_bqkv[i] = src[layer*512 + (col & 511)];
    }
}

__global__ void transpose_v_kernel()
{
    __shared__ float t[32][33];
    const int bh = blockIdx.z, b = bh >> 2, h = bh & 3;
    const int k0 = blockIdx.x * 32;
    const int n0 = blockIdx.y * 32;
    for (int i = threadIdx.y; i < 32; i += 8)
        t[i][threadIdx.x] = g_qkvr[((size_t)b * 256 + k0 + i) * 1536 + 1024 + h * 128 + n0 + threadIdx.x];
    __syncthreads();
    for (int i = threadIdx.y; i < 32; i += 8)
        g_vt[((size_t)bh * 128 + n0 + i) * 256 + k0 + threadIdx.x] = t[threadIdx.x][i];
}

__global__ void round_h_kernel(const float* __restrict__ H)
{
    int i = blockIdx.x * 256 + threadIdx.x;
    float4 v = *(const float4*)(H + i * 4);
    *(float4*)(g_Hr + i * 4) = make_float4(rnaf(v.x), rnaf(v.y), rnaf(v.z), rnaf(v.w));
}

__global__ __launch_bounds__(256, 2) void gemm_kernel(
    const float* __restrict__ A, const float* __restrict__ W,
    float* __restrict__ C, int M, int N, int K,
    const float* __restrict__ bias)
{
    __shared__ float As[8][132];
    __shared__ float Bs[8][128];
    const int tid = threadIdx.x;
    const int m0 = blockIdx.y * 128, n0 = blockIdx.x * 128;
    const int arow = tid >> 1;
    const int aq   = (tid & 1) << 2;
    const int brow = tid >> 5;
    const int bcol = (tid & 31) << 2;
    const float* Ap = A + (size_t)(m0 + arow) * K + aq;
    const float* Wp = W + (size_t)brow * N + n0 + bcol;
    const int tx = tid & 15, ty = tid >> 4;

    float acc[8][8];
#pragma unroll
    for (int i = 0; i < 8; i++)
#pragma unroll
        for (int j = 0; j < 8; j++) acc[i][j] = 0.f;

    for (int k0 = 0; k0 < K; k0 += 8) {
        float4 av = *(const float4*)(Ap + k0);
        float4 bv = *(const float4*)(Wp + (size_t)k0 * N);
        As[aq+0][arow] = av.x; As[aq+1][arow] = av.y;
        As[aq+2][arow] = av.z; As[aq+3][arow] = av.w;
        *(float4*)&Bs[brow][bcol] = bv;
        __syncthreads();
#pragma unroll
        for (int kk = 0; kk < 8; kk++) {
            float fa[8], fb[8];
            *(float4*)&fa[0] = *(const float4*)&As[kk][ty*8];
            *(float4*)&fa[4] = *(const float4*)&As[kk][ty*8+4];
            *(float4*)&fb[0] = *(const float4*)&Bs[kk][tx*8];
            *(float4*)&fb[4] = *(const float4*)&Bs[kk][tx*8+4];
#pragma unroll
            for (int i = 0; i < 8; i++)
#pragma unroll
                for (int j = 0; j < 8; j++)
                    acc[i][j] = fmaf(fa[i], fb[j], acc[i][j]);
        }
        __syncthreads();
    }

    float bl[8];
#pragma unroll
    for (int j = 0; j < 8; j++) bl[j] = bias ? bias[n0 + tx*8 + j] : 0.f;
#pragma unroll
    for (int i = 0; i < 8; i++) {
        int m = m0 + ty*8 + i;
        float* cp = C + (size_t)m * N + n0 + tx*8;
        *(float4*)cp     = make_float4(acc[i][0]+bl[0], acc[i][1]+bl[1], acc[i][2]+bl[2], acc[i][3]+bl[3]);
        *(float4*)(cp+4) = make_float4(acc[i][4]+bl[4], acc[i][5]+bl[5], acc[i][6]+bl[6], acc[i][7]+bl[7]);
    }
}

// warp-per-row softmax over 256-wide rows of g_att (8 rows per block)
__global__ __launch_bounds__(256) void softmax_kernel()
{
    const int lane = threadIdx.x & 31;
    const int row = blockIdx.x * 8 + (threadIdx.x >> 5);
    float* p = g_att + (size_t)row * SSQ;
    float v[8];
    float mx = -1e30f;
#pragma unroll
    for (int j = 0; j < 8; j++){
        v[j] = p[lane + 32*j];
        mx = fmaxf(mx, v[j]);
    }
    mx = warpRedMax(mx);
    float s = 0.f;
#pragma unroll
    for (int j = 0; j < 8; j++){
        v[j] = expf(v[j] - mx);
        s += v[j];
    }
    s = warpRedSum(s);
#pragma unroll
    for (int j = 0; j < 8; j++)
        p[lane + 32*j] = rnaf(v[j] / s);
}

__global__ __launch_bounds__(256) void z_kernel(const float* __restrict__ eps)
{
    const int lane = threadIdx.x & 31;
    const int bs = blockIdx.x * 8 + (threadIdx.x >> 5);
    const float mean0 = g_stats[(size_t)bs*128 + lane];
    const float mean1 = g_stats[(size_t)bs*128 + 32 + lane];
    const float lv0   = g_stats[(size_t)bs*128 + 64 + lane];
    const float lv1   = g_stats[(size_t)bs*128 + 96 + lane];
    const float sd0 = expf(0.5f * lv0), sd1 = expf(0.5f * lv1);
    const float lvs = lv0 + lv1;
    for (int m = 0; m < 10; m++) {
        size_t off = ((size_t)bs*10 + m)*64;
        float e0 = eps[off + lane], e1 = eps[off + 32 + lane];
        float z0 = mean0 + e0 * sd0, z1 = mean1 + e1 * sd1;
        g_z[off + lane] = z0;        g_z[off + 32 + lane] = z1;
        g_zr[off + lane] = rnaf(z0); g_zr[off + 32 + lane] = rnaf(z1);
        float qv = warpRedSum(lvs + e0*e0 + e1*e1);
        if (lane == 0) g_logqz[(size_t)bs*10 + m] = -0.5f*qv + 64.f*LOG_NORM_F;
    }
}

__global__ void init_mu_kernel(const int* __restrict__ idx)
{
    const int b = blockIdx.x, k = blockIdx.y, l = threadIdx.x;
    const int lane = l & 31, w = l >> 5;
    const int n = idx[b*KCL + k];
    float v = g_z[((size_t)b*NPB + n)*64 + l];
    g_mu[((size_t)b*KCL + k)*64 + l] = v;
    float s = warpRedSum(v*v);
    __shared__ float sm[2];
    if (lane == 0) sm[w] = s;
    __syncthreads();
    if (l == 0) {
        g_m2[b*KCL + k] = sm[0] + sm[1];
        g_logpi[b*KCL + k] = -2.9957322735539909f;
    }
}

// zero BOTH parities of Nk (2*320) + muacc (2*20480) once
__global__ void zero_em_kernel()
{
    int i = blockIdx.x * 256 + threadIdx.x;
    if (i < 2*BB*KCL) g_Nk[i] = 0.f;
    if (i < 2*BB*KCL*64) g_muacc[i] = 0.f;
}

// Fused EM step: posteriors (smem) + Nk + muacc accumulation.
// Writes into parity buffers; idempotently zeroes the OTHER parity
// (consumed by the previous em_fin) for use 2 iterations later.
__global__ __launch_bounds__(256) void em_step_kernel(int parity)
{
    const int b = blockIdx.y;
    const int tid = threadIdx.x, lane = tid & 31, w = tid >> 5;
    __shared__ float mus[KCL*64];
    __shared__ float sc[KCL];
    __shared__ float nkacc[KCL];
    __shared__ float zt[64*65];   // padded rows
    __shared__ float pt[64*21];   // padded posteriors

    const int n0 = blockIdx.x * 64;
    for (int i = tid; i < KCL*64; i += 256) mus[i] = g_mu[(size_t)b*KCL*64 + i];
    if (tid < KCL) { sc[tid] = -0.5f*g_m2[b*KCL+tid] + g_logpi[b*KCL+tid]; nkacc[tid] = 0.f; }
    for (int i = tid; i < 64*64; i += 256)
        zt[(i >> 6)*65 + (i & 63)] = g_z[((size_t)b*NPB + n0)*64 + i];

    // zero other-parity slices (idempotent; previous em_fin already consumed them)
    {
        const int op = parity ^ 1;
        if (tid < 32)
            g_muacc[((size_t)op*BB + b)*KCL*64 + blockIdx.x*32 + tid] = 0.f;
        if (blockIdx.x == 0 && tid < KCL)
            g_Nk[(op*BB + b)*KCL + tid] = 0.f;
    }
    __syncthreads();

    // posteriors: warp per 8 rows, streaming softmax over K=20 (same math as before)
    float nkloc = 0.f;
    const int nb = w * 8;
    for (int t = 0; t < 8; t++) {
        const int n = nb + t;
        float z0 = zt[n*65 + lane], z1 = zt[n*65 + 32 + lane];
        float mx = -1e30f, s = 0.f, myll = 0.f;
#pragma unroll
        for (int k2 = 0; k2 < KCL; k2++) {
            float p = z0*mus[k2*64+lane] + z1*mus[k2*64+32+lane];
            p = warpRedSum(p) + sc[k2];
            if (lane == k2) myll = p;
            float nm = fmaxf(mx, p);
            s = s*expf(mx - nm) + expf(p - nm);
            mx = nm;
        }
        if (lane < KCL) {
            float pk = expf(myll - mx) / s;
            pt[n*21 + lane] = pk;
            nkloc += pk;
        }
    }
    if (lane < KCL) atomicAdd(&nkacc[lane], nkloc);
    __syncthreads();

    // muacc: thread (l, kq) accumulates 5 k's over the 64 local n
    {
        const int l = tid & 63, kq = tid >> 6;
        float a0=0.f, a1=0.f, a2=0.f, a3=0.f, a4=0.f;
#pragma unroll 4
        for (int nn = 0; nn < 64; nn++){
            float zv = zt[nn*65 + l];
            const float* pr = pt + nn*21 + kq*5;
            a0 = fmaf(pr[0], zv, a0);
            a1 = fmaf(pr[1], zv, a1);
            a2 = fmaf(pr[2], zv, a2);
            a3 = fmaf(pr[3], zv, a3);
            a4 = fmaf(pr[4], zv, a4);
        }
        float* dst = g_muacc + (((size_t)parity*BB + b)*KCL + kq*5)*64 + l;
        atomicAdd(dst,          a0);
        atomicAdd(dst + 64,     a1);
        atomicAdd(dst + 128,    a2);
        atomicAdd(dst + 192,    a3);
        atomicAdd(dst + 256,    a4);
    }
    if (tid < KCL) atomicAdd(&g_Nk[(parity*BB + b)*KCL + tid], nkacc[tid]);
}

__global__ void em_fin_kernel(int parity)
{
    const int k = blockIdx.x, b = blockIdx.y, l = threadIdx.x;
    const int lane = l & 31, w = l >> 5;
    const float* Nk = g_Nk + (parity*BB + b)*KCL;
    float nk = Nk[k];
    float m = g_muacc[(((size_t)parity*BB + b)*KCL + k)*64 + l] / nk;
    g_mu[((size_t)b*KCL + k)*64 + l] = m;
    float s = warpRedSum(m*m);
    __shared__ float sm[2];
    if (lane == 0) sm[w] = s;
    __syncthreads();
    if (l == 0) {
        g_m2[b*KCL + k] = sm[0] + sm[1];
        float tot = 0.f;
        for (int j = 0; j < KCL; j++) tot += Nk[j];
        g_logpi[b*KCL + k] = logf(nk / tot);
    }
}

__global__ __launch_bounds__(256) void kl_kernel()
{
    const int b = blockIdx.y;
    const int tid = threadIdx.x, lane = tid & 31, w = tid >> 5;
    __shared__ float mus[KCL*64];
    __shared__ float sc[KCL];
    for (int i = tid; i < KCL*64; i += 256) mus[i] = g_mu[(size_t)b*KCL*64 + i];
    if (tid < KCL) sc[tid] = -0.5f*g_m2[b*KCL+tid] + g_logpi[b*KCL+tid];
    __syncthreads();

    double loc = 0.0;
    const int nbase = blockIdx.x*64 + w*8;
    for (int t = 0; t < 8; t++) {
        int n = nbase + t;
        const float* zp = g_z + ((size_t)b*NPB + n)*64;
        float z0 = zp[lane], z1 = zp[lane+32];
        float sq = warpRedSum(z0*z0 + z1*z1);
        float mx = -1e30f, s = 0.f;
#pragma unroll
        for (int k2 = 0; k2 < KCL; k2++) {
            float p = z0*mus[k2*64+lane] + z1*mus[k2*64+32+lane];
            p = warpRedSum(p) + sc[k2];
            float nm = fmaxf(mx, p);
            s = s*expf(mx - nm) + expf(p - nm);
            mx = nm;
        }
        float lpz = mx + logf(s) - 0.5f*sq + 64.f*LOG_NORM_F;
        if (lane == 0) loc += (double)(g_logqz[(size_t)b*NPB + n] - lpz);
    }
    __shared__ double dacc[8];
    if (lane == 0) dacc[w] = loc;
    __syncthreads();
    if (tid == 0) {
        double t = 0;
        for (int i = 0; i < 8; i++) t += dacc[i];
        atomicAdd(&g_kl, t);
    }
}

__global__ void zero_accum_kernel() { g_rec = 0.0; g_kl = 0.0; }

__global__ void finalize_kernel(float* __restrict__ out)
{
    out[0] = (float)(g_rec / 40960.0);
    out[1] = (float)(g_kl / 40960.0);
}

static void* symaddr(const void* s)
{
    void* p = nullptr;
    cudaGetSymbolAddress(&p, s);
    return p;
}

#define GEMM_SMEM 98304

extern "C" void kernel_launch(void* const* d_in, const int* in_sizes, int n_in,
                              void* d_out, int out_size)
{
    const float *H, *eps, *wq, *bq, *wk, *bk, *wv, *bv, *wo, *bo, *wz, *bz;
    const float *w1, *b1, *w2, *b2, *w3, *b3;
    const int* init_idx;

    if (n_in >= 3 && in_sizes[2] == 320) {
        H = (const float*)d_in[0];  eps = (const float*)d_in[1]; init_idx = (const int*)d_in[2];
        wq = (const float*)d_in[3]; bq = (const float*)d_in[4];
        wk = (const float*)d_in[5]; bk = (const float*)d_in[6];
        wv = (const float*)d_in[7]; bv = (const float*)d_in[8];
        wo = (const float*)d_in[9]; bo = (const float*)d_in[10];
        wz = (const float*)d_in[11]; bz = (const float*)d_in[12];
        w1 = (const float*)d_in[13]; b1 = (const float*)d_in[14];
        w2 = (const float*)d_in[15]; b2 = (const float*)d_in[16];
        w3 = (const float*)d_in[17]; b3 = (const float*)d_in[18];
    } else {
        H = (const float*)d_in[0];  eps = (const float*)d_in[1];
        wq = (const float*)d_in[2]; bq = (const float*)d_in[3];
        wk = (const float*)d_in[4]; bk = (const float*)d_in[5];
        wv = (const float*)d_in[6]; bv = (const float*)d_in[7];
        wo = (const float*)d_in[8]; bo = (const float*)d_in[9];
        wz = (const float*)d_in[10]; bz = (const float*)d_in[11];
        w1 = (const float*)d_in[12]; b1 = (const float*)d_in[13];
        w2 = (const float*)d_in[14]; b2 = (const float*)d_in[15];
        w3 = (const float*)d_in[16]; b3 = (const float*)d_in[17];
        init_idx = (const int*)d_in[18];
    }

    cudaFuncSetAttribute(gemm_mma_kernel,
                         cudaFuncAttributeMaxDynamicSharedMemorySize, GEMM_SMEM);

    float* Hr    = (float*)symaddr(g_Hr);
    float* qkv   = (float*)symaddr(g_qkv);
    float* qkvr  = (float*)symaddr(g_qkvr);
    float* op    = (float*)symaddr(g_o);
    float* orp   = (float*)symaddr(g_or);
    float* hA    = (float*)symaddr(g_hA);
    float* hAr   = (float*)symaddr(g_hAr);
    float* hB    = (float*)symaddr(g_hB);
    float* hBr   = (float*)symaddr(g_hBr);
    float* attp  = (float*)symaddr(g_att);
    float* st    = (float*)symaddr(g_stats);
    float* zrp   = (float*)symaddr(g_zr);
    float* vtp   = (float*)symaddr(g_vt);
    float* wqkv0 = (float*)symaddr(g_wqkv0);
    float* wo0t  = (float*)symaddr(g_wo0);
    float* wqkv1 = (float*)symaddr(g_wqkv1);
    float* wo1t  = (float*)symaddr(g_wo1);
    float* w1t   = (float*)symaddr(g_w1t);
    float* w2t   = (float*)symaddr(g_w2t);
    float* w3t   = (float*)symaddr(g_w3t);
    float* bqkv  = (float*)symaddr(g_bqkv);
    float* d1p   = (float*)symaddr(g_d1);
    float* d2p   = (float*)symaddr(g_d2);

    zero_accum_kernel<<<1, 1>>>();
    round_h_kernel<<<2048, 256>>>(H);
    pack_bias_kernel<<<12, 256>>>(bq, bk, bv);
    transpose_qkv_kernel<<<dim3(16,16,3), dim3(32,8)>>>(wq, wk, wv, wqkv0);
    transpose_w_kernel<<<dim3(16,16), dim3(32,8)>>>(wo, wo0t, 512, 512);

    const float scl = 0.044194173824159216f;
    const float* wqkvT[2] = { wqkv0, wqkv1 };
    const float* woT[2]   = { wo0t, wo1t };
    const float* xinr = Hr;
    float* layer_out[2]  = { hA, hB };
    float* layer_outr[2] = { hAr, hBr };

    for (int i = 0; i < 2; i++) {
        const size_t boff = (size_t)i * DD;

        gemm_mma_kernel<<<dim3(12,32,1), 256, GEMM_SMEM>>>(
            xinr,512,0,0, wqkvT[i],512,0,0, qkv,1536,0,0, qkvr, 512,
            bqkv + (size_t)i*1536, nullptr,0,0,0, 1.f,0,0,0,nullptr);

        if (i == 0) {
            transpose_qkv_kernel<<<dim3(16,16,3), dim3(32,8)>>>(wq + DD*DD, wk + DD*DD, wv + DD*DD, wqkv1);
            transpose_w_kernel<<<dim3(16,16), dim3(32,8)>>>(wo + DD*DD, wo1t, 512, 512);
            transpose_w_kernel<<<dim3(32,2), dim3(32,8)>>>(w1, w1t, 64, 1024);
            transpose_w_kernel<<<dim3(32,32), dim3(32,8)>>>(w2, w2t, 1024, 1024);
            transpose_w_kernel<<<dim3(16,32), dim3(32,8)>>>(w3, w3t, 1024, 512);
        }

        // scores: K = 128 (head dim)
        gemm_mma_kernel<<<dim3(2,2,64), 256, GEMM_SMEM>>>(
            qkvr,1536,393216,128, qkvr+512,1536,393216,128,
            attp,256,262144,65536, nullptr, 128,
            nullptr, nullptr,0,0,0, scl,0,0,0,nullptr);
        softmax_kernel<<<64*SSQ/8, 256>>>();

        transpose_v_kernel<<<dim3(8,4,64), dim3(32,8)>>>();
        gemm_mma_kernel<<<dim3(1,2,64), 256, GEMM_SMEM>>>(
            attp,256,262144,65536, vtp,256,131072,32768,
            op,512,131072,128, orp, 256,
            nullptr, qkv,1536,393216,128, 1.f,0,0,0,nullptr);

        gemm_mma_kernel<<<dim3(4,32,1), 256, GEMM_SMEM>>>(
            orp,512,0,0, woT[i],512,0,0, layer_out[i],512,0,0,
            layer_outr[i], 512, bo+boff, op,512,0,0, 1.f,1,0,0,nullptr);
        xinr = layer_outr[i];
    }

    gemm_kernel<<<dim3(1, 32), 256>>>(hB, wz, st, NTOK, 128, DD, bz);

    z_kernel<<<512, 256>>>(eps);
    init_mu_kernel<<<dim3(BB, KCL), 64>>>(init_idx);
    zero_em_kernel<<<161, 256>>>();

    for (int it = 0; it < 5; it++) {
        em_step_kernel<<<dim3(40, BB), 256>>>(it & 1);
        em_fin_kernel<<<dim3(KCL, BB), 64>>>(it & 1);
    }

    gemm_mma_kernel<<<dim3(8,320,1), 256, GEMM_SMEM>>>(
        zrp,64,0,0, w1t,64,0,0, d1p,1024,0,0, nullptr,
        64, b1, nullptr,0,0,0, 1.f,1,1,0,nullptr);
    gemm_mma_kernel<<<dim3(8,320,1), 256, GEMM_SMEM>>>(
        d1p,1024,0,0, w2t,1024,0,0, d2p,1024,0,0, nullptr,
        1024, b2, nullptr,0,0,0, 1.f,1,1,0,nullptr);
    gemm_mma_kernel<<<dim3(4,320,1), 256, GEMM_SMEM>>>(
        d2p,1024,0,0, w3t,1024,0,0, nullptr,512,0,0, nullptr,
        1024, b3, nullptr,0,0,0, 1.f,0,0,1,H);

    kl_kernel<<<dim3(40, BB), 256>>>();
    finalize_kernel<<<1, 1>>>((float*)d_out);
    (void)in_sizes; (void)n_in; (void)out_size;
}

// round 10
// speedup vs baseline: 3.6714x; 1.5343x over previous
#include <cuda_runtime.h>
#include <cuda_bf16.h>
#include <math.h>
#include <stdint.h>

#define BB   16
#define SSQ  256
#define DD   512
#define KCL  20
#define NTOK 4096
#define NZ   40960
#define NPB  2560
#define LOG_NORM_F (-0.91893853320467274178f)

typedef __nv_bfloat16 bf16;
typedef __nv_bfloat162 bf162;

// fp32 buffers
__device__ float g_qkv[NTOK*1536];        // raw fused qkv (q = residual)
__device__ float g_o[NTOK*DD];            // raw o (residual for wo / stats path)
__device__ float g_hA[NTOK*DD];
__device__ float g_hB[NTOK*DD];
__device__ float g_att[64*SSQ*SSQ];       // raw scores (softmax input)
__device__ float g_stats[NTOK*128];
__device__ float g_z[NZ*64];
__device__ float g_logqz[NZ];
__device__ float g_mu[BB*KCL*64];
__device__ float g_muacc[2*BB*KCL*64];
__device__ float g_m2[BB*KCL];
__device__ float g_logpi[BB*KCL];
__device__ float g_Nk[2*BB*KCL];
__device__ float g_bqkv[2*1536];
__device__ double g_rec;
__device__ double g_kl;
// bf16 GEMM operand buffers
__device__ bf16 g_Hb[NTOK*DD];
__device__ bf16 g_qkvb[NTOK*1536];
__device__ bf16 g_vtb[64*128*256];
__device__ bf16 g_ob[NTOK*DD];
__device__ bf16 g_hAb[NTOK*DD];
__device__ bf16 g_hBb[NTOK*DD];
__device__ bf16 g_attb[64*SSQ*SSQ];
__device__ bf16 g_zb[NZ*64];
__device__ bf16 g_wqkv0[1536*512];
__device__ bf16 g_wo0[512*512];
__device__ bf16 g_wqkv1[1536*512];
__device__ bf16 g_wo1[512*512];
__device__ bf16 g_w1t[1024*64];
__device__ bf16 g_w2t[1024*1024];
__device__ bf16 g_w3t[512*1024];
__device__ bf16 g_d1[41943040];
__device__ bf16 g_d2[41943040];

__device__ __forceinline__ float warpRedSum(float v){
#pragma unroll
    for (int o = 16; o > 0; o >>= 1) v += __shfl_xor_sync(0xffffffffu, v, o);
    return v;
}
__device__ __forceinline__ float warpRedMax(float v){
#pragma unroll
    for (int o = 16; o > 0; o >>= 1) v = fmaxf(v, __shfl_xor_sync(0xffffffffu, v, o));
    return v;
}
__device__ __forceinline__ uint32_t smem_u32(const void* p){
    uint32_t a;
    asm("{ .reg .u64 t; cvta.to.shared.u64 t, %1; cvt.u32.u64 %0, t; }" : "=r"(a) : "l"(p));
    return a;
}
__device__ __forceinline__ void ldsm4(uint32_t* r, uint32_t addr){
    asm volatile("ldmatrix.sync.aligned.m8n8.x4.shared.b16 {%0,%1,%2,%3}, [%4];"
        : "=r"(r[0]), "=r"(r[1]), "=r"(r[2]), "=r"(r[3]) : "r"(addr));
}
__device__ __forceinline__ void mma16(float* d, const uint32_t* a, const uint32_t* b){
    asm volatile(
        "mma.sync.aligned.m16n8k16.row.col.f32.bf16.bf16.f32 "
        "{%0,%1,%2,%3}, {%4,%5,%6,%7}, {%8,%9}, {%0,%1,%2,%3};"
        : "+f"(d[0]), "+f"(d[1]), "+f"(d[2]), "+f"(d[3])
        : "r"(a[0]), "r"(a[1]), "r"(a[2]), "r"(a[3]), "r"(b[0]), "r"(b[1]));
}
#define CP16(dst, src) \
    asm volatile("cp.async.cg.shared.global [%0], [%1], 16;" :: "r"(dst), "l"(src))
#define CP_COMMIT() asm volatile("cp.async.commit_group;" ::: "memory")

// =======================================================================
// BF16 tensor-core GEMM: epi( scale * sum_k A[m,k]*B[n,k] ), fp32 accum.
// A,B bf16 [rows x K] row-major (ld in elements). 128x128 tile, K-chunk 64
// (128B rows), 3-buffer 2-ahead cp.async pipeline, 1 barrier/chunk.
// 8 warps (4Mx2N), warp tile 32x64 of m16n8k16. Same swizzle/ldmatrix
// lane decomposition as the tf32 version (16B group == one 8x8 b16 matrix).
// Outputs: optional fp32 C, optional bf16 Cb (both with full epilogue).
// =======================================================================
__global__ __launch_bounds__(256, 2) void gemm_mma_kernel(
    const bf16* __restrict__ A, int lda, long long sAb, long long sAh,
    const bf16* __restrict__ B, int ldb, long long sBb, long long sBh,
    float* __restrict__ C, int ldc, long long sCb, long long sCh,
    bf16* __restrict__ Cb,
    int K,
    const float* __restrict__ bias,
    const float* __restrict__ residual, int ldres, long long sRb, long long sRh,
    float scale, int doRelu, int lossMode,
    const float* __restrict__ lossH)
{
    extern __shared__ __align__(16) char smem[];   // 3 * 32768
    const int tid = threadIdx.x;
    const int wid = tid >> 5, lane = tid & 31;

    const int zb = blockIdx.z >> 2, zh = blockIdx.z & 3;
    A += (long long)zb * sAb + (long long)zh * sAh;
    B += (long long)zb * sBb + (long long)zh * sBh;
    if (C)        C        += (long long)zb * sCb + (long long)zh * sCh;
    if (Cb)       Cb       += (long long)zb * sCb + (long long)zh * sCh;
    if (residual) residual += (long long)zb * sRb + (long long)zh * sRh;

    const int m0 = blockIdx.y * 128, n0 = blockIdx.x * 128;
    const int kTiles = K >> 6;                      // 64 bf16 per chunk
    const uint32_t smem0 = smem_u32(smem);

    const int srow = tid & 127;
    const bool isB = (tid >= 128);
    const bf16* gsrc = isB ? (B + (size_t)(n0 + srow) * ldb)
                           : (A + (size_t)(m0 + srow) * lda);
    const uint32_t sdst0 = smem0 + (isB ? 16384 : 0) + srow * 128;
    const int rx = srow & 7;

    const int pstages = kTiles < 2 ? kTiles : 2;
    for (int c = 0; c < pstages; c++){
        const bf16* gs = gsrc + c * 64;
        const uint32_t sd = sdst0 + c * 32768;
#pragma unroll
        for (int j = 0; j < 8; j++)
            CP16(sd + ((j ^ rx) << 4), gs + j * 8);
        CP_COMMIT();
    }

    float acc[2][8][4];
#pragma unroll
    for (int i = 0; i < 2; i++)
#pragma unroll
        for (int j = 0; j < 8; j++)
#pragma unroll
            for (int q = 0; q < 4; q++) acc[i][j][q] = 0.f;

    const int wm = (wid & 3) * 32;
    const int wn = (wid >> 2) * 64;
    const int rr = lane & 7;
    const int qm = lane >> 3;
    const int qlow = qm & 1, qhigh = qm >> 1;
    uint32_t rowbaseA[2];
#pragma unroll
    for (int mt = 0; mt < 2; mt++)
        rowbaseA[mt] = (uint32_t)((wm + mt*16 + rr + 8*qlow) * 128);
    uint32_t rowbaseB[4];
#pragma unroll
    for (int p = 0; p < 4; p++)
        rowbaseB[p] = (uint32_t)(16384 + (wn + (2*p + qhigh)*8 + rr) * 128);

    for (int c = 0; c < kTiles; c++){
        if (c + 1 < kTiles) asm volatile("cp.async.wait_group 1;" ::: "memory");
        else                asm volatile("cp.async.wait_group 0;" ::: "memory");
        __syncthreads();

        if (c + 2 < kTiles){
            const bf16* gs = gsrc + (c + 2) * 64;
            const uint32_t sd = sdst0 + ((c + 2) % 3) * 32768;
#pragma unroll
            for (int j = 0; j < 8; j++)
                CP16(sd + ((j ^ rx) << 4), gs + j * 8);
            CP_COMMIT();
        }

        const uint32_t st = smem0 + (c % 3) * 32768;
        // 4 k16 steps per chunk; k16 step t uses 16B groups {2t, 2t+1}
#pragma unroll
        for (int t = 0; t < 4; t++){
            const uint32_t offA = (uint32_t)(((2*t + qhigh) ^ rr) << 4);
            const uint32_t offB = (uint32_t)(((2*t + qlow) ^ rr) << 4);
            uint32_t a[2][4], bb[4][4];
            ldsm4(a[0], st + rowbaseA[0] + offA);   // a0..a3 for mt=0
            ldsm4(a[1], st + rowbaseA[1] + offA);   // mt=1
#pragma unroll
            for (int p = 0; p < 4; p++)
                ldsm4(bb[p], st + rowbaseB[p] + offB);  // {nt=2p:k0-7,k8-15, nt=2p+1:...}
#pragma unroll
            for (int p = 0; p < 4; p++){
                mma16(acc[0][2*p+0], a[0], &bb[p][0]);
                mma16(acc[1][2*p+0], a[1], &bb[p][0]);
                mma16(acc[0][2*p+1], a[0], &bb[p][2]);
                mma16(acc[1][2*p+1], a[1], &bb[p][2]);
            }
        }
    }

    if (!lossMode){
#pragma unroll
        for (int mt = 0; mt < 2; mt++){
#pragma unroll
            for (int half = 0; half < 2; half++){
                int r = m0 + wm + mt*16 + (lane >> 2) + half*8;
                float* crow = C ? (C + (size_t)r * ldc) : nullptr;
                bf16* crowb = Cb ? (Cb + (size_t)r * ldc) : nullptr;
                const float* rrow = residual ? (residual + (size_t)r * ldres) : nullptr;
#pragma unroll
                for (int nt = 0; nt < 8; nt++){
                    int col = n0 + wn + nt*8 + (lane & 3)*2;
                    float f0 = acc[mt][nt][half*2 + 0] * scale;
                    float f1 = acc[mt][nt][half*2 + 1] * scale;
                    if (bias){ f0 += bias[col]; f1 += bias[col + 1]; }
                    if (doRelu){ f0 = fmaxf(f0, 0.f); f1 = fmaxf(f1, 0.f); }
                    if (rrow){
                        float2 rv = *(const float2*)(rrow + col);
                        f0 += rv.x; f1 += rv.y;
                    }
                    if (crow)  *(float2*)(crow + col) = make_float2(f0, f1);
                    if (crowb) *(bf162*)(crowb + col) = __floats2bfloat162_rn(f0, f1);
                }
            }
        }
    } else {
        double lsum = 0.0;
#pragma unroll
        for (int mt = 0; mt < 2; mt++){
#pragma unroll
            for (int half = 0; half < 2; half++){
                int r = m0 + wm + mt*16 + (lane >> 2) + half*8;
                const float* hrow = lossH + (size_t)(r / 10) * 512;
#pragma unroll
                for (int nt = 0; nt < 8; nt++){
                    int col = n0 + wn + nt*8 + (lane & 3)*2;
                    float f0 = fmaxf(acc[mt][nt][half*2 + 0] + bias[col], 0.f);
                    float f1 = fmaxf(acc[mt][nt][half*2 + 1] + bias[col + 1], 0.f);
                    float d0 = f0 - hrow[col];
                    float d1 = f1 - hrow[col + 1];
                    lsum += (double)d0 * d0 + (double)d1 * d1;
                }
            }
        }
#pragma unroll
        for (int o = 16; o > 0; o >>= 1) lsum += __shfl_xor_sync(0xffffffffu, lsum, o);
        __shared__ double ds[8];
        if (lane == 0) ds[wid] = lsum;
        __syncthreads();
        if (tid == 0){
            double t = 0;
            for (int i = 0; i < 8; i++) t += ds[i];
            atomicAdd(&g_rec, t);
        }
    }
}

// weight transpose -> bf16: out[n*K + k] = bf16(W[k*N + n])
__global__ void transpose_w_kernel(const float* __restrict__ W,
                                   bf16* __restrict__ out, int K, int N)
{
    __shared__ float t[32][33];
    const int k0 = blockIdx.y * 32, n0 = blockIdx.x * 32;
    for (int i = threadIdx.y; i < 32; i += 8)
        t[i][threadIdx.x] = W[(size_t)(k0 + i) * N + n0 + threadIdx.x];
    __syncthreads();
    for (int i = threadIdx.y; i < 32; i += 8)
        out[(size_t)(n0 + i) * K + k0 + threadIdx.x] = __float2bfloat16(t[threadIdx.x][i]);
}

__global__ void transpose_qkv_kernel(const float* __restrict__ Wq,
                                     const float* __restrict__ Wk,
                                     const float* __restrict__ Wv,
                                     bf16* __restrict__ out)
{
    __shared__ float t[32][33];
    const float* W = blockIdx.z == 0 ? Wq : (blockIdx.z == 1 ? Wk : Wv);
    const int k0 = blockIdx.y * 32, n0 = blockIdx.x * 32;
    for (int i = threadIdx.y; i < 32; i += 8)
        t[i][threadIdx.x] = W[(size_t)(k0 + i) * 512 + n0 + threadIdx.x];
    __syncthreads();
    const int nout = blockIdx.z * 512 + n0;
    for (int i = threadIdx.y; i < 32; i += 8)
        out[(size_t)(nout + i) * 512 + k0 + threadIdx.x] = __float2bfloat16(t[threadIdx.x][i]);
}

__global__ void pack_bias_kernel(const float* __restrict__ bq,
                                 const float* __restrict__ bk,
                                 const float* __restrict__ bv)
{
    int i = blockIdx.x * 256 + threadIdx.x;
    if (i < 2*1536){
        int layer = i / 1536, col = i % 1536;
        const float* src = col < 512 ? bq : (col < 1024 ? bk : bv);
        g_bqkv[i] = src[layer*512 + (col & 511)];
    }
}

// g_vtb[bh][n][k] = g_qkvb[b][k][1024 + h*128 + n]   (bf16, lossless roundtrip via float)
__global__ void transpose_v_kernel()
{
    __shared__ float t[32][33];
    const int bh = blockIdx.z, b = bh >> 2, h = bh & 3;
    const int k0 = blockIdx.x * 32;
    const int n0 = blockIdx.y * 32;
    for (int i = threadIdx.y; i < 32; i += 8)
        t[i][threadIdx.x] = __bfloat162float(
            g_qkvb[((size_t)b * 256 + k0 + i) * 1536 + 1024 + h * 128 + n0 + threadIdx.x]);
    __syncthreads();
    for (int i = threadIdx.y; i < 32; i += 8)
        g_vtb[((size_t)bh * 128 + n0 + i) * 256 + k0 + threadIdx.x] = __float2bfloat16(t[threadIdx.x][i]);
}

// bf16 copy of H
__global__ void round_h_kernel(const float* __restrict__ H)
{
    int i = blockIdx.x * 256 + threadIdx.x;
    float4 v = *(const float4*)(H + i * 4);
    bf162 lo = __floats2bfloat162_rn(v.x, v.y);
    bf162 hi = __floats2bfloat162_rn(v.z, v.w);
    *(bf162*)(g_Hb + i * 4) = lo;
    *(bf162*)(g_Hb + i * 4 + 2) = hi;
}

// fp32 SIMT GEMM (precision-sensitive stats projection only)
__global__ __launch_bounds__(256, 2) void gemm_kernel(
    const float* __restrict__ A, const float* __restrict__ W,
    float* __restrict__ C, int M, int N, int K,
    const float* __restrict__ bias)
{
    __shared__ float As[8][132];
    __shared__ float Bs[8][128];
    const int tid = threadIdx.x;
    const int m0 = blockIdx.y * 128, n0 = blockIdx.x * 128;
    const int arow = tid >> 1;
    const int aq   = (tid & 1) << 2;
    const int brow = tid >> 5;
    const int bcol = (tid & 31) << 2;
    const float* Ap = A + (size_t)(m0 + arow) * K + aq;
    const float* Wp = W + (size_t)brow * N + n0 + bcol;
    const int tx = tid & 15, ty = tid >> 4;

    float acc[8][8];
#pragma unroll
    for (int i = 0; i < 8; i++)
#pragma unroll
        for (int j = 0; j < 8; j++) acc[i][j] = 0.f;

    for (int k0 = 0; k0 < K; k0 += 8) {
        float4 av = *(const float4*)(Ap + k0);
        float4 bv = *(const float4*)(Wp + (size_t)k0 * N);
        As[aq+0][arow] = av.x; As[aq+1][arow] = av.y;
        As[aq+2][arow] = av.z; As[aq+3][arow] = av.w;
        *(float4*)&Bs[brow][bcol] = bv;
        __syncthreads();
#pragma unroll
        for (int kk = 0; kk < 8; kk++) {
            float fa[8], fb[8];
            *(float4*)&fa[0] = *(const float4*)&As[kk][ty*8];
            *(float4*)&fa[4] = *(const float4*)&As[kk][ty*8+4];
            *(float4*)&fb[0] = *(const float4*)&Bs[kk][tx*8];
            *(float4*)&fb[4] = *(const float4*)&Bs[kk][tx*8+4];
#pragma unroll
            for (int i = 0; i < 8; i++)
#pragma unroll
                for (int j = 0; j < 8; j++)
                    acc[i][j] = fmaf(fa[i], fb[j], acc[i][j]);
        }
        __syncthreads();
    }

    float bl[8];
#pragma unroll
    for (int j = 0; j < 8; j++) bl[j] = bias ? bias[n0 + tx*8 + j] : 0.f;
#pragma unroll
    for (int i = 0; i < 8; i++) {
        int m = m0 + ty*8 + i;
        float* cp = C + (size_t)m * N + n0 + tx*8;
        *(float4*)cp     = make_float4(acc[i][0]+bl[0], acc[i][1]+bl[1], acc[i][2]+bl[2], acc[i][3]+bl[3]);
        *(float4*)(cp+4) = make_float4(acc[i][4]+bl[4], acc[i][5]+bl[5], acc[i][6]+bl[6], acc[i][7]+bl[7]);
    }
}

// warp-per-row softmax: read fp32 att, write bf16 attb
__global__ __launch_bounds__(256) void softmax_kernel()
{
    const int lane = threadIdx.x & 31;
    const int row = blockIdx.x * 8 + (threadIdx.x >> 5);
    const float* p = g_att + (size_t)row * SSQ;
    bf16* po = g_attb + (size_t)row * SSQ;
    float v[8];
    float mx = -1e30f;
#pragma unroll
    for (int j = 0; j < 8; j++){
        v[j] = p[lane + 32*j];
        mx = fmaxf(mx, v[j]);
    }
    mx = warpRedMax(mx);
    float s = 0.f;
#pragma unroll
    for (int j = 0; j < 8; j++){
        v[j] = expf(v[j] - mx);
        s += v[j];
    }
    s = warpRedSum(s);
#pragma unroll
    for (int j = 0; j < 8; j++)
        po[lane + 32*j] = __float2bfloat16(v[j] / s);
}

__global__ __launch_bounds__(256) void z_kernel(const float* __restrict__ eps)
{
    const int lane = threadIdx.x & 31;
    const int bs = blockIdx.x * 8 + (threadIdx.x >> 5);
    const float mean0 = g_stats[(size_t)bs*128 + lane];
    const float mean1 = g_stats[(size_t)bs*128 + 32 + lane];
    const float lv0   = g_stats[(size_t)bs*128 + 64 + lane];
    const float lv1   = g_stats[(size_t)bs*128 + 96 + lane];
    const float sd0 = expf(0.5f * lv0), sd1 = expf(0.5f * lv1);
    const float lvs = lv0 + lv1;
    for (int m = 0; m < 10; m++) {
        size_t off = ((size_t)bs*10 + m)*64;
        float e0 = eps[off + lane], e1 = eps[off + 32 + lane];
        float z0 = mean0 + e0 * sd0, z1 = mean1 + e1 * sd1;
        g_z[off + lane] = z0;        g_z[off + 32 + lane] = z1;
        g_zb[off + lane] = __float2bfloat16(z0);
        g_zb[off + 32 + lane] = __float2bfloat16(z1);
        float qv = warpRedSum(lvs + e0*e0 + e1*e1);
        if (lane == 0) g_logqz[(size_t)bs*10 + m] = -0.5f*qv + 64.f*LOG_NORM_F;
    }
}

__global__ void init_mu_kernel(const int* __restrict__ idx)
{
    const int b = blockIdx.x, k = blockIdx.y, l = threadIdx.x;
    const int lane = l & 31, w = l >> 5;
    const int n = idx[b*KCL + k];
    float v = g_z[((size_t)b*NPB + n)*64 + l];
    g_mu[((size_t)b*KCL + k)*64 + l] = v;
    float s = warpRedSum(v*v);
    __shared__ float sm[2];
    if (lane == 0) sm[w] = s;
    __syncthreads();
    if (l == 0) {
        g_m2[b*KCL + k] = sm[0] + sm[1];
        g_logpi[b*KCL + k] = -2.9957322735539909f;
    }
}

__global__ void zero_em_kernel()
{
    int i = blockIdx.x * 256 + threadIdx.x;
    if (i < 2*BB*KCL) g_Nk[i] = 0.f;
    if (i < 2*BB*KCL*64) g_muacc[i] = 0.f;
}

__global__ __launch_bounds__(256) void em_step_kernel(int parity)
{
    const int b = blockIdx.y;
    const int tid = threadIdx.x, lane = tid & 31, w = tid >> 5;
    __shared__ float mus[KCL*64];
    __shared__ float sc[KCL];
    __shared__ float nkacc[KCL];
    __shared__ float zt[64*65];
    __shared__ float pt[64*21];

    const int n0 = blockIdx.x * 64;
    for (int i = tid; i < KCL*64; i += 256) mus[i] = g_mu[(size_t)b*KCL*64 + i];
    if (tid < KCL) { sc[tid] = -0.5f*g_m2[b*KCL+tid] + g_logpi[b*KCL+tid]; nkacc[tid] = 0.f; }
    for (int i = tid; i < 64*64; i += 256)
        zt[(i >> 6)*65 + (i & 63)] = g_z[((size_t)b*NPB + n0)*64 + i];

    {
        const int op = parity ^ 1;
        if (tid < 32)
            g_muacc[((size_t)op*BB + b)*KCL*64 + blockIdx.x*32 + tid] = 0.f;
        if (blockIdx.x == 0 && tid < KCL)
            g_Nk[(op*BB + b)*KCL + tid] = 0.f;
    }
    __syncthreads();

    float nkloc = 0.f;
    const int nb = w * 8;
    for (int t = 0; t < 8; t++) {
        const int n = nb + t;
        float z0 = zt[n*65 + lane], z1 = zt[n*65 + 32 + lane];
        float mx = -1e30f, s = 0.f, myll = 0.f;
#pragma unroll
        for (int k2 = 0; k2 < KCL; k2++) {
            float p = z0*mus[k2*64+lane] + z1*mus[k2*64+32+lane];
            p = warpRedSum(p) + sc[k2];
            if (lane == k2) myll = p;
            float nm = fmaxf(mx, p);
            s = s*expf(mx - nm) + expf(p - nm);
            mx = nm;
        }
        if (lane < KCL) {
            float pk = expf(myll - mx) / s;
            pt[n*21 + lane] = pk;
            nkloc += pk;
        }
    }
    if (lane < KCL) atomicAdd(&nkacc[lane], nkloc);
    __syncthreads();

    {
        const int l = tid & 63, kq = tid >> 6;
        float a0=0.f, a1=0.f, a2=0.f, a3=0.f, a4=0.f;
#pragma unroll 4
        for (int nn = 0; nn < 64; nn++){
            float zv = zt[nn*65 + l];
            const float* pr = pt + nn*21 + kq*5;
            a0 = fmaf(pr[0], zv, a0);
            a1 = fmaf(pr[1], zv, a1);
            a2 = fmaf(pr[2], zv, a2);
            a3 = fmaf(pr[3], zv, a3);
            a4 = fmaf(pr[4], zv, a4);
        }
        float* dst = g_muacc + (((size_t)parity*BB + b)*KCL + kq*5)*64 + l;
        atomicAdd(dst,       a0);
        atomicAdd(dst + 64,  a1);
        atomicAdd(dst + 128, a2);
        atomicAdd(dst + 192, a3);
        atomicAdd(dst + 256, a4);
    }
    if (tid < KCL) atomicAdd(&g_Nk[(parity*BB + b)*KCL + tid], nkacc[tid]);
}

__global__ void em_fin_kernel(int parity)
{
    const int k = blockIdx.x, b = blockIdx.y, l = threadIdx.x;
    const int lane = l & 31, w = l >> 5;
    const float* Nk = g_Nk + (parity*BB + b)*KCL;
    float nk = Nk[k];
    float m = g_muacc[(((size_t)parity*BB + b)*KCL + k)*64 + l] / nk;
    g_mu[((size_t)b*KCL + k)*64 + l] = m;
    float s = warpRedSum(m*m);
    __shared__ float sm[2];
    if (lane == 0) sm[w] = s;
    __syncthreads();
    if (l == 0) {
        g_m2[b*KCL + k] = sm[0] + sm[1];
        float tot = 0.f;
        for (int j = 0; j < KCL; j++) tot += Nk[j];
        g_logpi[b*KCL + k] = logf(nk / tot);
    }
}

__global__ __launch_bounds__(256) void kl_kernel()
{
    const int b = blockIdx.y;
    const int tid = threadIdx.x, lane = tid & 31, w = tid >> 5;
    __shared__ float mus[KCL*64];
    __shared__ float sc[KCL];
    for (int i = tid; i < KCL*64; i += 256) mus[i] = g_mu[(size_t)b*KCL*64 + i];
    if (tid < KCL) sc[tid] = -0.5f*g_m2[b*KCL+tid] + g_logpi[b*KCL+tid];
    __syncthreads();

    double loc = 0.0;
    const int nbase = blockIdx.x*64 + w*8;
    for (int t = 0; t < 8; t++) {
        int n = nbase + t;
        const float* zp = g_z + ((size_t)b*NPB + n)*64;
        float z0 = zp[lane], z1 = zp[lane+32];
        float sq = warpRedSum(z0*z0 + z1*z1);
        float mx = -1e30f, s = 0.f;
#pragma unroll
        for (int k2 = 0; k2 < KCL; k2++) {
            float p = z0*mus[k2*64+lane] + z1*mus[k2*64+32+lane];
            p = warpRedSum(p) + sc[k2];
            float nm = fmaxf(mx, p);
            s = s*expf(mx - nm) + expf(p - nm);
            mx = nm;
        }
        float lpz = mx + logf(s) - 0.5f*sq + 64.f*LOG_NORM_F;
        if (lane == 0) loc += (double)(g_logqz[(size_t)b*NPB + n] - lpz);
    }
    __shared__ double dacc[8];
    if (lane == 0) dacc[w] = loc;
    __syncthreads();
    if (tid == 0) {
        double t = 0;
        for (int i = 0; i < 8; i++) t += dacc[i];
        atomicAdd(&g_kl, t);
    }
}

__global__ void zero_accum_kernel() { g_rec = 0.0; g_kl = 0.0; }

__global__ void finalize_kernel(float* __restrict__ out)
{
    out[0] = (float)(g_rec / 40960.0);
    out[1] = (float)(g_kl / 40960.0);
}

static void* symaddr(const void* s)
{
    void* p = nullptr;
    cudaGetSymbolAddress(&p, s);
    return p;
}

#define GEMM_SMEM 98304

extern "C" void kernel_launch(void* const* d_in, const int* in_sizes, int n_in,
                              void* d_out, int out_size)
{
    const float *H, *eps, *wq, *bq, *wk, *bk, *wv, *bv, *wo, *bo, *wz, *bz;
    const float *w1, *b1, *w2, *b2, *w3, *b3;
    const int* init_idx;

    if (n_in >= 3 && in_sizes[2] == 320) {
        H = (const float*)d_in[0];  eps = (const float*)d_in[1]; init_idx = (const int*)d_in[2];
        wq = (const float*)d_in[3]; bq = (const float*)d_in[4];
        wk = (const float*)d_in[5]; bk = (const float*)d_in[6];
        wv = (const float*)d_in[7]; bv = (const float*)d_in[8];
        wo = (const float*)d_in[9]; bo = (const float*)d_in[10];
        wz = (const float*)d_in[11]; bz = (const float*)d_in[12];
        w1 = (const float*)d_in[13]; b1 = (const float*)d_in[14];
        w2 = (const float*)d_in[15]; b2 = (const float*)d_in[16];
        w3 = (const float*)d_in[17]; b3 = (const float*)d_in[18];
    } else {
        H = (const float*)d_in[0];  eps = (const float*)d_in[1];
        wq = (const float*)d_in[2]; bq = (const float*)d_in[3];
        wk = (const float*)d_in[4]; bk = (const float*)d_in[5];
        wv = (const float*)d_in[6]; bv = (const float*)d_in[7];
        wo = (const float*)d_in[8]; bo = (const float*)d_in[9];
        wz = (const float*)d_in[10]; bz = (const float*)d_in[11];
        w1 = (const float*)d_in[12]; b1 = (const float*)d_in[13];
        w2 = (const float*)d_in[14]; b2 = (const float*)d_in[15];
        w3 = (const float*)d_in[16]; b3 = (const float*)d_in[17];
        init_idx = (const int*)d_in[18];
    }

    cudaFuncSetAttribute(gemm_mma_kernel,
                         cudaFuncAttributeMaxDynamicSharedMemorySize, GEMM_SMEM);

    bf16* Hb    = (bf16*)symaddr(g_Hb);
    float* qkv  = (float*)symaddr(g_qkv);
    bf16* qkvb  = (bf16*)symaddr(g_qkvb);
    float* op   = (float*)symaddr(g_o);
    bf16* ob    = (bf16*)symaddr(g_ob);
    float* hA   = (float*)symaddr(g_hA);
    bf16* hAb   = (bf16*)symaddr(g_hAb);
    float* hB   = (float*)symaddr(g_hB);
    bf16* hBb   = (bf16*)symaddr(g_hBb);
    float* attp = (float*)symaddr(g_att);
    bf16* attb  = (bf16*)symaddr(g_attb);
    float* st   = (float*)symaddr(g_stats);
    bf16* zb    = (bf16*)symaddr(g_zb);
    bf16* vtb   = (bf16*)symaddr(g_vtb);
    bf16* wqkv0 = (bf16*)symaddr(g_wqkv0);
    bf16* wo0t  = (bf16*)symaddr(g_wo0);
    bf16* wqkv1 = (bf16*)symaddr(g_wqkv1);
    bf16* wo1t  = (bf16*)symaddr(g_wo1);
    bf16* w1t   = (bf16*)symaddr(g_w1t);
    bf16* w2t   = (bf16*)symaddr(g_w2t);
    bf16* w3t   = (bf16*)symaddr(g_w3t);
    float* bqkv = (float*)symaddr(g_bqkv);
    bf16* d1b   = (bf16*)symaddr(g_d1);
    bf16* d2b   = (bf16*)symaddr(g_d2);

    zero_accum_kernel<<<1, 1>>>();
    round_h_kernel<<<2048, 256>>>(H);
    pack_bias_kernel<<<12, 256>>>(bq, bk, bv);
    transpose_qkv_kernel<<<dim3(16,16,3), dim3(32,8)>>>(wq, wk, wv, wqkv0);
    transpose_w_kernel<<<dim3(16,16), dim3(32,8)>>>(wo, wo0t, 512, 512);

    const float scl = 0.044194173824159216f;
    bf16* wqkvT[2] = { wqkv0, wqkv1 };
    bf16* woT[2]   = { wo0t, wo1t };
    const bf16* xinb = Hb;
    float* layer_out[2]  = { hA, hB };
    bf16* layer_outb[2]  = { hAb, hBb };

    for (int i = 0; i < 2; i++) {
        const size_t boff = (size_t)i * DD;

        // fused qkv: fp32 raw + bf16
        gemm_mma_kernel<<<dim3(12,32,1), 256, GEMM_SMEM>>>(
            xinb,512,0,0, wqkvT[i],512,0,0, qkv,1536,0,0, qkvb, 512,
            bqkv + (size_t)i*1536, nullptr,0,0,0, 1.f,0,0,nullptr);

        if (i == 0) {
            transpose_qkv_kernel<<<dim3(16,16,3), dim3(32,8)>>>(wq + DD*DD, wk + DD*DD, wv + DD*DD, wqkv1);
            transpose_w_kernel<<<dim3(16,16), dim3(32,8)>>>(wo + DD*DD, wo1t, 512, 512);
            transpose_w_kernel<<<dim3(32,2), dim3(32,8)>>>(w1, w1t, 64, 1024);
            transpose_w_kernel<<<dim3(32,32), dim3(32,8)>>>(w2, w2t, 1024, 1024);
            transpose_w_kernel<<<dim3(16,32), dim3(32,8)>>>(w3, w3t, 1024, 512);
        }

        // scores = q k^T / sqrt(D), K = 128 (head dim)
        gemm_mma_kernel<<<dim3(2,2,64), 256, GEMM_SMEM>>>(
            qkvb,1536,393216,128, qkvb+512,1536,393216,128,
            attp,256,262144,65536, nullptr, 128,
            nullptr, nullptr,0,0,0, scl,0,0,nullptr);
        softmax_kernel<<<64*SSQ/8, 256>>>();

        // o = q + att @ v : fp32 raw + bf16
        transpose_v_kernel<<<dim3(8,4,64), dim3(32,8)>>>();
        gemm_mma_kernel<<<dim3(1,2,64), 256, GEMM_SMEM>>>(
            attb,256,262144,65536, vtb,256,131072,32768,
            op,512,131072,128, ob, 256,
            nullptr, qkv,1536,393216,128, 1.f,0,0,nullptr);

        // out = o + relu(ob @ wo + bo) : fp32 raw + bf16
        gemm_mma_kernel<<<dim3(4,32,1), 256, GEMM_SMEM>>>(
            ob,512,0,0, woT[i],512,0,0, layer_out[i],512,0,0,
            layer_outb[i], 512, bo+boff, op,512,0,0, 1.f,1,0,nullptr);
        xinb = layer_outb[i];
    }

    // stats (precision-sensitive): fp32 SIMT on raw hB
    gemm_kernel<<<dim3(1, 32), 256>>>(hB, wz, st, NTOK, 128, DD, bz);

    z_kernel<<<512, 256>>>(eps);
    init_mu_kernel<<<dim3(BB, KCL), 64>>>(init_idx);
    zero_em_kernel<<<161, 256>>>();

    for (int it = 0; it < 5; it++) {
        em_step_kernel<<<dim3(40, BB), 256>>>(it & 1);
        em_fin_kernel<<<dim3(KCL, BB), 64>>>(it & 1);
    }

    // decoder: bf16 in, bf16 intermediates, fused loss on last
    gemm_mma_kernel<<<dim3(8,320,1), 256, GEMM_SMEM>>>(
        zb,64,0,0, w1t,64,0,0, nullptr,1024,0,0, d1b,
        64, b1, nullptr,0,0,0, 1.f,1,0,nullptr);
    gemm_mma_kernel<<<dim3(8,320,1), 256, GEMM_SMEM>>>(
        d1b,1024,0,0, w2t,1024,0,0, nullptr,1024,0,0, d2b,
        1024, b2, nullptr,0,0,0, 1.f,1,0,nullptr);
    gemm_mma_kernel<<<dim3(4,320,1), 256, GEMM_SMEM>>>(
        d2b,1024,0,0, w3t,1024,0,0, nullptr,512,0,0, nullptr,
        1024, b3, nullptr,0,0,0, 1.f,0,1,H);

    kl_kernel<<<dim3(40, BB), 256>>>();
    finalize_kernel<<<1, 1>>>((float*)d_out);
    (void)in_sizes; (void)n_in; (void)out_size;
}

// round 11
// speedup vs baseline: 3.9028x; 1.0630x over previous
#include <cuda_runtime.h>
#include <cuda_bf16.h>
#include <math.h>
#include <stdint.h>

#define BB   16
#define SSQ  256
#define DD   512
#define KCL  20
#define NTOK 4096
#define NZ   40960
#define NPB  2560
#define LOG_NORM_F (-0.91893853320467274178f)

typedef __nv_bfloat16 bf16;
typedef __nv_bfloat162 bf162;

// fp32 buffers
__device__ float g_qkv[NTOK*1536];
__device__ float g_o[NTOK*DD];
__device__ float g_hB[NTOK*DD];
__device__ float g_att[64*SSQ*SSQ];
__device__ float g_stats[NTOK*128];
__device__ float g_z[NZ*64];
__device__ float g_logqz[NZ];
__device__ float g_mu[BB*KCL*64];
__device__ float g_muacc[2*BB*KCL*64];
__device__ float g_m2[BB*KCL];
__device__ float g_logpi[BB*KCL];
__device__ float g_Nk[2*BB*KCL];
__device__ float g_bqkv[2*1536];
__device__ double g_rec;
__device__ double g_kl;
// bf16 GEMM operand buffers
__device__ bf16 g_Hb[NTOK*DD];
__device__ bf16 g_qkvb[NTOK*1536];
__device__ bf16 g_vtb[64*128*256];
__device__ bf16 g_ob[NTOK*DD];
__device__ bf16 g_hAb[NTOK*DD];
__device__ bf16 g_hBb[NTOK*DD];
__device__ bf16 g_attb[64*SSQ*SSQ];
__device__ bf16 g_zb[NZ*64];
__device__ bf16 g_wqkv0[1536*512];
__device__ bf16 g_wo0[512*512];
__device__ bf16 g_wqkv1[1536*512];
__device__ bf16 g_wo1[512*512];
__device__ bf16 g_w1t[1024*64];
__device__ bf16 g_w2t[1024*1024];
__device__ bf16 g_w3t[512*1024];
__device__ bf16 g_d1[41943040];
__device__ bf16 g_d2[41943040];

__device__ __forceinline__ float warpRedSum(float v){
#pragma unroll
    for (int o = 16; o > 0; o >>= 1) v += __shfl_xor_sync(0xffffffffu, v, o);
    return v;
}
__device__ __forceinline__ float warpRedMax(float v){
#pragma unroll
    for (int o = 16; o > 0; o >>= 1) v = fmaxf(v, __shfl_xor_sync(0xffffffffu, v, o));
    return v;
}
__device__ __forceinline__ uint32_t smem_u32(const void* p){
    uint32_t a;
    asm("{ .reg .u64 t; cvta.to.shared.u64 t, %1; cvt.u32.u64 %0, t; }" : "=r"(a) : "l"(p));
    return a;
}
__device__ __forceinline__ void ldsm4(uint32_t* r, uint32_t addr){
    asm volatile("ldmatrix.sync.aligned.m8n8.x4.shared.b16 {%0,%1,%2,%3}, [%4];"
        : "=r"(r[0]), "=r"(r[1]), "=r"(r[2]), "=r"(r[3]) : "r"(addr));
}
__device__ __forceinline__ void mma16(float* d, const uint32_t* a, const uint32_t* b){
    asm volatile(
        "mma.sync.aligned.m16n8k16.row.col.f32.bf16.bf16.f32 "
        "{%0,%1,%2,%3}, {%4,%5,%6,%7}, {%8,%9}, {%0,%1,%2,%3};"
        : "+f"(d[0]), "+f"(d[1]), "+f"(d[2]), "+f"(d[3])
        : "r"(a[0]), "r"(a[1]), "r"(a[2]), "r"(a[3]), "r"(b[0]), "r"(b[1]));
}
#define CP16(dst, src) \
    asm volatile("cp.async.cg.shared.global [%0], [%1], 16;" :: "r"(dst), "l"(src))
#define CP_COMMIT() asm volatile("cp.async.commit_group;" ::: "memory")

// =======================================================================
// BF16 tensor-core GEMM (see R10). c32lim: fp32 C written only for
// blocks with n0 < c32lim (block-uniform).
// =======================================================================
__global__ __launch_bounds__(256, 2) void gemm_mma_kernel(
    const bf16* __restrict__ A, int lda, long long sAb, long long sAh,
    const bf16* __restrict__ B, int ldb, long long sBb, long long sBh,
    float* __restrict__ C, int ldc, long long sCb, long long sCh,
    bf16* __restrict__ Cb, int c32lim,
    int K,
    const float* __restrict__ bias,
    const float* __restrict__ residual, int ldres, long long sRb, long long sRh,
    float scale, int doRelu, int lossMode,
    const float* __restrict__ lossH)
{
    extern __shared__ __align__(16) char smem[];
    const int tid = threadIdx.x;
    const int wid = tid >> 5, lane = tid & 31;

    const int zb = blockIdx.z >> 2, zh = blockIdx.z & 3;
    A += (long long)zb * sAb + (long long)zh * sAh;
    B += (long long)zb * sBb + (long long)zh * sBh;
    if (C)        C        += (long long)zb * sCb + (long long)zh * sCh;
    if (Cb)       Cb       += (long long)zb * sCb + (long long)zh * sCh;
    if (residual) residual += (long long)zb * sRb + (long long)zh * sRh;

    const int m0 = blockIdx.y * 128, n0 = blockIdx.x * 128;
    const bool wr32 = (C != nullptr) && (n0 < c32lim);
    const int kTiles = K >> 6;
    const uint32_t smem0 = smem_u32(smem);

    const int srow = tid & 127;
    const bool isB = (tid >= 128);
    const bf16* gsrc = isB ? (B + (size_t)(n0 + srow) * ldb)
                           : (A + (size_t)(m0 + srow) * lda);
    const uint32_t sdst0 = smem0 + (isB ? 16384 : 0) + srow * 128;
    const int rx = srow & 7;

    const int pstages = kTiles < 2 ? kTiles : 2;
    for (int c = 0; c < pstages; c++){
        const bf16* gs = gsrc + c * 64;
        const uint32_t sd = sdst0 + c * 32768;
#pragma unroll
        for (int j = 0; j < 8; j++)
            CP16(sd + ((j ^ rx) << 4), gs + j * 8);
        CP_COMMIT();
    }

    float acc[2][8][4];
#pragma unroll
    for (int i = 0; i < 2; i++)
#pragma unroll
        for (int j = 0; j < 8; j++)
#pragma unroll
            for (int q = 0; q < 4; q++) acc[i][j][q] = 0.f;

    const int wm = (wid & 3) * 32;
    const int wn = (wid >> 2) * 64;
    const int rr = lane & 7;
    const int qm = lane >> 3;
    const int qlow = qm & 1, qhigh = qm >> 1;
    uint32_t rowbaseA[2];
#pragma unroll
    for (int mt = 0; mt < 2; mt++)
        rowbaseA[mt] = (uint32_t)((wm + mt*16 + rr + 8*qlow) * 128);
    uint32_t rowbaseB[4];
#pragma unroll
    for (int p = 0; p < 4; p++)
        rowbaseB[p] = (uint32_t)(16384 + (wn + (2*p + qhigh)*8 + rr) * 128);

    for (int c = 0; c < kTiles; c++){
        if (c + 1 < kTiles) asm volatile("cp.async.wait_group 1;" ::: "memory");
        else                asm volatile("cp.async.wait_group 0;" ::: "memory");
        __syncthreads();

        if (c + 2 < kTiles){
            const bf16* gs = gsrc + (c + 2) * 64;
            const uint32_t sd = sdst0 + ((c + 2) % 3) * 32768;
#pragma unroll
            for (int j = 0; j < 8; j++)
                CP16(sd + ((j ^ rx) << 4), gs + j * 8);
            CP_COMMIT();
        }

        const uint32_t st = smem0 + (c % 3) * 32768;
#pragma unroll
        for (int t = 0; t < 4; t++){
            const uint32_t offA = (uint32_t)(((2*t + qhigh) ^ rr) << 4);
            const uint32_t offB = (uint32_t)(((2*t + qlow) ^ rr) << 4);
            uint32_t a[2][4], bb[4][4];
            ldsm4(a[0], st + rowbaseA[0] + offA);
            ldsm4(a[1], st + rowbaseA[1] + offA);
#pragma unroll
            for (int p = 0; p < 4; p++)
                ldsm4(bb[p], st + rowbaseB[p] + offB);
#pragma unroll
            for (int p = 0; p < 4; p++){
                mma16(acc[0][2*p+0], a[0], &bb[p][0]);
                mma16(acc[1][2*p+0], a[1], &bb[p][0]);
                mma16(acc[0][2*p+1], a[0], &bb[p][2]);
                mma16(acc[1][2*p+1], a[1], &bb[p][2]);
            }
        }
    }

    if (!lossMode){
#pragma unroll
        for (int mt = 0; mt < 2; mt++){
#pragma unroll
            for (int half = 0; half < 2; half++){
                int r = m0 + wm + mt*16 + (lane >> 2) + half*8;
                float* crow = wr32 ? (C + (size_t)r * ldc) : nullptr;
                bf16* crowb = Cb ? (Cb + (size_t)r * ldc) : nullptr;
                const float* rrow = residual ? (residual + (size_t)r * ldres) : nullptr;
#pragma unroll
                for (int nt = 0; nt < 8; nt++){
                    int col = n0 + wn + nt*8 + (lane & 3)*2;
                    float f0 = acc[mt][nt][half*2 + 0] * scale;
                    float f1 = acc[mt][nt][half*2 + 1] * scale;
                    if (bias){ f0 += bias[col]; f1 += bias[col + 1]; }
                    if (doRelu){ f0 = fmaxf(f0, 0.f); f1 = fmaxf(f1, 0.f); }
                    if (rrow){
                        float2 rv = *(const float2*)(rrow + col);
                        f0 += rv.x; f1 += rv.y;
                    }
                    if (crow)  *(float2*)(crow + col) = make_float2(f0, f1);
                    if (crowb) *(bf162*)(crowb + col) = __floats2bfloat162_rn(f0, f1);
                }
            }
        }
    } else {
        double lsum = 0.0;
#pragma unroll
        for (int mt = 0; mt < 2; mt++){
#pragma unroll
            for (int half = 0; half < 2; half++){
                int r = m0 + wm + mt*16 + (lane >> 2) + half*8;
                const float* hrow = lossH + (size_t)(r / 10) * 512;
#pragma unroll
                for (int nt = 0; nt < 8; nt++){
                    int col = n0 + wn + nt*8 + (lane & 3)*2;
                    float f0 = fmaxf(acc[mt][nt][half*2 + 0] + bias[col], 0.f);
                    float f1 = fmaxf(acc[mt][nt][half*2 + 1] + bias[col + 1], 0.f);
                    float d0 = f0 - hrow[col];
                    float d1 = f1 - hrow[col + 1];
                    lsum += (double)d0 * d0 + (double)d1 * d1;
                }
            }
        }
#pragma unroll
        for (int o = 16; o > 0; o >>= 1) lsum += __shfl_xor_sync(0xffffffffu, lsum, o);
        __shared__ double ds[8];
        if (lane == 0) ds[wid] = lsum;
        __syncthreads();
        if (tid == 0){
            double t = 0;
            for (int i = 0; i < 8; i++) t += ds[i];
            atomicAdd(&g_rec, t);
        }
    }
}

__global__ void transpose_w_kernel(const float* __restrict__ W,
                                   bf16* __restrict__ out, int K, int N)
{
    __shared__ float t[32][33];
    const int k0 = blockIdx.y * 32, n0 = blockIdx.x * 32;
    for (int i = threadIdx.y; i < 32; i += 8)
        t[i][threadIdx.x] = W[(size_t)(k0 + i) * N + n0 + threadIdx.x];
    __syncthreads();
    for (int i = threadIdx.y; i < 32; i += 8)
        out[(size_t)(n0 + i) * K + k0 + threadIdx.x] = __float2bfloat16(t[threadIdx.x][i]);
}

__global__ void transpose_qkv_kernel(const float* __restrict__ Wq,
                                     const float* __restrict__ Wk,
                                     const float* __restrict__ Wv,
                                     bf16* __restrict__ out)
{
    __shared__ float t[32][33];
    const float* W = blockIdx.z == 0 ? Wq : (blockIdx.z == 1 ? Wk : Wv);
    const int k0 = blockIdx.y * 32, n0 = blockIdx.x * 32;
    for (int i = threadIdx.y; i < 32; i += 8)
        t[i][threadIdx.x] = W[(size_t)(k0 + i) * 512 + n0 + threadIdx.x];
    __syncthreads();
    const int nout = blockIdx.z * 512 + n0;
    for (int i = threadIdx.y; i < 32; i += 8)
        out[(size_t)(nout + i) * 512 + k0 + threadIdx.x] = __float2bfloat16(t[threadIdx.x][i]);
}

__global__ void pack_bias_kernel(const float* __restrict__ bq,
                                 const float* __restrict__ bk,
                                 const float* __restrict__ bv)
{
    int i = blockIdx.x * 256 + threadIdx.x;
    if (i < 2*1536){
        int layer = i / 1536, col = i % 1536;
        const float* src = col < 512 ? bq : (col < 1024 ? bk : bv);
        g_bqkv[i] = src[layer*512 + (col & 511)];
    }
}

__global__ void transpose_v_kernel()
{
    __shared__ float t[32][33];
    const int bh = blockIdx.z, b = bh >> 2, h = bh & 3;
    const int k0 = blockIdx.x * 32;
    const int n0 = blockIdx.y * 32;
    for (int i = threadIdx.y; i < 32; i += 8)
        t[i][threadIdx.x] = __bfloat162float(
            g_qkvb[((size_t)b * 256 + k0 + i) * 1536 + 1024 + h * 128 + n0 + threadIdx.x]);
    __syncthreads();
    for (int i = threadIdx.y; i < 32; i += 8)
        g_vtb[((size_t)bh * 128 + n0 + i) * 256 + k0 + threadIdx.x] = __float2bfloat16(t[threadIdx.x][i]);
}

__global__ void round_h_kernel(const float* __restrict__ H)
{
    int i = blockIdx.x * 256 + threadIdx.x;
    float4 v = *(const float4*)(H + i * 4);
    *(bf162*)(g_Hb + i * 4)     = __floats2bfloat162_rn(v.x, v.y);
    *(bf162*)(g_Hb + i * 4 + 2) = __floats2bfloat162_rn(v.z, v.w);
}

__global__ __launch_bounds__(256, 2) void gemm_kernel(
    const float* __restrict__ A, const float* __restrict__ W,
    float* __restrict__ C, int M, int N, int K,
    const float* __restrict__ bias)
{
    __shared__ float As[8][132];
    __shared__ float Bs[8][128];
    const int tid = threadIdx.x;
    const int m0 = blockIdx.y * 128, n0 = blockIdx.x * 128;
    const int arow = tid >> 1;
    const int aq   = (tid & 1) << 2;
    const int brow = tid >> 5;
    const int bcol = (tid & 31) << 2;
    const float* Ap = A + (size_t)(m0 + arow) * K + aq;
    const float* Wp = W + (size_t)brow * N + n0 + bcol;
    const int tx = tid & 15, ty = tid >> 4;

    float acc[8][8];
#pragma unroll
    for (int i = 0; i < 8; i++)
#pragma unroll
        for (int j = 0; j < 8; j++) acc[i][j] = 0.f;

    for (int k0 = 0; k0 < K; k0 += 8) {
        float4 av = *(const float4*)(Ap + k0);
        float4 bv = *(const float4*)(Wp + (size_t)k0 * N);
        As[aq+0][arow] = av.x; As[aq+1][arow] = av.y;
        As[aq+2][arow] = av.z; As[aq+3][arow] = av.w;
        *(float4*)&Bs[brow][bcol] = bv;
        __syncthreads();
#pragma unroll
        for (int kk = 0; kk < 8; kk++) {
            float fa[8], fb[8];
            *(float4*)&fa[0] = *(const float4*)&As[kk][ty*8];
            *(float4*)&fa[4] = *(const float4*)&As[kk][ty*8+4];
            *(float4*)&fb[0] = *(const float4*)&Bs[kk][tx*8];
            *(float4*)&fb[4] = *(const float4*)&Bs[kk][tx*8+4];
#pragma unroll
            for (int i = 0; i < 8; i++)
#pragma unroll
                for (int j = 0; j < 8; j++)
                    acc[i][j] = fmaf(fa[i], fb[j], acc[i][j]);
        }
        __syncthreads();
    }

    float bl[8];
#pragma unroll
    for (int j = 0; j < 8; j++) bl[j] = bias ? bias[n0 + tx*8 + j] : 0.f;
#pragma unroll
    for (int i = 0; i < 8; i++) {
        int m = m0 + ty*8 + i;
        float* cp = C + (size_t)m * N + n0 + tx*8;
        *(float4*)cp     = make_float4(acc[i][0]+bl[0], acc[i][1]+bl[1], acc[i][2]+bl[2], acc[i][3]+bl[3]);
        *(float4*)(cp+4) = make_float4(acc[i][4]+bl[4], acc[i][5]+bl[5], acc[i][6]+bl[6], acc[i][7]+bl[7]);
    }
}

__global__ __launch_bounds__(256) void softmax_kernel()
{
    const int lane = threadIdx.x & 31;
    const int row = blockIdx.x * 8 + (threadIdx.x >> 5);
    const float* p = g_att + (size_t)row * SSQ;
    bf16* po = g_attb + (size_t)row * SSQ;
    float v[8];
    float mx = -1e30f;
#pragma unroll
    for (int j = 0; j < 8; j++){
        v[j] = p[lane + 32*j];
        mx = fmaxf(mx, v[j]);
    }
    mx = warpRedMax(mx);
    float s = 0.f;
#pragma unroll
    for (int j = 0; j < 8; j++){
        v[j] = expf(v[j] - mx);
        s += v[j];
    }
    s = warpRedSum(s);
#pragma unroll
    for (int j = 0; j < 8; j++)
        po[lane + 32*j] = __float2bfloat16(v[j] / s);
}

__global__ __launch_bounds__(256) void z_kernel(const float* __restrict__ eps)
{
    const int lane = threadIdx.x & 31;
    const int bs = blockIdx.x * 8 + (threadIdx.x >> 5);
    const float mean0 = g_stats[(size_t)bs*128 + lane];
    const float mean1 = g_stats[(size_t)bs*128 + 32 + lane];
    const float lv0   = g_stats[(size_t)bs*128 + 64 + lane];
    const float lv1   = g_stats[(size_t)bs*128 + 96 + lane];
    const float sd0 = expf(0.5f * lv0), sd1 = expf(0.5f * lv1);
    const float lvs = lv0 + lv1;
    for (int m = 0; m < 10; m++) {
        size_t off = ((size_t)bs*10 + m)*64;
        float e0 = eps[off + lane], e1 = eps[off + 32 + lane];
        float z0 = mean0 + e0 * sd0, z1 = mean1 + e1 * sd1;
        g_z[off + lane] = z0;        g_z[off + 32 + lane] = z1;
        g_zb[off + lane] = __float2bfloat16(z0);
        g_zb[off + 32 + lane] = __float2bfloat16(z1);
        float qv = warpRedSum(lvs + e0*e0 + e1*e1);
        if (lane == 0) g_logqz[(size_t)bs*10 + m] = -0.5f*qv + 64.f*LOG_NORM_F;
    }
}

__global__ void init_mu_kernel(const int* __restrict__ idx)
{
    const int b = blockIdx.x, k = blockIdx.y, l = threadIdx.x;
    const int lane = l & 31, w = l >> 5;
    const int n = idx[b*KCL + k];
    float v = g_z[((size_t)b*NPB + n)*64 + l];
    g_mu[((size_t)b*KCL + k)*64 + l] = v;
    float s = warpRedSum(v*v);
    __shared__ float sm[2];
    if (lane == 0) sm[w] = s;
    __syncthreads();
    if (l == 0) {
        g_m2[b*KCL + k] = sm[0] + sm[1];
        g_logpi[b*KCL + k] = -2.9957322735539909f;
    }
}

__global__ void zero_em_kernel()
{
    int i = blockIdx.x * 256 + threadIdx.x;
    if (i < 2*BB*KCL) g_Nk[i] = 0.f;
    if (i < 2*BB*KCL*64) g_muacc[i] = 0.f;
}

__global__ __launch_bounds__(256) void em_step_kernel(int parity)
{
    const int b = blockIdx.y;
    const int tid = threadIdx.x, lane = tid & 31, w = tid >> 5;
    __shared__ float mus[KCL*64];
    __shared__ float sc[KCL];
    __shared__ float nkacc[KCL];
    __shared__ float zt[64*65];
    __shared__ float pt[64*21];

    const int n0 = blockIdx.x * 64;
    for (int i = tid; i < KCL*64; i += 256) mus[i] = g_mu[(size_t)b*KCL*64 + i];
    if (tid < KCL) { sc[tid] = -0.5f*g_m2[b*KCL+tid] + g_logpi[b*KCL+tid]; nkacc[tid] = 0.f; }
    for (int i = tid; i < 64*64; i += 256)
        zt[(i >> 6)*65 + (i & 63)] = g_z[((size_t)b*NPB + n0)*64 + i];

    {
        const int op = parity ^ 1;
        if (tid < 32)
            g_muacc[((size_t)op*BB + b)*KCL*64 + blockIdx.x*32 + tid] = 0.f;
        if (blockIdx.x == 0 && tid < KCL)
            g_Nk[(op*BB + b)*KCL + tid] = 0.f;
    }
    __syncthreads();

    float nkloc = 0.f;
    const int nb = w * 8;
    for (int t = 0; t < 8; t++) {
        const int n = nb + t;
        float z0 = zt[n*65 + lane], z1 = zt[n*65 + 32 + lane];
        float mx = -1e30f, s = 0.f, myll = 0.f;
#pragma unroll
        for (int k2 = 0; k2 < KCL; k2++) {
            float p = z0*mus[k2*64+lane] + z1*mus[k2*64+32+lane];
            p = warpRedSum(p) + sc[k2];
            if (lane == k2) myll = p;
            float nm = fmaxf(mx, p);
            s = s*expf(mx - nm) + expf(p - nm);
            mx = nm;
        }
        if (lane < KCL) {
            float pk = expf(myll - mx) / s;
            pt[n*21 + lane] = pk;
            nkloc += pk;
        }
    }
    if (lane < KCL) atomicAdd(&nkacc[lane], nkloc);
    __syncthreads();

    {
        const int l = tid & 63, kq = tid >> 6;
        float a0=0.f, a1=0.f, a2=0.f, a3=0.f, a4=0.f;
#pragma unroll 4
        for (int nn = 0; nn < 64; nn++){
            float zv = zt[nn*65 + l];
            const float* pr = pt + nn*21 + kq*5;
            a0 = fmaf(pr[0], zv, a0);
            a1 = fmaf(pr[1], zv, a1);
            a2 = fmaf(pr[2], zv, a2);
            a3 = fmaf(pr[3], zv, a3);
            a4 = fmaf(pr[4], zv, a4);
        }
        float* dst = g_muacc + (((size_t)parity*BB + b)*KCL + kq*5)*64 + l;
        atomicAdd(dst,       a0);
        atomicAdd(dst + 64,  a1);
        atomicAdd(dst + 128, a2);
        atomicAdd(dst + 192, a3);
        atomicAdd(dst + 256, a4);
    }
    if (tid < KCL) atomicAdd(&g_Nk[(parity*BB + b)*KCL + tid], nkacc[tid]);
}

__global__ void em_fin_kernel(int parity)
{
    const int k = blockIdx.x, b = blockIdx.y, l = threadIdx.x;
    const int lane = l & 31, w = l >> 5;
    const float* Nk = g_Nk + (parity*BB + b)*KCL;
    float nk = Nk[k];
    float m = g_muacc[(((size_t)parity*BB + b)*KCL + k)*64 + l] / nk;
    g_mu[((size_t)b*KCL + k)*64 + l] = m;
    float s = warpRedSum(m*m);
    __shared__ float sm[2];
    if (lane == 0) sm[w] = s;
    __syncthreads();
    if (l == 0) {
        g_m2[b*KCL + k] = sm[0] + sm[1];
        float tot = 0.f;
        for (int j = 0; j < KCL; j++) tot += Nk[j];
        g_logpi[b*KCL + k] = logf(nk / tot);
    }
}

__global__ __launch_bounds__(256) void kl_kernel()
{
    const int b = blockIdx.y;
    const int tid = threadIdx.x, lane = tid & 31, w = tid >> 5;
    __shared__ float mus[KCL*64];
    __shared__ float sc[KCL];
    for (int i = tid; i < KCL*64; i += 256) mus[i] = g_mu[(size_t)b*KCL*64 + i];
    if (tid < KCL) sc[tid] = -0.5f*g_m2[b*KCL+tid] + g_logpi[b*KCL+tid];
    __syncthreads();

    double loc = 0.0;
    const int nbase = blockIdx.x*64 + w*8;
    for (int t = 0; t < 8; t++) {
        int n = nbase + t;
        const float* zp = g_z + ((size_t)b*NPB + n)*64;
        float z0 = zp[lane], z1 = zp[lane+32];
        float sq = warpRedSum(z0*z0 + z1*z1);
        float mx = -1e30f, s = 0.f;
#pragma unroll
        for (int k2 = 0; k2 < KCL; k2++) {
            float p = z0*mus[k2*64+lane] + z1*mus[k2*64+32+lane];
            p = warpRedSum(p) + sc[k2];
            float nm = fmaxf(mx, p);
            s = s*expf(mx - nm) + expf(p - nm);
            mx = nm;
        }
        float lpz = mx + logf(s) - 0.5f*sq + 64.f*LOG_NORM_F;
        if (lane == 0) loc += (double)(g_logqz[(size_t)b*NPB + n] - lpz);
    }
    __shared__ double dacc[8];
    if (lane == 0) dacc[w] = loc;
    __syncthreads();
    if (tid == 0) {
        double t = 0;
        for (int i = 0; i < 8; i++) t += dacc[i];
        atomicAdd(&g_kl, t);
    }
}

__global__ void zero_accum_kernel() { g_rec = 0.0; g_kl = 0.0; }

__global__ void finalize_kernel(float* __restrict__ out)
{
    out[0] = (float)(g_rec / 40960.0);
    out[1] = (float)(g_kl / 40960.0);
}

static void* symaddr(const void* s)
{
    void* p = nullptr;
    cudaGetSymbolAddress(&p, s);
    return p;
}

#define GEMM_SMEM 98304
#define BIG32 (1 << 30)

extern "C" void kernel_launch(void* const* d_in, const int* in_sizes, int n_in,
                              void* d_out, int out_size)
{
    const float *H, *eps, *wq, *bq, *wk, *bk, *wv, *bv, *wo, *bo, *wz, *bz;
    const float *w1, *b1, *w2, *b2, *w3, *b3;
    const int* init_idx;

    if (n_in >= 3 && in_sizes[2] == 320) {
        H = (const float*)d_in[0];  eps = (const float*)d_in[1]; init_idx = (const int*)d_in[2];
        wq = (const float*)d_in[3]; bq = (const float*)d_in[4];
        wk = (const float*)d_in[5]; bk = (const float*)d_in[6];
        wv = (const float*)d_in[7]; bv = (const float*)d_in[8];
        wo = (const float*)d_in[9]; bo = (const float*)d_in[10];
        wz = (const float*)d_in[11]; bz = (const float*)d_in[12];
        w1 = (const float*)d_in[13]; b1 = (const float*)d_in[14];
        w2 = (const float*)d_in[15]; b2 = (const float*)d_in[16];
        w3 = (const float*)d_in[17]; b3 = (const float*)d_in[18];
    } else {
        H = (const float*)d_in[0];  eps = (const float*)d_in[1];
        wq = (const float*)d_in[2]; bq = (const float*)d_in[3];
        wk = (const float*)d_in[4]; bk = (const float*)d_in[5];
        wv = (const float*)d_in[6]; bv = (const float*)d_in[7];
        wo = (const float*)d_in[8]; bo = (const float*)d_in[9];
        wz = (const float*)d_in[10]; bz = (const float*)d_in[11];
        w1 = (const float*)d_in[12]; b1 = (const float*)d_in[13];
        w2 = (const float*)d_in[14]; b2 = (const float*)d_in[15];
        w3 = (const float*)d_in[16]; b3 = (const float*)d_in[17];
        init_idx = (const int*)d_in[18];
    }

    cudaFuncSetAttribute(gemm_mma_kernel,
                         cudaFuncAttributeMaxDynamicSharedMemorySize, GEMM_SMEM);

    // persistent side stream + events for the captured fork (created once;
    // host-side resources only — every call enqueues the identical work)
    static cudaStream_t s2 = nullptr;
    static cudaEvent_t evFork = nullptr, evJoin = nullptr;
    if (s2 == nullptr) {
        cudaStreamCreateWithFlags(&s2, cudaStreamNonBlocking);
        cudaEventCreateWithFlags(&evFork, cudaEventDisableTiming);
        cudaEventCreateWithFlags(&evJoin, cudaEventDisableTiming);
    }

    bf16* Hb    = (bf16*)symaddr(g_Hb);
    float* qkv  = (float*)symaddr(g_qkv);
    bf16* qkvb  = (bf16*)symaddr(g_qkvb);
    float* op   = (float*)symaddr(g_o);
    bf16* ob    = (bf16*)symaddr(g_ob);
    bf16* hAb   = (bf16*)symaddr(g_hAb);
    float* hB   = (float*)symaddr(g_hB);
    bf16* hBb   = (bf16*)symaddr(g_hBb);
    float* attp = (float*)symaddr(g_att);
    bf16* attb  = (bf16*)symaddr(g_attb);
    float* st   = (float*)symaddr(g_stats);
    bf16* zbp   = (bf16*)symaddr(g_zb);
    bf16* vtb   = (bf16*)symaddr(g_vtb);
    bf16* wqkv0 = (bf16*)symaddr(g_wqkv0);
    bf16* wo0t  = (bf16*)symaddr(g_wo0);
    bf16* wqkv1 = (bf16*)symaddr(g_wqkv1);
    bf16* wo1t  = (bf16*)symaddr(g_wo1);
    bf16* w1t   = (bf16*)symaddr(g_w1t);
    bf16* w2t   = (bf16*)symaddr(g_w2t);
    bf16* w3t   = (bf16*)symaddr(g_w3t);
    float* bqkv = (float*)symaddr(g_bqkv);
    bf16* d1b   = (bf16*)symaddr(g_d1);
    bf16* d2b   = (bf16*)symaddr(g_d2);

    zero_accum_kernel<<<1, 1>>>();
    round_h_kernel<<<2048, 256>>>(H);
    pack_bias_kernel<<<12, 256>>>(bq, bk, bv);
    transpose_qkv_kernel<<<dim3(16,16,3), dim3(32,8)>>>(wq, wk, wv, wqkv0);
    transpose_w_kernel<<<dim3(16,16), dim3(32,8)>>>(wo, wo0t, 512, 512);

    const float scl = 0.044194173824159216f;
    bf16* wqkvT[2] = { wqkv0, wqkv1 };
    bf16* woT[2]   = { wo0t, wo1t };
    const bf16* xinb = Hb;
    float* layer_out[2]  = { nullptr, hB };     // hA fp32 is dead
    bf16* layer_outb[2]  = { hAb, hBb };

    for (int i = 0; i < 2; i++) {
        const size_t boff = (size_t)i * DD;

        // fused qkv: fp32 written only for q columns (residual)
        gemm_mma_kernel<<<dim3(12,32,1), 256, GEMM_SMEM>>>(
            xinb,512,0,0, wqkvT[i],512,0,0, qkv,1536,0,0, qkvb, 512, 512,
            bqkv + (size_t)i*1536, nullptr,0,0,0, 1.f,0,0,nullptr);

        if (i == 0) {
            transpose_qkv_kernel<<<dim3(16,16,3), dim3(32,8)>>>(wq + DD*DD, wk + DD*DD, wv + DD*DD, wqkv1);
            transpose_w_kernel<<<dim3(16,16), dim3(32,8)>>>(wo + DD*DD, wo1t, 512, 512);
            transpose_w_kernel<<<dim3(32,2), dim3(32,8)>>>(w1, w1t, 64, 1024);
            transpose_w_kernel<<<dim3(32,32), dim3(32,8)>>>(w2, w2t, 1024, 1024);
            transpose_w_kernel<<<dim3(16,32), dim3(32,8)>>>(w3, w3t, 1024, 512);
        }

        // scores = q k^T / sqrt(D), K = 128 (head dim)
        gemm_mma_kernel<<<dim3(2,2,64), 256, GEMM_SMEM>>>(
            qkvb,1536,393216,128, qkvb+512,1536,393216,128,
            attp,256,262144,65536, nullptr, BIG32, 128,
            nullptr, nullptr,0,0,0, scl,0,0,nullptr);
        softmax_kernel<<<64*SSQ/8, 256>>>();

        // o = q + att @ v : fp32 raw + bf16
        transpose_v_kernel<<<dim3(8,4,64), dim3(32,8)>>>();
        gemm_mma_kernel<<<dim3(1,2,64), 256, GEMM_SMEM>>>(
            attb,256,262144,65536, vtb,256,131072,32768,
            op,512,131072,128, ob, BIG32, 256,
            nullptr, qkv,1536,393216,128, 1.f,0,0,nullptr);

        // out = o + relu(ob @ wo + bo) : fp32 (only layer 1 / stats) + bf16
        gemm_mma_kernel<<<dim3(4,32,1), 256, GEMM_SMEM>>>(
            ob,512,0,0, woT[i],512,0,0, layer_out[i],512,0,0,
            layer_outb[i], BIG32, 512, bo+boff, op,512,0,0, 1.f,1,0,nullptr);
        xinb = layer_outb[i];
    }

    // stats (precision-sensitive): fp32 SIMT on raw hB
    gemm_kernel<<<dim3(1, 32), 256>>>(hB, wz, st, NTOK, 128, DD, bz);
    z_kernel<<<512, 256>>>(eps);

    // ---- fork: EM + KL on s2, decoder on default stream ----
    cudaEventRecord(evFork, 0);
    cudaStreamWaitEvent(s2, evFork, 0);

    init_mu_kernel<<<dim3(BB, KCL), 64, 0, s2>>>(init_idx);
    zero_em_kernel<<<161, 256, 0, s2>>>();
    for (int it = 0; it < 5; it++) {
        em_step_kernel<<<dim3(40, BB), 256, 0, s2>>>(it & 1);
        em_fin_kernel<<<dim3(KCL, BB), 64, 0, s2>>>(it & 1);
    }
    kl_kernel<<<dim3(40, BB), 256, 0, s2>>>();
    cudaEventRecord(evJoin, s2);

    // decoder on default stream (independent of EM)
    gemm_mma_kernel<<<dim3(8,320,1), 256, GEMM_SMEM>>>(
        zbp,64,0,0, w1t,64,0,0, nullptr,1024,0,0, d1b, BIG32,
        64, b1, nullptr,0,0,0, 1.f,1,0,nullptr);
    gemm_mma_kernel<<<dim3(8,320,1), 256, GEMM_SMEM>>>(
        d1b,1024,0,0, w2t,1024,0,0, nullptr,1024,0,0, d2b, BIG32,
        1024, b2, nullptr,0,0,0, 1.f,1,0,nullptr);
    gemm_mma_kernel<<<dim3(4,320,1), 256, GEMM_SMEM>>>(
        d2b,1024,0,0, w3t,1024,0,0, nullptr,512,0,0, nullptr, BIG32,
        1024, b3, nullptr,0,0,0, 1.f,0,1,H);

    // join and finalize
    cudaStreamWaitEvent(0, evJoin, 0);
    finalize_kernel<<<1, 1>>>((float*)d_out);
    (void)in_sizes; (void)n_in; (void)out_size;
}

// round 13
// speedup vs baseline: 3.9855x; 1.0212x over previous
#include <cuda_runtime.h>
#include <cuda_bf16.h>
#include <math.h>
#include <stdint.h>

#define BB   16
#define SSQ  256
#define DD   512
#define KCL  20
#define NTOK 4096
#define NZ   40960
#define NPB  2560
#define LOG_NORM_F (-0.91893853320467274178f)

typedef __nv_bfloat16 bf16;
typedef __nv_bfloat162 bf162;

// fp32 buffers
__device__ float g_qkv[NTOK*1536];
__device__ float g_o[NTOK*DD];
__device__ float g_hB[NTOK*DD];
__device__ float g_att[64*SSQ*SSQ];
__device__ float g_stats[NTOK*128];
__device__ float g_z[NZ*64];
__device__ float g_logqz[NZ];
__device__ float g_mu[BB*KCL*64];
__device__ float g_muacc[2*BB*KCL*64];
__device__ float g_m2[BB*KCL];
__device__ float g_logpi[BB*KCL];
__device__ float g_Nk[2*BB*KCL];
__device__ float g_bqkv[2*1536];
__device__ double g_rec;
__device__ double g_kl;
// bf16 GEMM operand buffers
__device__ bf16 g_Hb[NTOK*DD];
__device__ bf16 g_qkvb[NTOK*1536];
__device__ bf16 g_vtb[64*128*256];
__device__ bf16 g_ob[NTOK*DD];
__device__ bf16 g_hAb[NTOK*DD];
__device__ bf16 g_attb[64*SSQ*SSQ];
__device__ bf16 g_zb[NZ*64];
__device__ bf16 g_wqkv0[1536*512];
__device__ bf16 g_wo0[512*512];
__device__ bf16 g_wqkv1[1536*512];
__device__ bf16 g_wo1[512*512];
__device__ bf16 g_w1t[1024*64];
__device__ bf16 g_w2t[1024*1024];
__device__ bf16 g_w3t[512*1024];
__device__ bf16 g_d1[41943040];
__device__ bf16 g_d2[41943040];

__device__ __forceinline__ float warpRedSum(float v){
#pragma unroll
    for (int o = 16; o > 0; o >>= 1) v += __shfl_xor_sync(0xffffffffu, v, o);
    return v;
}
__device__ __forceinline__ float warpRedMax(float v){
#pragma unroll
    for (int o = 16; o > 0; o >>= 1) v = fmaxf(v, __shfl_xor_sync(0xffffffffu, v, o));
    return v;
}
__device__ __forceinline__ uint32_t smem_u32(const void* p){
    uint32_t a;
    asm("{ .reg .u64 t; cvta.to.shared.u64 t, %1; cvt.u32.u64 %0, t; }" : "=r"(a) : "l"(p));
    return a;
}
__device__ __forceinline__ void ldsm4(uint32_t* r, uint32_t addr){
    asm volatile("ldmatrix.sync.aligned.m8n8.x4.shared.b16 {%0,%1,%2,%3}, [%4];"
        : "=r"(r[0]), "=r"(r[1]), "=r"(r[2]), "=r"(r[3]) : "r"(addr));
}
__device__ __forceinline__ void mma16(float* d, const uint32_t* a, const uint32_t* b){
    asm volatile(
        "mma.sync.aligned.m16n8k16.row.col.f32.bf16.bf16.f32 "
        "{%0,%1,%2,%3}, {%4,%5,%6,%7}, {%8,%9}, {%0,%1,%2,%3};"
        : "+f"(d[0]), "+f"(d[1]), "+f"(d[2]), "+f"(d[3])
        : "r"(a[0]), "r"(a[1]), "r"(a[2]), "r"(a[3]), "r"(b[0]), "r"(b[1]));
}
#define CP16(dst, src) \
    asm volatile("cp.async.cg.shared.global [%0], [%1], 16;" :: "r"(dst), "l"(src))
#define CP_COMMIT() asm volatile("cp.async.commit_group;" ::: "memory")

// =======================================================================
// BF16 tensor-core GEMM (see R10/R11).
// =======================================================================
__global__ __launch_bounds__(256, 2) void gemm_mma_kernel(
    const bf16* __restrict__ A, int lda, long long sAb, long long sAh,
    const bf16* __restrict__ B, int ldb, long long sBb, long long sBh,
    float* __restrict__ C, int ldc, long long sCb, long long sCh,
    bf16* __restrict__ Cb, int c32lim,
    int K,
    const float* __restrict__ bias,
    const float* __restrict__ residual, int ldres, long long sRb, long long sRh,
    float scale, int doRelu, int lossMode,
    const float* __restrict__ lossH)
{
    extern __shared__ __align__(16) char smem[];
    const int tid = threadIdx.x;
    const int wid = tid >> 5, lane = tid & 31;

    const int zb = blockIdx.z >> 2, zh = blockIdx.z & 3;
    A += (long long)zb * sAb + (long long)zh * sAh;
    B += (long long)zb * sBb + (long long)zh * sBh;
    if (C)        C        += (long long)zb * sCb + (long long)zh * sCh;
    if (Cb)       Cb       += (long long)zb * sCb + (long long)zh * sCh;
    if (residual) residual += (long long)zb * sRb + (long long)zh * sRh;

    const int m0 = blockIdx.y * 128, n0 = blockIdx.x * 128;
    const bool wr32 = (C != nullptr) && (n0 < c32lim);
    const int kTiles = K >> 6;
    const uint32_t smem0 = smem_u32(smem);

    const int srow = tid & 127;
    const bool isB = (tid >= 128);
    const bf16* gsrc = isB ? (B + (size_t)(n0 + srow) * ldb)
                           : (A + (size_t)(m0 + srow) * lda);
    const uint32_t sdst0 = smem0 + (isB ? 16384 : 0) + srow * 128;
    const int rx = srow & 7;

    const int pstages = kTiles < 2 ? kTiles : 2;
    for (int c = 0; c < pstages; c++){
        const bf16* gs = gsrc + c * 64;
        const uint32_t sd = sdst0 + c * 32768;
#pragma unroll
        for (int j = 0; j < 8; j++)
            CP16(sd + ((j ^ rx) << 4), gs + j * 8);
        CP_COMMIT();
    }

    float acc[2][8][4];
#pragma unroll
    for (int i = 0; i < 2; i++)
#pragma unroll
        for (int j = 0; j < 8; j++)
#pragma unroll
            for (int q = 0; q < 4; q++) acc[i][j][q] = 0.f;

    const int wm = (wid & 3) * 32;
    const int wn = (wid >> 2) * 64;
    const int rr = lane & 7;
    const int qm = lane >> 3;
    const int qlow = qm & 1, qhigh = qm >> 1;
    uint32_t rowbaseA[2];
#pragma unroll
    for (int mt = 0; mt < 2; mt++)
        rowbaseA[mt] = (uint32_t)((wm + mt*16 + rr + 8*qlow) * 128);
    uint32_t rowbaseB[4];
#pragma unroll
    for (int p = 0; p < 4; p++)
        rowbaseB[p] = (uint32_t)(16384 + (wn + (2*p + qhigh)*8 + rr) * 128);

    for (int c = 0; c < kTiles; c++){
        if (c + 1 < kTiles) asm volatile("cp.async.wait_group 1;" ::: "memory");
        else                asm volatile("cp.async.wait_group 0;" ::: "memory");
        __syncthreads();

        if (c + 2 < kTiles){
            const bf16* gs = gsrc + (c + 2) * 64;
            const uint32_t sd = sdst0 + ((c + 2) % 3) * 32768;
#pragma unroll
            for (int j = 0; j < 8; j++)
                CP16(sd + ((j ^ rx) << 4), gs + j * 8);
            CP_COMMIT();
        }

        const uint32_t st = smem0 + (c % 3) * 32768;
#pragma unroll
        for (int t = 0; t < 4; t++){
            const uint32_t offA = (uint32_t)(((2*t + qhigh) ^ rr) << 4);
            const uint32_t offB = (uint32_t)(((2*t + qlow) ^ rr) << 4);
            uint32_t a[2][4], bb[4][4];
            ldsm4(a[0], st + rowbaseA[0] + offA);
            ldsm4(a[1], st + rowbaseA[1] + offA);
#pragma unroll
            for (int p = 0; p < 4; p++)
                ldsm4(bb[p], st + rowbaseB[p] + offB);
#pragma unroll
            for (int p = 0; p < 4; p++){
                mma16(acc[0][2*p+0], a[0], &bb[p][0]);
                mma16(acc[1][2*p+0], a[1], &bb[p][0]);
                mma16(acc[0][2*p+1], a[0], &bb[p][2]);
                mma16(acc[1][2*p+1], a[1], &bb[p][2]);
            }
        }
    }

    if (!lossMode){
#pragma unroll
        for (int mt = 0; mt < 2; mt++){
#pragma unroll
            for (int half = 0; half < 2; half++){
                int r = m0 + wm + mt*16 + (lane >> 2) + half*8;
                float* crow = wr32 ? (C + (size_t)r * ldc) : nullptr;
                bf16* crowb = Cb ? (Cb + (size_t)r * ldc) : nullptr;
                const float* rrow = residual ? (residual + (size_t)r * ldres) : nullptr;
#pragma unroll
                for (int nt = 0; nt < 8; nt++){
                    int col = n0 + wn + nt*8 + (lane & 3)*2;
                    float f0 = acc[mt][nt][half*2 + 0] * scale;
                    float f1 = acc[mt][nt][half*2 + 1] * scale;
                    if (bias){ f0 += bias[col]; f1 += bias[col + 1]; }
                    if (doRelu){ f0 = fmaxf(f0, 0.f); f1 = fmaxf(f1, 0.f); }
                    if (rrow){
                        float2 rv = *(const float2*)(rrow + col);
                        f0 += rv.x; f1 += rv.y;
                    }
                    if (crow)  *(float2*)(crow + col) = make_float2(f0, f1);
                    if (crowb) *(bf162*)(crowb + col) = __floats2bfloat162_rn(f0, f1);
                }
            }
        }
    } else {
        double lsum = 0.0;
#pragma unroll
        for (int mt = 0; mt < 2; mt++){
#pragma unroll
            for (int half = 0; half < 2; half++){
                int r = m0 + wm + mt*16 + (lane >> 2) + half*8;
                const float* hrow = lossH + (size_t)(r / 10) * 512;
#pragma unroll
                for (int nt = 0; nt < 8; nt++){
                    int col = n0 + wn + nt*8 + (lane & 3)*2;
                    float f0 = fmaxf(acc[mt][nt][half*2 + 0] + bias[col], 0.f);
                    float f1 = fmaxf(acc[mt][nt][half*2 + 1] + bias[col + 1], 0.f);
                    float d0 = f0 - hrow[col];
                    float d1 = f1 - hrow[col + 1];
                    lsum += (double)d0 * d0 + (double)d1 * d1;
                }
            }
        }
#pragma unroll
        for (int o = 16; o > 0; o >>= 1) lsum += __shfl_xor_sync(0xffffffffu, lsum, o);
        __shared__ double ds[8];
        if (lane == 0) ds[wid] = lsum;
        __syncthreads();
        if (tid == 0){
            double t = 0;
            for (int i = 0; i < 8; i++) t += ds[i];
            atomicAdd(&g_rec, t);
        }
    }
}

__global__ void transpose_w_kernel(const float* __restrict__ W,
                                   bf16* __restrict__ out, int K, int N)
{
    __shared__ float t[32][33];
    const int k0 = blockIdx.y * 32, n0 = blockIdx.x * 32;
    for (int i = threadIdx.y; i < 32; i += 8)
        t[i][threadIdx.x] = W[(size_t)(k0 + i) * N + n0 + threadIdx.x];
    __syncthreads();
    for (int i = threadIdx.y; i < 32; i += 8)
        out[(size_t)(n0 + i) * K + k0 + threadIdx.x] = __float2bfloat16(t[threadIdx.x][i]);
}

__global__ void transpose_qkv_kernel(const float* __restrict__ Wq,
                                     const float* __restrict__ Wk,
                                     const float* __restrict__ Wv,
                                     bf16* __restrict__ out)
{
    __shared__ float t[32][33];
    const float* W = blockIdx.z == 0 ? Wq : (blockIdx.z == 1 ? Wk : Wv);
    const int k0 = blockIdx.y * 32, n0 = blockIdx.x * 32;
    for (int i = threadIdx.y; i < 32; i += 8)
        t[i][threadIdx.x] = W[(size_t)(k0 + i) * 512 + n0 + threadIdx.x];
    __syncthreads();
    const int nout = blockIdx.z * 512 + n0;
    for (int i = threadIdx.y; i < 32; i += 8)
        out[(size_t)(nout + i) * 512 + k0 + threadIdx.x] = __float2bfloat16(t[threadIdx.x][i]);
}

__global__ void pack_bias_kernel(const float* __restrict__ bq,
                                 const float* __restrict__ bk,
                                 const float* __restrict__ bv)
{
    int i = blockIdx.x * 256 + threadIdx.x;
    if (i < 2*1536){
        int layer = i / 1536, col = i % 1536;
        const float* src = col < 512 ? bq : (col < 1024 ? bk : bv);
        g_bqkv[i] = src[layer*512 + (col & 511)];
    }
}

__global__ void transpose_v_kernel()
{
    __shared__ float t[32][33];
    const int bh = blockIdx.z, b = bh >> 2, h = bh & 3;
    const int k0 = blockIdx.x * 32;
    const int n0 = blockIdx.y * 32;
    for (int i = threadIdx.y; i < 32; i += 8)
        t[i][threadIdx.x] = __bfloat162float(
            g_qkvb[((size_t)b * 256 + k0 + i) * 1536 + 1024 + h * 128 + n0 + threadIdx.x]);
    __syncthreads();
    for (int i = threadIdx.y; i < 32; i += 8)
        g_vtb[((size_t)bh * 128 + n0 + i) * 256 + k0 + threadIdx.x] = __float2bfloat16(t[threadIdx.x][i]);
}

__global__ void round_h_kernel(const float* __restrict__ H)
{
    int i = blockIdx.x * 256 + threadIdx.x;
    float4 v = *(const float4*)(H + i * 4);
    *(bf162*)(g_Hb + i * 4)     = __floats2bfloat162_rn(v.x, v.y);
    *(bf162*)(g_Hb + i * 4 + 2) = __floats2bfloat162_rn(v.z, v.w);
}

// fp32 SIMT stats GEMM, 32x128 tile -> grid 128 (occupancy fix).
__global__ __launch_bounds__(256) void stats_gemm_kernel(
    const float* __restrict__ A, const float* __restrict__ W,
    float* __restrict__ C, const float* __restrict__ bias)
{
    __shared__ float As[8][32];
    __shared__ float Bs[8][128];
    const int tid = threadIdx.x;
    const int m0 = blockIdx.x * 32;
    const int tx = tid & 15, ty = tid >> 4;

    float acc[2][8];
#pragma unroll
    for (int i = 0; i < 2; i++)
#pragma unroll
        for (int j = 0; j < 8; j++) acc[i][j] = 0.f;

    for (int k0 = 0; k0 < 512; k0 += 8) {
        if (tid < 64) {
            int r = tid >> 1, cq = (tid & 1) * 4;
            float4 v = *(const float4*)(A + (size_t)(m0 + r) * 512 + k0 + cq);
            As[cq+0][r] = v.x; As[cq+1][r] = v.y;
            As[cq+2][r] = v.z; As[cq+3][r] = v.w;
        }
        {
            int r = tid >> 5, col = (tid & 31) * 4;
            *(float4*)&Bs[r][col] = *(const float4*)(W + (size_t)(k0 + r) * 128 + col);
        }
        __syncthreads();
#pragma unroll
        for (int kk = 0; kk < 8; kk++) {
            float fa0 = As[kk][2*ty], fa1 = As[kk][2*ty + 1];
            float fb[8];
            *(float4*)&fb[0] = *(const float4*)&Bs[kk][tx*8];
            *(float4*)&fb[4] = *(const float4*)&Bs[kk][tx*8 + 4];
#pragma unroll
            for (int j = 0; j < 8; j++){
                acc[0][j] = fmaf(fa0, fb[j], acc[0][j]);
                acc[1][j] = fmaf(fa1, fb[j], acc[1][j]);
            }
        }
        __syncthreads();
    }

    float bl[8];
#pragma unroll
    for (int j = 0; j < 8; j++) bl[j] = bias[tx*8 + j];
#pragma unroll
    for (int i = 0; i < 2; i++) {
        float* cp = C + (size_t)(m0 + 2*ty + i) * 128 + tx*8;
#pragma unroll
        for (int j = 0; j < 8; j++) cp[j] = acc[i][j] + bl[j];
    }
}

__global__ __launch_bounds__(256) void softmax_kernel()
{
    const int lane = threadIdx.x & 31;
    const int row = blockIdx.x * 8 + (threadIdx.x >> 5);
    const float* p = g_att + (size_t)row * SSQ;
    bf16* po = g_attb + (size_t)row * SSQ;
    float v[8];
    float mx = -1e30f;
#pragma unroll
    for (int j = 0; j < 8; j++){
        v[j] = p[lane + 32*j];
        mx = fmaxf(mx, v[j]);
    }
    mx = warpRedMax(mx);
    float s = 0.f;
#pragma unroll
    for (int j = 0; j < 8; j++){
        v[j] = expf(v[j] - mx);
        s += v[j];
    }
    s = warpRedSum(s);
#pragma unroll
    for (int j = 0; j < 8; j++)
        po[lane + 32*j] = __float2bfloat16(v[j] / s);
}

__global__ __launch_bounds__(256) void z_kernel(const float* __restrict__ eps)
{
    const int lane = threadIdx.x & 31;
    const int bs = blockIdx.x * 8 + (threadIdx.x >> 5);
    const float mean0 = g_stats[(size_t)bs*128 + lane];
    const float mean1 = g_stats[(size_t)bs*128 + 32 + lane];
    const float lv0   = g_stats[(size_t)bs*128 + 64 + lane];
    const float lv1   = g_stats[(size_t)bs*128 + 96 + lane];
    const float sd0 = expf(0.5f * lv0), sd1 = expf(0.5f * lv1);
    const float lvs = lv0 + lv1;
    for (int m = 0; m < 10; m++) {
        size_t off = ((size_t)bs*10 + m)*64;
        float e0 = eps[off + lane], e1 = eps[off + 32 + lane];
        float z0 = mean0 + e0 * sd0, z1 = mean1 + e1 * sd1;
        g_z[off + lane] = z0;        g_z[off + 32 + lane] = z1;
        g_zb[off + lane] = __float2bfloat16(z0);
        g_zb[off + 32 + lane] = __float2bfloat16(z1);
        float qv = warpRedSum(lvs + e0*e0 + e1*e1);
        if (lane == 0) g_logqz[(size_t)bs*10 + m] = -0.5f*qv + 64.f*LOG_NORM_F;
    }
}

__global__ void init_mu_kernel(const int* __restrict__ idx)
{
    const int b = blockIdx.x, k = blockIdx.y, l = threadIdx.x;
    const int lane = l & 31, w = l >> 5;
    const int n = idx[b*KCL + k];
    float v = g_z[((size_t)b*NPB + n)*64 + l];
    g_mu[((size_t)b*KCL + k)*64 + l] = v;
    float s = warpRedSum(v*v);
    __shared__ float sm[2];
    if (lane == 0) sm[w] = s;
    __syncthreads();
    if (l == 0) {
        g_m2[b*KCL + k] = sm[0] + sm[1];
        g_logpi[b*KCL + k] = -2.9957322735539909f;
    }
}

__global__ void zero_em_kernel()
{
    int i = blockIdx.x * 256 + threadIdx.x;
    if (i < 2*BB*KCL) g_Nk[i] = 0.f;
    if (i < 2*BB*KCL*64) g_muacc[i] = 0.f;
}

__global__ __launch_bounds__(256) void em_step_kernel(int parity)
{
    const int b = blockIdx.y;
    const int tid = threadIdx.x, lane = tid & 31, w = tid >> 5;
    __shared__ float mus[KCL*64];
    __shared__ float sc[KCL];
    __shared__ float nkacc[KCL];
    __shared__ float zt[64*65];
    __shared__ float pt[64*21];

    const int n0 = blockIdx.x * 64;
    for (int i = tid; i < KCL*64; i += 256) mus[i] = g_mu[(size_t)b*KCL*64 + i];
    if (tid < KCL) { sc[tid] = -0.5f*g_m2[b*KCL+tid] + g_logpi[b*KCL+tid]; nkacc[tid] = 0.f; }
    for (int i = tid; i < 64*64; i += 256)
        zt[(i >> 6)*65 + (i & 63)] = g_z[((size_t)b*NPB + n0)*64 + i];

    {
        const int op = parity ^ 1;
        if (tid < 32)
            g_muacc[((size_t)op*BB + b)*KCL*64 + blockIdx.x*32 + tid] = 0.f;
        if (blockIdx.x == 0 && tid < KCL)
            g_Nk[(op*BB + b)*KCL + tid] = 0.f;
    }
    __syncthreads();

    float nkloc = 0.f;
    const int nb = w * 8;
    for (int t = 0; t < 8; t++) {
        const int n = nb + t;
        float z0 = zt[n*65 + lane], z1 = zt[n*65 + 32 + lane];
        float mx = -1e30f, s = 0.f, myll = 0.f;
#pragma unroll
        for (int k2 = 0; k2 < KCL; k2++) {
            float p = z0*mus[k2*64+lane] + z1*mus[k2*64+32+lane];
            p = warpRedSum(p) + sc[k2];
            if (lane == k2) myll = p;
            float nm = fmaxf(mx, p);
            s = s*expf(mx - nm) + expf(p - nm);
            mx = nm;
        }
        if (lane < KCL) {
            float pk = expf(myll - mx) / s;
            pt[n*21 + lane] = pk;
            nkloc += pk;
        }
    }
    if (lane < KCL) atomicAdd(&nkacc[lane], nkloc);
    __syncthreads();

    {
        const int l = tid & 63, kq = tid >> 6;
        float a0=0.f, a1=0.f, a2=0.f, a3=0.f, a4=0.f;
#pragma unroll 4
        for (int nn = 0; nn < 64; nn++){
            float zv = zt[nn*65 + l];
            const float* pr = pt + nn*21 + kq*5;
            a0 = fmaf(pr[0], zv, a0);
            a1 = fmaf(pr[1], zv, a1);
            a2 = fmaf(pr[2], zv, a2);
            a3 = fmaf(pr[3], zv, a3);
            a4 = fmaf(pr[4], zv, a4);
        }
        float* dst = g_muacc + (((size_t)parity*BB + b)*KCL + kq*5)*64 + l;
        atomicAdd(dst,       a0);
        atomicAdd(dst + 64,  a1);
        atomicAdd(dst + 128, a2);
        atomicAdd(dst + 192, a3);
        atomicAdd(dst + 256, a4);
    }
    if (tid < KCL) atomicAdd(&g_Nk[(parity*BB + b)*KCL + tid], nkacc[tid]);
}

__global__ void em_fin_kernel(int parity)
{
    const int k = blockIdx.x, b = blockIdx.y, l = threadIdx.x;
    const int lane = l & 31, w = l >> 5;
    const float* Nk = g_Nk + (parity*BB + b)*KCL;
    float nk = Nk[k];
    float m = g_muacc[(((size_t)parity*BB + b)*KCL + k)*64 + l] / nk;
    g_mu[((size_t)b*KCL + k)*64 + l] = m;
    float s = warpRedSum(m*m);
    __shared__ float sm[2];
    if (lane == 0) sm[w] = s;
    __syncthreads();
    if (l == 0) {
        g_m2[b*KCL + k] = sm[0] + sm[1];
        float tot = 0.f;
        for (int j = 0; j < KCL; j++) tot += Nk[j];
        g_logpi[b*KCL + k] = logf(nk / tot);
    }
}

__global__ __launch_bounds__(256) void kl_kernel()
{
    const int b = blockIdx.y;
    const int tid = threadIdx.x, lane = tid & 31, w = tid >> 5;
    __shared__ float mus[KCL*64];
    __shared__ float sc[KCL];
    for (int i = tid; i < KCL*64; i += 256) mus[i] = g_mu[(size_t)b*KCL*64 + i];
    if (tid < KCL) sc[tid] = -0.5f*g_m2[b*KCL+tid] + g_logpi[b*KCL+tid];
    __syncthreads();

    double loc = 0.0;
    const int nbase = blockIdx.x*64 + w*8;
    for (int t = 0; t < 8; t++) {
        int n = nbase + t;
        const float* zp = g_z + ((size_t)b*NPB + n)*64;
        float z0 = zp[lane], z1 = zp[lane+32];
        float sq = warpRedSum(z0*z0 + z1*z1);
        float mx = -1e30f, s = 0.f;
#pragma unroll
        for (int k2 = 0; k2 < KCL; k2++) {
            float p = z0*mus[k2*64+lane] + z1*mus[k2*64+32+lane];
            p = warpRedSum(p) + sc[k2];
            float nm = fmaxf(mx, p);
            s = s*expf(mx - nm) + expf(p - nm);
            mx = nm;
        }
        float lpz = mx + logf(s) - 0.5f*sq + 64.f*LOG_NORM_F;
        if (lane == 0) loc += (double)(g_logqz[(size_t)b*NPB + n] - lpz);
    }
    __shared__ double dacc[8];
    if (lane == 0) dacc[w] = loc;
    __syncthreads();
    if (tid == 0) {
        double t = 0;
        for (int i = 0; i < 8; i++) t += dacc[i];
        atomicAdd(&g_kl, t);
    }
}

__global__ void zero_accum_kernel() { g_rec = 0.0; g_kl = 0.0; }

__global__ void finalize_kernel(float* __restrict__ out)
{
    out[0] = (float)(g_rec / 40960.0);
    out[1] = (float)(g_kl / 40960.0);
}

static void* symaddr(const void* s)
{
    void* p = nullptr;
    cudaGetSymbolAddress(&p, s);
    return p;
}

#define GEMM_SMEM 98304
#define BIG32 (1 << 30)

extern "C" void kernel_launch(void* const* d_in, const int* in_sizes, int n_in,
                              void* d_out, int out_size)
{
    const float *H, *eps, *wq, *bq, *wk, *bk, *wv, *bv, *wo, *bo, *wz, *bz;
    const float *w1, *b1, *w2, *b2, *w3, *b3;
    const int* init_idx;

    if (n_in >= 3 && in_sizes[2] == 320) {
        H = (const float*)d_in[0];  eps = (const float*)d_in[1]; init_idx = (const int*)d_in[2];
        wq = (const float*)d_in[3]; bq = (const float*)d_in[4];
        wk = (const float*)d_in[5]; bk = (const float*)d_in[6];
        wv = (const float*)d_in[7]; bv = (const float*)d_in[8];
        wo = (const float*)d_in[9]; bo = (const float*)d_in[10];
        wz = (const float*)d_in[11]; bz = (const float*)d_in[12];
        w1 = (const float*)d_in[13]; b1 = (const float*)d_in[14];
        w2 = (const float*)d_in[15]; b2 = (const float*)d_in[16];
        w3 = (const float*)d_in[17]; b3 = (const float*)d_in[18];
    } else {
        H = (const float*)d_in[0];  eps = (const float*)d_in[1];
        wq = (const float*)d_in[2]; bq = (const float*)d_in[3];
        wk = (const float*)d_in[4]; bk = (const float*)d_in[5];
        wv = (const float*)d_in[6]; bv = (const float*)d_in[7];
        wo = (const float*)d_in[8]; bo = (const float*)d_in[9];
        wz = (const float*)d_in[10]; bz = (const float*)d_in[11];
        w1 = (const float*)d_in[12]; b1 = (const float*)d_in[13];
        w2 = (const float*)d_in[14]; b2 = (const float*)d_in[15];
        w3 = (const float*)d_in[16]; b3 = (const float*)d_in[17];
        init_idx = (const int*)d_in[18];
    }

    cudaFuncSetAttribute(gemm_mma_kernel,
                         cudaFuncAttributeMaxDynamicSharedMemorySize, GEMM_SMEM);

    static cudaStream_t s2 = nullptr;
    static cudaEvent_t evStart = nullptr, evW = nullptr, evFork = nullptr, evJoin = nullptr;
    static cudaEvent_t evQ[2] = {nullptr, nullptr}, evV[2] = {nullptr, nullptr};
    if (s2 == nullptr) {
        cudaStreamCreateWithFlags(&s2, cudaStreamNonBlocking);
        cudaEventCreateWithFlags(&evStart, cudaEventDisableTiming);
        cudaEventCreateWithFlags(&evW, cudaEventDisableTiming);
        cudaEventCreateWithFlags(&evFork, cudaEventDisableTiming);
        cudaEventCreateWithFlags(&evJoin, cudaEventDisableTiming);
        for (int i = 0; i < 2; i++){
            cudaEventCreateWithFlags(&evQ[i], cudaEventDisableTiming);
            cudaEventCreateWithFlags(&evV[i], cudaEventDisableTiming);
        }
    }

    bf16* Hb    = (bf16*)symaddr(g_Hb);
    float* qkv  = (float*)symaddr(g_qkv);
    bf16* qkvb  = (bf16*)symaddr(g_qkvb);
    float* op   = (float*)symaddr(g_o);
    bf16* ob    = (bf16*)symaddr(g_ob);
    bf16* hAb   = (bf16*)symaddr(g_hAb);
    float* hB   = (float*)symaddr(g_hB);
    float* attp = (float*)symaddr(g_att);
    bf16* attb  = (bf16*)symaddr(g_attb);
    float* st   = (float*)symaddr(g_stats);
    bf16* zbp   = (bf16*)symaddr(g_zb);
    bf16* vtb   = (bf16*)symaddr(g_vtb);
    bf16* wqkv0 = (bf16*)symaddr(g_wqkv0);
    bf16* wo0t  = (bf16*)symaddr(g_wo0);
    bf16* wqkv1 = (bf16*)symaddr(g_wqkv1);
    bf16* wo1t  = (bf16*)symaddr(g_wo1);
    bf16* w1t   = (bf16*)symaddr(g_w1t);
    bf16* w2t   = (bf16*)symaddr(g_w2t);
    bf16* w3t   = (bf16*)symaddr(g_w3t);
    float* bqkv = (float*)symaddr(g_bqkv);
    bf16* d1b   = (bf16*)symaddr(g_d1);
    bf16* d2b   = (bf16*)symaddr(g_d2);

    // fork s2 into the capture FIRST (s2 work must be downstream of an event
    // recorded in the capturing origin stream)
    zero_accum_kernel<<<1, 1>>>();
    cudaEventRecord(evStart, 0);
    cudaStreamWaitEvent(s2, evStart, 0);

    // s2: layer-1 + decoder weight transposes (independent of main chain)
    transpose_qkv_kernel<<<dim3(16,16,3), dim3(32,8), 0, s2>>>(wq + DD*DD, wk + DD*DD, wv + DD*DD, wqkv1);
    transpose_w_kernel<<<dim3(16,16), dim3(32,8), 0, s2>>>(wo + DD*DD, wo1t, 512, 512);
    transpose_w_kernel<<<dim3(32,2), dim3(32,8), 0, s2>>>(w1, w1t, 64, 1024);
    transpose_w_kernel<<<dim3(32,32), dim3(32,8), 0, s2>>>(w2, w2t, 1024, 1024);
    transpose_w_kernel<<<dim3(16,32), dim3(32,8), 0, s2>>>(w3, w3t, 1024, 512);
    cudaEventRecord(evW, s2);

    // default: prologue
    round_h_kernel<<<2048, 256>>>(H);
    pack_bias_kernel<<<12, 256>>>(bq, bk, bv);
    transpose_qkv_kernel<<<dim3(16,16,3), dim3(32,8)>>>(wq, wk, wv, wqkv0);
    transpose_w_kernel<<<dim3(16,16), dim3(32,8)>>>(wo, wo0t, 512, 512);

    const float scl = 0.044194173824159216f;
    bf16* wqkvT[2] = { wqkv0, wqkv1 };
    bf16* woT[2]   = { wo0t, wo1t };
    const bf16* xinb = Hb;
    float* layer_out[2]  = { nullptr, hB };
    bf16* layer_outb[2]  = { hAb, nullptr };   // hB bf16 copy is dead

    for (int i = 0; i < 2; i++) {
        const size_t boff = (size_t)i * DD;

        if (i == 1) cudaStreamWaitEvent(0, evW, 0);  // wqkv1/wo1t ready

        // fused qkv: fp32 written only for q columns (residual)
        gemm_mma_kernel<<<dim3(12,32,1), 256, GEMM_SMEM>>>(
            xinb,512,0,0, wqkvT[i],512,0,0, qkv,1536,0,0, qkvb, 512, 512,
            bqkv + (size_t)i*1536, nullptr,0,0,0, 1.f,0,0,nullptr);

        // transpose_v on s2, overlapped with scores+softmax
        cudaEventRecord(evQ[i], 0);
        cudaStreamWaitEvent(s2, evQ[i], 0);
        transpose_v_kernel<<<dim3(8,4,64), dim3(32,8), 0, s2>>>();
        cudaEventRecord(evV[i], s2);

        // scores = q k^T / sqrt(D), K = 128 (head dim)
        gemm_mma_kernel<<<dim3(2,2,64), 256, GEMM_SMEM>>>(
            qkvb,1536,393216,128, qkvb+512,1536,393216,128,
            attp,256,262144,65536, nullptr, BIG32, 128,
            nullptr, nullptr,0,0,0, scl,0,0,nullptr);
        softmax_kernel<<<64*SSQ/8, 256>>>();

        // o = q + att @ v
        cudaStreamWaitEvent(0, evV[i], 0);
        gemm_mma_kernel<<<dim3(1,2,64), 256, GEMM_SMEM>>>(
            attb,256,262144,65536, vtb,256,131072,32768,
            op,512,131072,128, ob, BIG32, 256,
            nullptr, qkv,1536,393216,128, 1.f,0,0,nullptr);

        // out = o + relu(ob @ wo + bo)
        gemm_mma_kernel<<<dim3(4,32,1), 256, GEMM_SMEM>>>(
            ob,512,0,0, woT[i],512,0,0, layer_out[i],512,0,0,
            layer_outb[i], BIG32, 512, bo+boff, op,512,0,0, 1.f,1,0,nullptr);
        xinb = layer_outb[i];
    }

    // stats (precision-sensitive): fp32 SIMT, 32-row tiles (grid 128)
    stats_gemm_kernel<<<128, 256>>>(hB, wz, st, bz);
    z_kernel<<<512, 256>>>(eps);

    // ---- fork: EM + KL on s2, decoder on default ----
    cudaEventRecord(evFork, 0);
    cudaStreamWaitEvent(s2, evFork, 0);

    init_mu_kernel<<<dim3(BB, KCL), 64, 0, s2>>>(init_idx);
    zero_em_kernel<<<161, 256, 0, s2>>>();
    for (int it = 0; it < 5; it++) {
        em_step_kernel<<<dim3(40, BB), 256, 0, s2>>>(it & 1);
        em_fin_kernel<<<dim3(KCL, BB), 64, 0, s2>>>(it & 1);
    }
    kl_kernel<<<dim3(40, BB), 256, 0, s2>>>();
    cudaEventRecord(evJoin, s2);

    // decoder on default stream
    gemm_mma_kernel<<<dim3(8,320,1), 256, GEMM_SMEM>>>(
        zbp,64,0,0, w1t,64,0,0, nullptr,1024,0,0, d1b, BIG32,
        64, b1, nullptr,0,0,0, 1.f,1,0,nullptr);
    gemm_mma_kernel<<<dim3(8,320,1), 256, GEMM_SMEM>>>(
        d1b,1024,0,0, w2t,1024,0,0, nullptr,1024,0,0, d2b, BIG32,
        1024, b2, nullptr,0,0,0, 1.f,1,0,nullptr);
    gemm_mma_kernel<<<dim3(4,320,1), 256, GEMM_SMEM>>>(
        d2b,1024,0,0, w3t,1024,0,0, nullptr,512,0,0, nullptr, BIG32,
        1024, b3, nullptr,0,0,0, 1.f,0,1,H);

    cudaStreamWaitEvent(0, evJoin, 0);
    finalize_kernel<<<1, 1>>>((float*)d_out);
    (void)in_sizes; (void)n_in; (void)out_size;
}

// round 14
// speedup vs baseline: 4.0100x; 1.0062x over previous
#include <cuda_runtime.h>
#include <cuda_bf16.h>
#include <math.h>
#include <stdint.h>

#define BB   16
#define SSQ  256
#define DD   512
#define KCL  20
#define NTOK 4096
#define NZ   40960
#define NPB  2560
#define LOG_NORM_F (-0.91893853320467274178f)

typedef __nv_bfloat16 bf16;
typedef __nv_bfloat162 bf162;

// fp32 buffers
__device__ float g_qkv[NTOK*1536];
__device__ float g_o[NTOK*DD];
__device__ float g_hB[NTOK*DD];
__device__ float g_att[64*SSQ*SSQ];
__device__ float g_z[NZ*64];
__device__ float g_logqz[NZ];
__device__ float g_mu[BB*KCL*64];
__device__ float g_muacc[2*BB*KCL*64];
__device__ float g_m2[BB*KCL];
__device__ float g_logpi[BB*KCL];
__device__ float g_Nk[2*BB*KCL];
__device__ float g_bqkv[2*1536];
__device__ double g_rec;
__device__ double g_kl;
// bf16 GEMM operand buffers
__device__ bf16 g_Hb[NTOK*DD];
__device__ bf16 g_qkvb[NTOK*1536];
__device__ bf16 g_vtb[64*128*256];
__device__ bf16 g_ob[NTOK*DD];
__device__ bf16 g_hAb[NTOK*DD];
__device__ bf16 g_attb[64*SSQ*SSQ];
__device__ bf16 g_zb[NZ*64];
__device__ bf16 g_wqkv0[1536*512];
__device__ bf16 g_wo0[512*512];
__device__ bf16 g_wqkv1[1536*512];
__device__ bf16 g_wo1[512*512];
__device__ bf16 g_w1t[1024*64];
__device__ bf16 g_w2t[1024*1024];
__device__ bf16 g_w3t[512*1024];
__device__ bf16 g_d1[41943040];
__device__ bf16 g_d2[41943040];

__device__ __forceinline__ float warpRedSum(float v){
#pragma unroll
    for (int o = 16; o > 0; o >>= 1) v += __shfl_xor_sync(0xffffffffu, v, o);
    return v;
}
__device__ __forceinline__ float warpRedMax(float v){
#pragma unroll
    for (int o = 16; o > 0; o >>= 1) v = fmaxf(v, __shfl_xor_sync(0xffffffffu, v, o));
    return v;
}
__device__ __forceinline__ uint32_t smem_u32(const void* p){
    uint32_t a;
    asm("{ .reg .u64 t; cvta.to.shared.u64 t, %1; cvt.u32.u64 %0, t; }" : "=r"(a) : "l"(p));
    return a;
}
__device__ __forceinline__ void ldsm4(uint32_t* r, uint32_t addr){
    asm volatile("ldmatrix.sync.aligned.m8n8.x4.shared.b16 {%0,%1,%2,%3}, [%4];"
        : "=r"(r[0]), "=r"(r[1]), "=r"(r[2]), "=r"(r[3]) : "r"(addr));
}
__device__ __forceinline__ void mma16(float* d, const uint32_t* a, const uint32_t* b){
    asm volatile(
        "mma.sync.aligned.m16n8k16.row.col.f32.bf16.bf16.f32 "
        "{%0,%1,%2,%3}, {%4,%5,%6,%7}, {%8,%9}, {%0,%1,%2,%3};"
        : "+f"(d[0]), "+f"(d[1]), "+f"(d[2]), "+f"(d[3])
        : "r"(a[0]), "r"(a[1]), "r"(a[2]), "r"(a[3]), "r"(b[0]), "r"(b[1]));
}
#define CP16(dst, src) \
    asm volatile("cp.async.cg.shared.global [%0], [%1], 16;" :: "r"(dst), "l"(src))
#define CP_COMMIT() asm volatile("cp.async.commit_group;" ::: "memory")

// =======================================================================
// BF16 tensor-core GEMM (see R10/R11).
// =======================================================================
__global__ __launch_bounds__(256, 2) void gemm_mma_kernel(
    const bf16* __restrict__ A, int lda, long long sAb, long long sAh,
    const bf16* __restrict__ B, int ldb, long long sBb, long long sBh,
    float* __restrict__ C, int ldc, long long sCb, long long sCh,
    bf16* __restrict__ Cb, int c32lim,
    int K,
    const float* __restrict__ bias,
    const float* __restrict__ residual, int ldres, long long sRb, long long sRh,
    float scale, int doRelu, int lossMode,
    const float* __restrict__ lossH)
{
    extern __shared__ __align__(16) char smem[];
    const int tid = threadIdx.x;
    const int wid = tid >> 5, lane = tid & 31;

    const int zb = blockIdx.z >> 2, zh = blockIdx.z & 3;
    A += (long long)zb * sAb + (long long)zh * sAh;
    B += (long long)zb * sBb + (long long)zh * sBh;
    if (C)        C        += (long long)zb * sCb + (long long)zh * sCh;
    if (Cb)       Cb       += (long long)zb * sCb + (long long)zh * sCh;
    if (residual) residual += (long long)zb * sRb + (long long)zh * sRh;

    const int m0 = blockIdx.y * 128, n0 = blockIdx.x * 128;
    const bool wr32 = (C != nullptr) && (n0 < c32lim);
    const int kTiles = K >> 6;
    const uint32_t smem0 = smem_u32(smem);

    const int srow = tid & 127;
    const bool isB = (tid >= 128);
    const bf16* gsrc = isB ? (B + (size_t)(n0 + srow) * ldb)
                           : (A + (size_t)(m0 + srow) * lda);
    const uint32_t sdst0 = smem0 + (isB ? 16384 : 0) + srow * 128;
    const int rx = srow & 7;

    const int pstages = kTiles < 2 ? kTiles : 2;
    for (int c = 0; c < pstages; c++){
        const bf16* gs = gsrc + c * 64;
        const uint32_t sd = sdst0 + c * 32768;
#pragma unroll
        for (int j = 0; j < 8; j++)
            CP16(sd + ((j ^ rx) << 4), gs + j * 8);
        CP_COMMIT();
    }

    float acc[2][8][4];
#pragma unroll
    for (int i = 0; i < 2; i++)
#pragma unroll
        for (int j = 0; j < 8; j++)
#pragma unroll
            for (int q = 0; q < 4; q++) acc[i][j][q] = 0.f;

    const int wm = (wid & 3) * 32;
    const int wn = (wid >> 2) * 64;
    const int rr = lane & 7;
    const int qm = lane >> 3;
    const int qlow = qm & 1, qhigh = qm >> 1;
    uint32_t rowbaseA[2];
#pragma unroll
    for (int mt = 0; mt < 2; mt++)
        rowbaseA[mt] = (uint32_t)((wm + mt*16 + rr + 8*qlow) * 128);
    uint32_t rowbaseB[4];
#pragma unroll
    for (int p = 0; p < 4; p++)
        rowbaseB[p] = (uint32_t)(16384 + (wn + (2*p + qhigh)*8 + rr) * 128);

    for (int c = 0; c < kTiles; c++){
        if (c + 1 < kTiles) asm volatile("cp.async.wait_group 1;" ::: "memory");
        else                asm volatile("cp.async.wait_group 0;" ::: "memory");
        __syncthreads();

        if (c + 2 < kTiles){
            const bf16* gs = gsrc + (c + 2) * 64;
            const uint32_t sd = sdst0 + ((c + 2) % 3) * 32768;
#pragma unroll
            for (int j = 0; j < 8; j++)
                CP16(sd + ((j ^ rx) << 4), gs + j * 8);
            CP_COMMIT();
        }

        const uint32_t st = smem0 + (c % 3) * 32768;
#pragma unroll
        for (int t = 0; t < 4; t++){
            const uint32_t offA = (uint32_t)(((2*t + qhigh) ^ rr) << 4);
            const uint32_t offB = (uint32_t)(((2*t + qlow) ^ rr) << 4);
            uint32_t a[2][4], bb[4][4];
            ldsm4(a[0], st + rowbaseA[0] + offA);
            ldsm4(a[1], st + rowbaseA[1] + offA);
#pragma unroll
            for (int p = 0; p < 4; p++)
                ldsm4(bb[p], st + rowbaseB[p] + offB);
#pragma unroll
            for (int p = 0; p < 4; p++){
                mma16(acc[0][2*p+0], a[0], &bb[p][0]);
                mma16(acc[1][2*p+0], a[1], &bb[p][0]);
                mma16(acc[0][2*p+1], a[0], &bb[p][2]);
                mma16(acc[1][2*p+1], a[1], &bb[p][2]);
            }
        }
    }

    if (!lossMode){
#pragma unroll
        for (int mt = 0; mt < 2; mt++){
#pragma unroll
            for (int half = 0; half < 2; half++){
                int r = m0 + wm + mt*16 + (lane >> 2) + half*8;
                float* crow = wr32 ? (C + (size_t)r * ldc) : nullptr;
                bf16* crowb = Cb ? (Cb + (size_t)r * ldc) : nullptr;
                const float* rrow = residual ? (residual + (size_t)r * ldres) : nullptr;
#pragma unroll
                for (int nt = 0; nt < 8; nt++){
                    int col = n0 + wn + nt*8 + (lane & 3)*2;
                    float f0 = acc[mt][nt][half*2 + 0] * scale;
                    float f1 = acc[mt][nt][half*2 + 1] * scale;
                    if (bias){ f0 += bias[col]; f1 += bias[col + 1]; }
                    if (doRelu){ f0 = fmaxf(f0, 0.f); f1 = fmaxf(f1, 0.f); }
                    if (rrow){
                        float2 rv = *(const float2*)(rrow + col);
                        f0 += rv.x; f1 += rv.y;
                    }
                    if (crow)  *(float2*)(crow + col) = make_float2(f0, f1);
                    if (crowb) *(bf162*)(crowb + col) = __floats2bfloat162_rn(f0, f1);
                }
            }
        }
    } else {
        double lsum = 0.0;
#pragma unroll
        for (int mt = 0; mt < 2; mt++){
#pragma unroll
            for (int half = 0; half < 2; half++){
                int r = m0 + wm + mt*16 + (lane >> 2) + half*8;
                const float* hrow = lossH + (size_t)(r / 10) * 512;
#pragma unroll
                for (int nt = 0; nt < 8; nt++){
                    int col = n0 + wn + nt*8 + (lane & 3)*2;
                    float f0 = fmaxf(acc[mt][nt][half*2 + 0] + bias[col], 0.f);
                    float f1 = fmaxf(acc[mt][nt][half*2 + 1] + bias[col + 1], 0.f);
                    float d0 = f0 - hrow[col];
                    float d1 = f1 - hrow[col + 1];
                    lsum += (double)d0 * d0 + (double)d1 * d1;
                }
            }
        }
#pragma unroll
        for (int o = 16; o > 0; o >>= 1) lsum += __shfl_xor_sync(0xffffffffu, lsum, o);
        __shared__ double ds[8];
        if (lane == 0) ds[wid] = lsum;
        __syncthreads();
        if (tid == 0){
            double t = 0;
            for (int i = 0; i < 8; i++) t += ds[i];
            atomicAdd(&g_rec, t);
        }
    }
}

__global__ void transpose_w_kernel(const float* __restrict__ W,
                                   bf16* __restrict__ out, int K, int N)
{
    __shared__ float t[32][33];
    const int k0 = blockIdx.y * 32, n0 = blockIdx.x * 32;
    for (int i = threadIdx.y; i < 32; i += 8)
        t[i][threadIdx.x] = W[(size_t)(k0 + i) * N + n0 + threadIdx.x];
    __syncthreads();
    for (int i = threadIdx.y; i < 32; i += 8)
        out[(size_t)(n0 + i) * K + k0 + threadIdx.x] = __float2bfloat16(t[threadIdx.x][i]);
}

__global__ void transpose_qkv_kernel(const float* __restrict__ Wq,
                                     const float* __restrict__ Wk,
                                     const float* __restrict__ Wv,
                                     bf16* __restrict__ out)
{
    __shared__ float t[32][33];
    const float* W = blockIdx.z == 0 ? Wq : (blockIdx.z == 1 ? Wk : Wv);
    const int k0 = blockIdx.y * 32, n0 = blockIdx.x * 32;
    for (int i = threadIdx.y; i < 32; i += 8)
        t[i][threadIdx.x] = W[(size_t)(k0 + i) * 512 + n0 + threadIdx.x];
    __syncthreads();
    const int nout = blockIdx.z * 512 + n0;
    for (int i = threadIdx.y; i < 32; i += 8)
        out[(size_t)(nout + i) * 512 + k0 + threadIdx.x] = __float2bfloat16(t[threadIdx.x][i]);
}

__global__ void pack_bias_kernel(const float* __restrict__ bq,
                                 const float* __restrict__ bk,
                                 const float* __restrict__ bv)
{
    int i = blockIdx.x * 256 + threadIdx.x;
    if (i < 2*1536){
        int layer = i / 1536, col = i % 1536;
        const float* src = col < 512 ? bq : (col < 1024 ? bk : bv);
        g_bqkv[i] = src[layer*512 + (col & 511)];
    }
}

__global__ void transpose_v_kernel()
{
    __shared__ float t[32][33];
    const int bh = blockIdx.z, b = bh >> 2, h = bh & 3;
    const int k0 = blockIdx.x * 32;
    const int n0 = blockIdx.y * 32;
    for (int i = threadIdx.y; i < 32; i += 8)
        t[i][threadIdx.x] = __bfloat162float(
            g_qkvb[((size_t)b * 256 + k0 + i) * 1536 + 1024 + h * 128 + n0 + threadIdx.x]);
    __syncthreads();
    for (int i = threadIdx.y; i < 32; i += 8)
        g_vtb[((size_t)bh * 128 + n0 + i) * 256 + k0 + threadIdx.x] = __float2bfloat16(t[threadIdx.x][i]);
}

__global__ void round_h_kernel(const float* __restrict__ H)
{
    int i = blockIdx.x * 256 + threadIdx.x;
    float4 v = *(const float4*)(H + i * 4);
    *(bf162*)(g_Hb + i * 4)     = __floats2bfloat162_rn(v.x, v.y);
    *(bf162*)(g_Hb + i * 4 + 2) = __floats2bfloat162_rn(v.z, v.w);
}

// =======================================================================
// Fused stats GEMM (32x128 tile, fp32 SIMT) + z/logqz computation.
// Phase 1 identical accumulation to the old stats_gemm (same k order);
// phase 2 identical formulas to the old z_kernel (warp per token).
// =======================================================================
__global__ __launch_bounds__(256) void stats_z_kernel(
    const float* __restrict__ A, const float* __restrict__ W,
    const float* __restrict__ bias, const float* __restrict__ eps)
{
    __shared__ float As[8][32];
    __shared__ float Bs[8][128];
    __shared__ float sst[32][132];
    const int tid = threadIdx.x;
    const int m0 = blockIdx.x * 32;
    const int tx = tid & 15, ty = tid >> 4;

    float acc[2][8];
#pragma unroll
    for (int i = 0; i < 2; i++)
#pragma unroll
        for (int j = 0; j < 8; j++) acc[i][j] = 0.f;

    for (int k0 = 0; k0 < 512; k0 += 8) {
        if (tid < 64) {
            int r = tid >> 1, cq = (tid & 1) * 4;
            float4 v = *(const float4*)(A + (size_t)(m0 + r) * 512 + k0 + cq);
            As[cq+0][r] = v.x; As[cq+1][r] = v.y;
            As[cq+2][r] = v.z; As[cq+3][r] = v.w;
        }
        {
            int r = tid >> 5, col = (tid & 31) * 4;
            *(float4*)&Bs[r][col] = *(const float4*)(W + (size_t)(k0 + r) * 128 + col);
        }
        __syncthreads();
#pragma unroll
        for (int kk = 0; kk < 8; kk++) {
            float fa0 = As[kk][2*ty], fa1 = As[kk][2*ty + 1];
            float fb[8];
            *(float4*)&fb[0] = *(const float4*)&Bs[kk][tx*8];
            *(float4*)&fb[4] = *(const float4*)&Bs[kk][tx*8 + 4];
#pragma unroll
            for (int j = 0; j < 8; j++){
                acc[0][j] = fmaf(fa0, fb[j], acc[0][j]);
                acc[1][j] = fmaf(fa1, fb[j], acc[1][j]);
            }
        }
        __syncthreads();
    }

    float bl[8];
#pragma unroll
    for (int j = 0; j < 8; j++) bl[j] = bias[tx*8 + j];
#pragma unroll
    for (int i = 0; i < 2; i++)
#pragma unroll
        for (int j = 0; j < 8; j++)
            sst[2*ty + i][tx*8 + j] = acc[i][j] + bl[j];
    __syncthreads();

    // phase 2: z + logqz, warp per token (4 tokens per warp)
    const int lane = tid & 31, w = tid >> 5;
    for (int tt = 0; tt < 4; tt++){
        const int t = w*4 + tt;
        const int bs = m0 + t;
        const float mean0 = sst[t][lane];
        const float mean1 = sst[t][32 + lane];
        const float lv0   = sst[t][64 + lane];
        const float lv1   = sst[t][96 + lane];
        const float sd0 = expf(0.5f * lv0), sd1 = expf(0.5f * lv1);
        const float lvs = lv0 + lv1;
        for (int m = 0; m < 10; m++) {
            size_t off = ((size_t)bs*10 + m)*64;
            float e0 = eps[off + lane], e1 = eps[off + 32 + lane];
            float z0 = mean0 + e0 * sd0, z1 = mean1 + e1 * sd1;
            g_z[off + lane] = z0;        g_z[off + 32 + lane] = z1;
            g_zb[off + lane] = __float2bfloat16(z0);
            g_zb[off + 32 + lane] = __float2bfloat16(z1);
            float qv = warpRedSum(lvs + e0*e0 + e1*e1);
            if (lane == 0) g_logqz[(size_t)bs*10 + m] = -0.5f*qv + 64.f*LOG_NORM_F;
        }
    }
}

__global__ __launch_bounds__(256) void softmax_kernel()
{
    const int lane = threadIdx.x & 31;
    const int row = blockIdx.x * 8 + (threadIdx.x >> 5);
    const float* p = g_att + (size_t)row * SSQ;
    bf16* po = g_attb + (size_t)row * SSQ;
    float v[8];
    float mx = -1e30f;
#pragma unroll
    for (int j = 0; j < 8; j++){
        v[j] = p[lane + 32*j];
        mx = fmaxf(mx, v[j]);
    }
    mx = warpRedMax(mx);
    float s = 0.f;
#pragma unroll
    for (int j = 0; j < 8; j++){
        v[j] = expf(v[j] - mx);
        s += v[j];
    }
    s = warpRedSum(s);
#pragma unroll
    for (int j = 0; j < 8; j++)
        po[lane + 32*j] = __float2bfloat16(v[j] / s);
}

__global__ void init_mu_kernel(const int* __restrict__ idx)
{
    const int b = blockIdx.x, k = blockIdx.y, l = threadIdx.x;
    const int lane = l & 31, w = l >> 5;
    const int n = idx[b*KCL + k];
    float v = g_z[((size_t)b*NPB + n)*64 + l];
    g_mu[((size_t)b*KCL + k)*64 + l] = v;
    float s = warpRedSum(v*v);
    __shared__ float sm[2];
    if (lane == 0) sm[w] = s;
    __syncthreads();
    if (l == 0) {
        g_m2[b*KCL + k] = sm[0] + sm[1];
        g_logpi[b*KCL + k] = -2.9957322735539909f;
    }
}

__global__ void zero_em_kernel()
{
    int i = blockIdx.x * 256 + threadIdx.x;
    if (i < 2*BB*KCL) g_Nk[i] = 0.f;
    if (i < 2*BB*KCL*64) g_muacc[i] = 0.f;
}

__global__ __launch_bounds__(256) void em_step_kernel(int parity)
{
    const int b = blockIdx.y;
    const int tid = threadIdx.x, lane = tid & 31, w = tid >> 5;
    __shared__ float mus[KCL*64];
    __shared__ float sc[KCL];
    __shared__ float nkacc[KCL];
    __shared__ float zt[64*65];
    __shared__ float pt[64*21];

    const int n0 = blockIdx.x * 64;
    for (int i = tid; i < KCL*64; i += 256) mus[i] = g_mu[(size_t)b*KCL*64 + i];
    if (tid < KCL) { sc[tid] = -0.5f*g_m2[b*KCL+tid] + g_logpi[b*KCL+tid]; nkacc[tid] = 0.f; }
    for (int i = tid; i < 64*64; i += 256)
        zt[(i >> 6)*65 + (i & 63)] = g_z[((size_t)b*NPB + n0)*64 + i];

    {
        const int op = parity ^ 1;
        if (tid < 32)
            g_muacc[((size_t)op*BB + b)*KCL*64 + blockIdx.x*32 + tid] = 0.f;
        if (blockIdx.x == 0 && tid < KCL)
            g_Nk[(op*BB + b)*KCL + tid] = 0.f;
    }
    __syncthreads();

    float nkloc = 0.f;
    const int nb = w * 8;
    for (int t = 0; t < 8; t++) {
        const int n = nb + t;
        float z0 = zt[n*65 + lane], z1 = zt[n*65 + 32 + lane];
        float mx = -1e30f, s = 0.f, myll = 0.f;
#pragma unroll
        for (int k2 = 0; k2 < KCL; k2++) {
            float p = z0*mus[k2*64+lane] + z1*mus[k2*64+32+lane];
            p = warpRedSum(p) + sc[k2];
            if (lane == k2) myll = p;
            float nm = fmaxf(mx, p);
            s = s*expf(mx - nm) + expf(p - nm);
            mx = nm;
        }
        if (lane < KCL) {
            float pk = expf(myll - mx) / s;
            pt[n*21 + lane] = pk;
            nkloc += pk;
        }
    }
    if (lane < KCL) atomicAdd(&nkacc[lane], nkloc);
    __syncthreads();

    {
        const int l = tid & 63, kq = tid >> 6;
        float a0=0.f, a1=0.f, a2=0.f, a3=0.f, a4=0.f;
#pragma unroll 4
        for (int nn = 0; nn < 64; nn++){
            float zv = zt[nn*65 + l];
            const float* pr = pt + nn*21 + kq*5;
            a0 = fmaf(pr[0], zv, a0);
            a1 = fmaf(pr[1], zv, a1);
            a2 = fmaf(pr[2], zv, a2);
            a3 = fmaf(pr[3], zv, a3);
            a4 = fmaf(pr[4], zv, a4);
        }
        float* dst = g_muacc + (((size_t)parity*BB + b)*KCL + kq*5)*64 + l;
        atomicAdd(dst,       a0);
        atomicAdd(dst + 64,  a1);
        atomicAdd(dst + 128, a2);
        atomicAdd(dst + 192, a3);
        atomicAdd(dst + 256, a4);
    }
    if (tid < KCL) atomicAdd(&g_Nk[(parity*BB + b)*KCL + tid], nkacc[tid]);
}

__global__ void em_fin_kernel(int parity)
{
    const int k = blockIdx.x, b = blockIdx.y, l = threadIdx.x;
    const int lane = l & 31, w = l >> 5;
    const float* Nk = g_Nk + (parity*BB + b)*KCL;
    float nk = Nk[k];
    float m = g_muacc[(((size_t)parity*BB + b)*KCL + k)*64 + l] / nk;
    g_mu[((size_t)b*KCL + k)*64 + l] = m;
    float s = warpRedSum(m*m);
    __shared__ float sm[2];
    if (lane == 0) sm[w] = s;
    __syncthreads();
    if (l == 0) {
        g_m2[b*KCL + k] = sm[0] + sm[1];
        float tot = 0.f;
        for (int j = 0; j < KCL; j++) tot += Nk[j];
        g_logpi[b*KCL + k] = logf(nk / tot);
    }
}

__global__ __launch_bounds__(256) void kl_kernel()
{
    const int b = blockIdx.y;
    const int tid = threadIdx.x, lane = tid & 31, w = tid >> 5;
    __shared__ float mus[KCL*64];
    __shared__ float sc[KCL];
    for (int i = tid; i < KCL*64; i += 256) mus[i] = g_mu[(size_t)b*KCL*64 + i];
    if (tid < KCL) sc[tid] = -0.5f*g_m2[b*KCL+tid] + g_logpi[b*KCL+tid];
    __syncthreads();

    double loc = 0.0;
    const int nbase = blockIdx.x*64 + w*8;
    for (int t = 0; t < 8; t++) {
        int n = nbase + t;
        const float* zp = g_z + ((size_t)b*NPB + n)*64;
        float z0 = zp[lane], z1 = zp[lane+32];
        float sq = warpRedSum(z0*z0 + z1*z1);
        float mx = -1e30f, s = 0.f;
#pragma unroll
        for (int k2 = 0; k2 < KCL; k2++) {
            float p = z0*mus[k2*64+lane] + z1*mus[k2*64+32+lane];
            p = warpRedSum(p) + sc[k2];
            float nm = fmaxf(mx, p);
            s = s*expf(mx - nm) + expf(p - nm);
            mx = nm;
        }
        float lpz = mx + logf(s) - 0.5f*sq + 64.f*LOG_NORM_F;
        if (lane == 0) loc += (double)(g_logqz[(size_t)b*NPB + n] - lpz);
    }
    __shared__ double dacc[8];
    if (lane == 0) dacc[w] = loc;
    __syncthreads();
    if (tid == 0) {
        double t = 0;
        for (int i = 0; i < 8; i++) t += dacc[i];
        atomicAdd(&g_kl, t);
    }
}

__global__ void zero_accum_kernel() { g_rec = 0.0; g_kl = 0.0; }

__global__ void finalize_kernel(float* __restrict__ out)
{
    out[0] = (float)(g_rec / 40960.0);
    out[1] = (float)(g_kl / 40960.0);
}

static void* symaddr(const void* s)
{
    void* p = nullptr;
    cudaGetSymbolAddress(&p, s);
    return p;
}

#define GEMM_SMEM 98304
#define BIG32 (1 << 30)

extern "C" void kernel_launch(void* const* d_in, const int* in_sizes, int n_in,
                              void* d_out, int out_size)
{
    const float *H, *eps, *wq, *bq, *wk, *bk, *wv, *bv, *wo, *bo, *wz, *bz;
    const float *w1, *b1, *w2, *b2, *w3, *b3;
    const int* init_idx;

    if (n_in >= 3 && in_sizes[2] == 320) {
        H = (const float*)d_in[0];  eps = (const float*)d_in[1]; init_idx = (const int*)d_in[2];
        wq = (const float*)d_in[3]; bq = (const float*)d_in[4];
        wk = (const float*)d_in[5]; bk = (const float*)d_in[6];
        wv = (const float*)d_in[7]; bv = (const float*)d_in[8];
        wo = (const float*)d_in[9]; bo = (const float*)d_in[10];
        wz = (const float*)d_in[11]; bz = (const float*)d_in[12];
        w1 = (const float*)d_in[13]; b1 = (const float*)d_in[14];
        w2 = (const float*)d_in[15]; b2 = (const float*)d_in[16];
        w3 = (const float*)d_in[17]; b3 = (const float*)d_in[18];
    } else {
        H = (const float*)d_in[0];  eps = (const float*)d_in[1];
        wq = (const float*)d_in[2]; bq = (const float*)d_in[3];
        wk = (const float*)d_in[4]; bk = (const float*)d_in[5];
        wv = (const float*)d_in[6]; bv = (const float*)d_in[7];
        wo = (const float*)d_in[8]; bo = (const float*)d_in[9];
        wz = (const float*)d_in[10]; bz = (const float*)d_in[11];
        w1 = (const float*)d_in[12]; b1 = (const float*)d_in[13];
        w2 = (const float*)d_in[14]; b2 = (const float*)d_in[15];
        w3 = (const float*)d_in[16]; b3 = (const float*)d_in[17];
        init_idx = (const int*)d_in[18];
    }

    cudaFuncSetAttribute(gemm_mma_kernel,
                         cudaFuncAttributeMaxDynamicSharedMemorySize, GEMM_SMEM);

    static cudaStream_t s2 = nullptr;
    static cudaEvent_t evStart = nullptr, evW0 = nullptr, evW = nullptr,
                       evFork = nullptr, evJoin = nullptr;
    static cudaEvent_t evQ[2] = {nullptr, nullptr}, evV[2] = {nullptr, nullptr};
    if (s2 == nullptr) {
        cudaStreamCreateWithFlags(&s2, cudaStreamNonBlocking);
        cudaEventCreateWithFlags(&evStart, cudaEventDisableTiming);
        cudaEventCreateWithFlags(&evW0, cudaEventDisableTiming);
        cudaEventCreateWithFlags(&evW, cudaEventDisableTiming);
        cudaEventCreateWithFlags(&evFork, cudaEventDisableTiming);
        cudaEventCreateWithFlags(&evJoin, cudaEventDisableTiming);
        for (int i = 0; i < 2; i++){
            cudaEventCreateWithFlags(&evQ[i], cudaEventDisableTiming);
            cudaEventCreateWithFlags(&evV[i], cudaEventDisableTiming);
        }
    }

    bf16* Hb    = (bf16*)symaddr(g_Hb);
    float* qkv  = (float*)symaddr(g_qkv);
    bf16* qkvb  = (bf16*)symaddr(g_qkvb);
    float* op   = (float*)symaddr(g_o);
    bf16* ob    = (bf16*)symaddr(g_ob);
    bf16* hAb   = (bf16*)symaddr(g_hAb);
    float* hB   = (float*)symaddr(g_hB);
    float* attp = (float*)symaddr(g_att);
    bf16* attb  = (bf16*)symaddr(g_attb);
    bf16* zbp   = (bf16*)symaddr(g_zb);
    bf16* vtb   = (bf16*)symaddr(g_vtb);
    bf16* wqkv0 = (bf16*)symaddr(g_wqkv0);
    bf16* wo0t  = (bf16*)symaddr(g_wo0);
    bf16* wqkv1 = (bf16*)symaddr(g_wqkv1);
    bf16* wo1t  = (bf16*)symaddr(g_wo1);
    bf16* w1t   = (bf16*)symaddr(g_w1t);
    bf16* w2t   = (bf16*)symaddr(g_w2t);
    bf16* w3t   = (bf16*)symaddr(g_w3t);
    float* bqkv = (float*)symaddr(g_bqkv);
    bf16* d1b   = (bf16*)symaddr(g_d1);
    bf16* d2b   = (bf16*)symaddr(g_d2);

    // fork s2 into the capture first
    zero_accum_kernel<<<1, 1>>>();
    cudaEventRecord(evStart, 0);
    cudaStreamWaitEvent(s2, evStart, 0);

    // s2: ALL weight transposes. wqkv0 first (needed earliest).
    transpose_qkv_kernel<<<dim3(16,16,3), dim3(32,8), 0, s2>>>(wq, wk, wv, wqkv0);
    cudaEventRecord(evW0, s2);
    transpose_w_kernel<<<dim3(16,16), dim3(32,8), 0, s2>>>(wo, wo0t, 512, 512);
    transpose_qkv_kernel<<<dim3(16,16,3), dim3(32,8), 0, s2>>>(wq + DD*DD, wk + DD*DD, wv + DD*DD, wqkv1);
    transpose_w_kernel<<<dim3(16,16), dim3(32,8), 0, s2>>>(wo + DD*DD, wo1t, 512, 512);
    transpose_w_kernel<<<dim3(32,2), dim3(32,8), 0, s2>>>(w1, w1t, 64, 1024);
    transpose_w_kernel<<<dim3(32,32), dim3(32,8), 0, s2>>>(w2, w2t, 1024, 1024);
    transpose_w_kernel<<<dim3(16,32), dim3(32,8), 0, s2>>>(w3, w3t, 1024, 512);
    cudaEventRecord(evW, s2);

    // default stream: prologue concurrent with s2 transposes
    round_h_kernel<<<2048, 256>>>(H);
    pack_bias_kernel<<<12, 256>>>(bq, bk, bv);

    const float scl = 0.044194173824159216f;
    bf16* wqkvT[2] = { wqkv0, wqkv1 };
    bf16* woT[2]   = { wo0t, wo1t };
    const bf16* xinb = Hb;
    float* layer_out[2]  = { nullptr, hB };
    bf16* layer_outb[2]  = { hAb, nullptr };

    for (int i = 0; i < 2; i++) {
        const size_t boff = (size_t)i * DD;

        if (i == 0) cudaStreamWaitEvent(0, evW0, 0);   // wqkv0 ready

        // fused qkv: fp32 written only for q columns (residual)
        gemm_mma_kernel<<<dim3(12,32,1), 256, GEMM_SMEM>>>(
            xinb,512,0,0, wqkvT[i],512,0,0, qkv,1536,0,0, qkvb, 512, 512,
            bqkv + (size_t)i*1536, nullptr,0,0,0, 1.f,0,0,nullptr);

        // transpose_v on s2, overlapped with scores+softmax
        cudaEventRecord(evQ[i], 0);
        cudaStreamWaitEvent(s2, evQ[i], 0);
        transpose_v_kernel<<<dim3(8,4,64), dim3(32,8), 0, s2>>>();
        cudaEventRecord(evV[i], s2);

        // scores = q k^T / sqrt(D), K = 128 (head dim)
        gemm_mma_kernel<<<dim3(2,2,64), 256, GEMM_SMEM>>>(
            qkvb,1536,393216,128, qkvb+512,1536,393216,128,
            attp,256,262144,65536, nullptr, BIG32, 128,
            nullptr, nullptr,0,0,0, scl,0,0,nullptr);
        softmax_kernel<<<64*SSQ/8, 256>>>();

        // o = q + att @ v
        cudaStreamWaitEvent(0, evV[i], 0);
        gemm_mma_kernel<<<dim3(1,2,64), 256, GEMM_SMEM>>>(
            attb,256,262144,65536, vtb,256,131072,32768,
            op,512,131072,128, ob, BIG32, 256,
            nullptr, qkv,1536,393216,128, 1.f,0,0,nullptr);

        // out = o + relu(ob @ wo + bo)
        if (i == 0) cudaStreamWaitEvent(0, evW, 0);    // remaining transposes ready
        gemm_mma_kernel<<<dim3(4,32,1), 256, GEMM_SMEM>>>(
            ob,512,0,0, woT[i],512,0,0, layer_out[i],512,0,0,
            layer_outb[i], BIG32, 512, bo+boff, op,512,0,0, 1.f,1,0,nullptr);
        xinb = layer_outb[i];
    }

    // fused stats + z (+ logqz), grid 128 x 32-token tiles
    stats_z_kernel<<<128, 256>>>(hB, wz, bz, eps);

    // ---- fork: EM + KL on s2, decoder on default ----
    cudaEventRecord(evFork, 0);
    cudaStreamWaitEvent(s2, evFork, 0);

    init_mu_kernel<<<dim3(BB, KCL), 64, 0, s2>>>(init_idx);
    zero_em_kernel<<<161, 256, 0, s2>>>();
    for (int it = 0; it < 5; it++) {
        em_step_kernel<<<dim3(40, BB), 256, 0, s2>>>(it & 1);
        em_fin_kernel<<<dim3(KCL, BB), 64, 0, s2>>>(it & 1);
    }
    kl_kernel<<<dim3(40, BB), 256, 0, s2>>>();
    cudaEventRecord(evJoin, s2);

    // decoder on default stream
    gemm_mma_kernel<<<dim3(8,320,1), 256, GEMM_SMEM>>>(
        zbp,64,0,0, w1t,64,0,0, nullptr,1024,0,0, d1b, BIG32,
        64, b1, nullptr,0,0,0, 1.f,1,0,nullptr);
    gemm_mma_kernel<<<dim3(8,320,1), 256, GEMM_SMEM>>>(
        d1b,1024,0,0, w2t,1024,0,0, nullptr,1024,0,0, d2b, BIG32,
        1024, b2, nullptr,0,0,0, 1.f,1,0,nullptr);
    gemm_mma_kernel<<<dim3(4,320,1), 256, GEMM_SMEM>>>(
        d2b,1024,0,0, w3t,1024,0,0, nullptr,512,0,0, nullptr, BIG32,
        1024, b3, nullptr,0,0,0, 1.f,0,1,H);

    cudaStreamWaitEvent(0, evJoin, 0);
    finalize_kernel<<<1, 1>>>((float*)d_out);
    (void)in_sizes; (void)n_in; (void)out_size;
}